// round 6
// baseline (speedup 1.0000x reference)
#include <cuda_runtime.h>
#include <cuda_bf16.h>
#include <stdint.h>
#include <math.h>

// Problem constants
#define BTN   64
#define SEQ   264
#define MROWS (BTN*SEQ)      // 16896
#define GDIM  1024
#define NH    16
#define NKV   4
#define HD    64
#define QKV_N 1536
#define NZ    256

// GEMM tiling: block 128x256, BK=32, 8 warps (warptile 64x64), 3-stage
#define BK    32
#define KT    (GDIM/BK)      // 32
#define A_PL  8192           // 128x32 bf16
#define B_PL  16384          // 256x32 bf16
#define STG_B (2*A_PL + 2*B_PL)    // 49152
#define GEMM_SMEM (3*STG_B)        // 147456

// Attention smem layout (bf16 planes, rows padded to 72 elems = 144 B)
#define KPAD  272
#define LDP   144
#define KPL   (KPAD*LDP)
#define QPL   (96*LDP)
#define SM_KHI 0
#define SM_KLO (KPL)
#define SM_VHI (2*KPL)
#define SM_VLO (3*KPL)
#define SM_QHI (4*KPL)
#define SM_QLO (4*KPL + QPL)
#define ATT_SMEM (4*KPL + 2*QPL)   // 184320

// ---------------------------------------------------------------------------
// device scratch
// ---------------------------------------------------------------------------
__device__ __align__(16) __nv_bfloat16 g_xhi[(size_t)MROWS * GDIM];
__device__ __align__(16) __nv_bfloat16 g_xlo[(size_t)MROWS * GDIM];
__device__ __align__(16) __nv_bfloat16 g_whi[(size_t)QKV_N * GDIM];
__device__ __align__(16) __nv_bfloat16 g_wlo[(size_t)QKV_N * GDIM];
__device__ __align__(16) __nv_bfloat16 g_wohi[(size_t)GDIM * GDIM];
__device__ __align__(16) __nv_bfloat16 g_wolo[(size_t)GDIM * GDIM];
__device__ __align__(16) __nv_bfloat16 g_ahi[(size_t)MROWS * GDIM];
__device__ __align__(16) __nv_bfloat16 g_alo[(size_t)MROWS * GDIM];
__device__ __align__(16) float         g_qkv[(size_t)MROWS * QKV_N];

// ---------------------------------------------------------------------------
// helpers
// ---------------------------------------------------------------------------
__device__ __forceinline__ uint32_t smem_u32(const void* p) {
    uint32_t a;
    asm("{ .reg .u64 t; cvta.to.shared.u64 t, %1; cvt.u32.u64 %0, t; }"
        : "=r"(a) : "l"(p));
    return a;
}
__device__ __forceinline__ void cp16(uint32_t dst, const void* src) {
    asm volatile("cp.async.cg.shared.global [%0], [%1], 16;" :: "r"(dst), "l"(src));
}
#define CP_COMMIT() asm volatile("cp.async.commit_group;" ::: "memory")
#define CP_WAIT(n)  asm volatile("cp.async.wait_group %0;" :: "n"(n) : "memory")

__device__ __forceinline__ void ldsm4(uint32_t* r, uint32_t addr) {
    asm volatile("ldmatrix.sync.aligned.m8n8.x4.shared.b16 {%0,%1,%2,%3}, [%4];"
                 : "=r"(r[0]), "=r"(r[1]), "=r"(r[2]), "=r"(r[3]) : "r"(addr));
}
__device__ __forceinline__ void ldsm4t(uint32_t* r, uint32_t addr) {
    asm volatile("ldmatrix.sync.aligned.m8n8.x4.trans.shared.b16 {%0,%1,%2,%3}, [%4];"
                 : "=r"(r[0]), "=r"(r[1]), "=r"(r[2]), "=r"(r[3]) : "r"(addr));
}
__device__ __forceinline__ void mma16816(float* c, const uint32_t* a, const uint32_t* b) {
    asm volatile(
        "mma.sync.aligned.m16n8k16.row.col.f32.bf16.bf16.f32 "
        "{%0,%1,%2,%3}, {%4,%5,%6,%7}, {%8,%9}, {%0,%1,%2,%3};"
        : "+f"(c[0]), "+f"(c[1]), "+f"(c[2]), "+f"(c[3])
        : "r"(a[0]), "r"(a[1]), "r"(a[2]), "r"(a[3]), "r"(b[0]), "r"(b[1]));
}

// swizzled byte offset of 16B unit (r, u) within an Nx32 bf16 plane (64B rows)
__device__ __forceinline__ uint32_t swz(int r, int u) {
    return (uint32_t)(r * 64 + ((u ^ ((r >> 1) & 3)) << 4));
}

// split two floats -> hi bf16x2 + lo bf16x2
__device__ __forceinline__ void split2(float a, float b, uint32_t& h, uint32_t& l) {
    __nv_bfloat16 ha = __float2bfloat16(a);
    __nv_bfloat16 hb = __float2bfloat16(b);
    float ra = a - __bfloat162float(ha);
    float rb = b - __bfloat162float(hb);
    h = (uint32_t)__bfloat16_as_ushort(ha) | ((uint32_t)__bfloat16_as_ushort(hb) << 16);
    l = (uint32_t)__bfloat16_as_ushort(__float2bfloat16(ra)) |
        ((uint32_t)__bfloat16_as_ushort(__float2bfloat16(rb)) << 16);
}

__device__ __forceinline__ void split8(const float* __restrict__ s, uint4& hv, uint4& lv) {
    float4 f0 = *(const float4*)s;
    float4 f1 = *(const float4*)(s + 4);
    split2(f0.x, f0.y, hv.x, lv.x);
    split2(f0.z, f0.w, hv.y, lv.y);
    split2(f1.x, f1.y, hv.z, lv.z);
    split2(f1.z, f1.w, hv.w, lv.w);
}

// ---------------------------------------------------------------------------
// split kernels
// ---------------------------------------------------------------------------
__global__ void split_rm(const float* __restrict__ src, __nv_bfloat16* __restrict__ hi,
                         __nv_bfloat16* __restrict__ lo, int nunits) {
    for (int i = blockIdx.x * blockDim.x + threadIdx.x; i < nunits;
         i += gridDim.x * blockDim.x) {
        uint4 hv, lv;
        split8(src + (size_t)i * 8, hv, lv);
        ((uint4*)hi)[i] = hv;
        ((uint4*)lo)[i] = lv;
    }
}

__global__ void split_w_qkv(const float* __restrict__ wq, const float* __restrict__ wk,
                            const float* __restrict__ wv) {
    int nunits = QKV_N * (GDIM / 8);
    for (int i = blockIdx.x * blockDim.x + threadIdx.x; i < nunits;
         i += gridDim.x * blockDim.x) {
        int row = i >> 7, ur = i & 127;
        const float* srow;
        if (row < NH * HD)                srow = wq + (size_t)row * GDIM;
        else if (row < NH*HD + NKV*HD)    srow = wk + (size_t)(row - NH*HD) * GDIM;
        else                              srow = wv + (size_t)(row - NH*HD - NKV*HD) * GDIM;
        uint4 hv, lv;
        split8(srow + ur * 8, hv, lv);
        ((uint4*)g_whi)[i] = hv;
        ((uint4*)g_wlo)[i] = lv;
    }
}

// ---------------------------------------------------------------------------
// bf16x3 GEMM via mma.sync: out[m][n] = sum_k A[m][k]*B[n][k], K=1024
// block 128x256, BK=32, 8 warps (warptile 64x64), 3-stage cp.async pipeline.
// Inner loop: 3 independent passes over nb -> same-acc distance 8 (no RAW stall)
// ---------------------------------------------------------------------------
__device__ __forceinline__ void load_stage(uint32_t sb, int stage,
        const __nv_bfloat16* __restrict__ Ah, const __nv_bfloat16* __restrict__ Al,
        const __nv_bfloat16* __restrict__ Bh, const __nv_bfloat16* __restrict__ Bl,
        int bm, int bn, int kc, int tid) {
    uint32_t st = sb + stage * STG_B;
#pragma unroll
    for (int i = 0; i < 4; i++) {
        int v = i * 256 + tid;
        int op = v >> 9, w = v & 511;
        int r = w >> 2, u = w & 3;
        const __nv_bfloat16* base = op ? Al : Ah;
        const __nv_bfloat16* g = base + (size_t)(bm * 128 + r) * GDIM + kc * BK + u * 8;
        cp16(st + op * A_PL + swz(r, u), g);
    }
#pragma unroll
    for (int i = 0; i < 8; i++) {
        int v = i * 256 + tid;
        int op = v >> 10, w = v & 1023;
        int r = w >> 2, u = w & 3;
        const __nv_bfloat16* base = op ? Bl : Bh;
        const __nv_bfloat16* g = base + (size_t)(bn * 256 + r) * GDIM + kc * BK + u * 8;
        cp16(st + 2 * A_PL + op * B_PL + swz(r, u), g);
    }
}

__global__ __launch_bounds__(256, 1)
void gemm_mma(const __nv_bfloat16* __restrict__ Ah, const __nv_bfloat16* __restrict__ Al,
              const __nv_bfloat16* __restrict__ Bh, const __nv_bfloat16* __restrict__ Bl,
              float* __restrict__ out, int ldc) {
    extern __shared__ __align__(1024) char smem[];
    uint32_t sb = smem_u32(smem);
    int tid = threadIdx.x, wid = tid >> 5, lane = tid & 31;
    int bm = blockIdx.y, bn = blockIdx.x;
    int wm = wid >> 2;
    int wn = wid & 3;

    float acc[4][8][4];
#pragma unroll
    for (int a = 0; a < 4; a++)
#pragma unroll
        for (int b = 0; b < 8; b++)
#pragma unroll
            for (int c = 0; c < 4; c++) acc[a][b][c] = 0.f;

    load_stage(sb, 0, Ah, Al, Bh, Bl, bm, bn, 0, tid); CP_COMMIT();
    load_stage(sb, 1, Ah, Al, Bh, Bl, bm, bn, 1, tid); CP_COMMIT();

    for (int kc = 0; kc < KT; kc++) {
        CP_WAIT(1);
        __syncthreads();
        if (kc + 2 < KT)
            load_stage(sb, (kc + 2) % 3, Ah, Al, Bh, Bl, bm, bn, kc + 2, tid);
        CP_COMMIT();

        uint32_t st = sb + (kc % 3) * STG_B;
#pragma unroll
        for (int ks = 0; ks < 2; ks++) {
            uint32_t bh[8][2], bl[8][2];
#pragma unroll
            for (int np = 0; np < 4; np++) {
                int r = wn * 64 + np * 16 + (lane & 7) + ((lane >> 4) & 1) * 8;
                int u = 2 * ks + ((lane >> 3) & 1);
                uint32_t ba = st + 2 * A_PL + swz(r, u);
                uint32_t t[4];
                ldsm4(t, ba);
                bh[np*2][0] = t[0]; bh[np*2][1] = t[1];
                bh[np*2+1][0] = t[2]; bh[np*2+1][1] = t[3];
                ldsm4(t, ba + B_PL);
                bl[np*2][0] = t[0]; bl[np*2][1] = t[1];
                bl[np*2+1][0] = t[2]; bl[np*2+1][1] = t[3];
            }
#pragma unroll
            for (int mt = 0; mt < 4; mt++) {
                int r = wm * 64 + mt * 16 + (lane & 15);
                int u = 2 * ks + (lane >> 4);
                uint32_t aa = st + swz(r, u);
                uint32_t ah[4], al[4];
                ldsm4(ah, aa);
                ldsm4(al, aa + A_PL);
                // three independent passes: same-acc distance = 8 mmas
#pragma unroll
                for (int nb = 0; nb < 8; nb++) mma16816(acc[mt][nb], ah, bh[nb]);
#pragma unroll
                for (int nb = 0; nb < 8; nb++) mma16816(acc[mt][nb], ah, bl[nb]);
#pragma unroll
                for (int nb = 0; nb < 8; nb++) mma16816(acc[mt][nb], al, bh[nb]);
            }
        }
    }

#pragma unroll
    for (int mt = 0; mt < 4; mt++)
#pragma unroll
        for (int nb = 0; nb < 8; nb++) {
            float* c = acc[mt][nb];
            int row = bm * 128 + wm * 64 + mt * 16 + (lane >> 2);
            int col = bn * 256 + wn * 64 + nb * 8 + 2 * (lane & 3);
            *(float2*)(out + (size_t)row * ldc + col) = make_float2(c[0], c[1]);
            *(float2*)(out + (size_t)(row + 8) * ldc + col) = make_float2(c[2], c[3]);
        }
}

// ---------------------------------------------------------------------------
// QKNorm + partial 2D RoPE (unchanged)
// ---------------------------------------------------------------------------
__global__ __launch_bounds__(256)
void norm_rope2(const float* __restrict__ qw, const float* __restrict__ kw) {
    int vec = blockIdx.x * 8 + (threadIdx.x >> 5);
    int lane = threadIdx.x & 31;
    int hh = vec % (NH + NKV);
    int row = vec / (NH + NKV);
    bool is_q = hh < NH;
    int col = is_q ? hh * HD : GDIM + (hh - NH) * HD;
    float* p = g_qkv + (size_t)row * QKV_N + col;
    float v0 = p[lane], v1 = p[lane + 32];
    float sq = v0 * v0 + v1 * v1;
#pragma unroll
    for (int o = 16; o; o >>= 1) sq += __shfl_xor_sync(0xffffffffu, sq, o);
    float scl = rsqrtf(sq * (1.0f / HD) + 1e-6f);
    const float* wv = is_q ? qw : kw;
    v0 *= scl * wv[lane];
    v1 *= scl * wv[lane + 32];
    int s = row % SEQ;
    if (s < NZ) {
        int j = lane & 15;
        float pos = (lane < 16) ? (float)(s >> 4) : (float)(s & 15);
        float invf = __expf(-(float)j * 0.57564627324851142f);
        float c, sn;
        sincosf(pos * invf, &sn, &c);
        float o0 = v0 * c - v1 * sn;
        float o1 = v1 * c + v0 * sn;
        v0 = o0; v1 = o1;
    }
    p[lane] = v0;
    p[lane + 32] = v1;
}

// ---------------------------------------------------------------------------
// Flash-style mma attention with de-serialized accumulator chains.
// ---------------------------------------------------------------------------
__device__ __forceinline__ void st_split4(char* hi, char* lo, float4 f) {
    uint32_t h0, l0, h1, l1;
    split2(f.x, f.y, h0, l0);
    split2(f.z, f.w, h1, l1);
    ((uint32_t*)hi)[0] = h0; ((uint32_t*)hi)[1] = h1;
    ((uint32_t*)lo)[0] = l0; ((uint32_t*)lo)[1] = l1;
}

__global__ __launch_bounds__(192, 1) void attn_mma() {
    extern __shared__ __align__(1024) char smem[];
    const int tid = threadIdx.x;
    const int mt = blockIdx.x, h = blockIdx.y, bt = blockIdx.z;
    const int m0 = (mt == 0) ? 0 : (mt == 1 ? 96 : 168);
    const int kvh = h >> 2;
    const float* gq = g_qkv + (size_t)bt * SEQ * QKV_N;
    const int kcol = GDIM + kvh * HD;
    const int vcol = GDIM + NKV * HD + kvh * HD;

    for (int idx = tid; idx < SEQ * 16; idx += 192) {
        int r = idx >> 4, u = idx & 15;
        const float* rp = gq + (size_t)r * QKV_N;
        float4 kk = *(const float4*)(rp + kcol + u * 4);
        float4 vv = *(const float4*)(rp + vcol + u * 4);
        int off = r * LDP + u * 8;
        st_split4(smem + SM_KHI + off, smem + SM_KLO + off, kk);
        st_split4(smem + SM_VHI + off, smem + SM_VLO + off, vv);
    }
    for (int idx = tid; idx < 96 * 16; idx += 192) {
        int r = idx >> 4, u = idx & 15;
        float4 qq = *(const float4*)(gq + (size_t)(m0 + r) * QKV_N + h * HD + u * 4);
        int off = r * LDP + u * 8;
        st_split4(smem + SM_QHI + off, smem + SM_QLO + off, qq);
    }
    for (int idx = tid; idx < 8 * 36; idx += 192) {
        int off = (SEQ + idx / 36) * LDP + (idx % 36) * 4;
        *(uint32_t*)(smem + SM_KHI + off) = 0;
        *(uint32_t*)(smem + SM_KLO + off) = 0;
        *(uint32_t*)(smem + SM_VHI + off) = 0;
        *(uint32_t*)(smem + SM_VLO + off) = 0;
    }
    __syncthreads();

    const uint32_t sb = smem_u32(smem);
    const int w = tid >> 5, lane = tid & 31;

    uint32_t qh[4][4], ql[4][4];
    {
        int r = w * 16 + (lane & 15);
        int uo = lane >> 4;
#pragma unroll
        for (int kc = 0; kc < 4; kc++) {
            uint32_t off = (uint32_t)(r * LDP + (2 * kc + uo) * 16);
            ldsm4(qh[kc], sb + SM_QHI + off);
            ldsm4(ql[kc], sb + SM_QLO + off);
        }
    }

    float oacc[8][4];
#pragma unroll
    for (int i = 0; i < 8; i++)
#pragma unroll
        for (int j = 0; j < 4; j++) oacc[i][j] = 0.f;
    float lsum0 = 0.f, lsum1 = 0.f;

    const int krow = (lane & 7) + ((lane >> 4) & 1) * 8;
    const int ku = (lane >> 3) & 1;
    const int vrow = (lane & 7) + ((lane >> 3) & 1) * 8;
    const int vu = (lane >> 4) & 1;

    for (int np = 0; np < 17; np++) {
        // ---- S = Q K^T: 6 independent accumulator chains (3 planes x 2 n8) ----
        float sA0[4] = {0,0,0,0}, sA1[4] = {0,0,0,0};
        float sB0[4] = {0,0,0,0}, sB1[4] = {0,0,0,0};
        float sC0[4] = {0,0,0,0}, sC1[4] = {0,0,0,0};
#pragma unroll
        for (int kc = 0; kc < 4; kc++) {
            uint32_t off = (uint32_t)((np * 16 + krow) * LDP + (2 * kc + ku) * 16);
            uint32_t bh[4], bl[4];
            ldsm4(bh, sb + SM_KHI + off);
            ldsm4(bl, sb + SM_KLO + off);
            mma16816(sA0, qh[kc], bh);
            mma16816(sA1, qh[kc], bh + 2);
            mma16816(sB0, qh[kc], bl);
            mma16816(sB1, qh[kc], bl + 2);
            mma16816(sC0, ql[kc], bh);
            mma16816(sC1, ql[kc], bh + 2);
        }
        // ---- softcap + exp ----
        float pf[2][4];
#pragma unroll
        for (int e = 0; e < 4; e++) {
            float s = (sA0[e] + sB0[e] + sC0[e]) * 0.125f;
            float t = __expf(-0.04f * fabsf(s));
            float th = __fdividef(1.f - t, 1.f + t);
            pf[0][e] = __expf((s >= 0.f) ? 50.f * th : -50.f * th);
            float s1 = (sA1[e] + sB1[e] + sC1[e]) * 0.125f;
            float t1 = __expf(-0.04f * fabsf(s1));
            float th1 = __fdividef(1.f - t1, 1.f + t1);
            pf[1][e] = __expf((s1 >= 0.f) ? 50.f * th1 : -50.f * th1);
        }
        if (np == 16) { pf[1][0] = pf[1][1] = pf[1][2] = pf[1][3] = 0.f; }
        lsum0 += pf[0][0] + pf[0][1] + pf[1][0] + pf[1][1];
        lsum1 += pf[0][2] + pf[0][3] + pf[1][2] + pf[1][3];

        uint32_t ph[4], pl[4];
        split2(pf[0][0], pf[0][1], ph[0], pl[0]);
        split2(pf[0][2], pf[0][3], ph[1], pl[1]);
        split2(pf[1][0], pf[1][1], ph[2], pl[2]);
        split2(pf[1][2], pf[1][3], ph[3], pl[3]);

        // ---- O += P V: preload all V frags, 3 passes of 8 independent mmas ----
        uint32_t vh[4][4], vl[4][4];
#pragma unroll
        for (int db = 0; db < 4; db++) {
            uint32_t off = (uint32_t)((np * 16 + vrow) * LDP + (2 * db + vu) * 16);
            ldsm4t(vh[db], sb + SM_VHI + off);
            ldsm4t(vl[db], sb + SM_VLO + off);
        }
#pragma unroll
        for (int db = 0; db < 4; db++) {
            mma16816(oacc[2*db],   ph, vh[db]);
            mma16816(oacc[2*db+1], ph, vh[db] + 2);
        }
#pragma unroll
        for (int db = 0; db < 4; db++) {
            mma16816(oacc[2*db],   ph, vl[db]);
            mma16816(oacc[2*db+1], ph, vl[db] + 2);
        }
#pragma unroll
        for (int db = 0; db < 4; db++) {
            mma16816(oacc[2*db],   pl, vh[db]);
            mma16816(oacc[2*db+1], pl, vh[db] + 2);
        }
    }

    lsum0 += __shfl_xor_sync(0xffffffffu, lsum0, 1);
    lsum0 += __shfl_xor_sync(0xffffffffu, lsum0, 2);
    lsum1 += __shfl_xor_sync(0xffffffffu, lsum1, 1);
    lsum1 += __shfl_xor_sync(0xffffffffu, lsum1, 2);
    float inv0 = __fdividef(1.f, lsum0);
    float inv1 = __fdividef(1.f, lsum1);

    size_t row0 = (size_t)bt * SEQ + m0 + w * 16 + (lane >> 2);
    int colb = h * HD + 2 * (lane & 3);
#pragma unroll
    for (int nb = 0; nb < 8; nb++) {
        int col = colb + nb * 8;
        uint32_t hv, lv;
        split2(oacc[nb][0] * inv0, oacc[nb][1] * inv0, hv, lv);
        *(uint32_t*)(g_ahi + row0 * GDIM + col) = hv;
        *(uint32_t*)(g_alo + row0 * GDIM + col) = lv;
        split2(oacc[nb][2] * inv1, oacc[nb][3] * inv1, hv, lv);
        *(uint32_t*)(g_ahi + (row0 + 8) * GDIM + col) = hv;
        *(uint32_t*)(g_alo + (row0 + 8) * GDIM + col) = lv;
    }
}

// ---------------------------------------------------------------------------
extern "C" void kernel_launch(void* const* d_in, const int* in_sizes, int n_in,
                              void* d_out, int out_size) {
    const float* x   = (const float*)d_in[0];
    const float* wq  = (const float*)d_in[1];
    const float* wk  = (const float*)d_in[2];
    const float* wv  = (const float*)d_in[3];
    const float* wo  = (const float*)d_in[4];
    const float* qnw = (const float*)d_in[5];
    const float* knw = (const float*)d_in[6];
    float* out = (float*)d_out;

    __nv_bfloat16 *xhi, *xlo, *whi, *wlo, *wohi, *wolo, *ahi, *alo;
    float* qkv;
    cudaGetSymbolAddress((void**)&xhi, g_xhi);
    cudaGetSymbolAddress((void**)&xlo, g_xlo);
    cudaGetSymbolAddress((void**)&whi, g_whi);
    cudaGetSymbolAddress((void**)&wlo, g_wlo);
    cudaGetSymbolAddress((void**)&wohi, g_wohi);
    cudaGetSymbolAddress((void**)&wolo, g_wolo);
    cudaGetSymbolAddress((void**)&ahi, g_ahi);
    cudaGetSymbolAddress((void**)&alo, g_alo);
    cudaGetSymbolAddress((void**)&qkv, g_qkv);

    cudaFuncSetAttribute((const void*)gemm_mma,
                         cudaFuncAttributeMaxDynamicSharedMemorySize, GEMM_SMEM);
    cudaFuncSetAttribute((const void*)attn_mma,
                         cudaFuncAttributeMaxDynamicSharedMemorySize, ATT_SMEM);

    // 1) split operands into bf16 hi/lo planes
    split_rm<<<4224, 256>>>(x, xhi, xlo, MROWS * GDIM / 8);
    split_w_qkv<<<768, 256>>>(wq, wk, wv);
    split_rm<<<512, 256>>>(wo, wohi, wolo, GDIM * GDIM / 8);

    // 2) QKV projection (block 128x256)
    gemm_mma<<<dim3(QKV_N / 256, MROWS / 128), 256, GEMM_SMEM>>>(
        xhi, xlo, whi, wlo, qkv, QKV_N);

    // 3) QKNorm + 2D RoPE
    norm_rope2<<<(MROWS * (NH + NKV)) / 8, 256>>>(qnw, knw);

    // 4) tensor-core attention
    attn_mma<<<dim3(3, NH, BTN), 192, ATT_SMEM>>>();

    // 5) output projection
    gemm_mma<<<dim3(GDIM / 256, MROWS / 128), 256, GEMM_SMEM>>>(
        ahi, alo, wohi, wolo, out, GDIM);
}

// round 7
// speedup vs baseline: 1.2536x; 1.2536x over previous
#include <cuda_runtime.h>
#include <cuda_bf16.h>
#include <stdint.h>
#include <math.h>

// Problem constants
#define BTN   64
#define SEQ   264
#define MROWS (BTN*SEQ)      // 16896
#define GDIM  1024
#define NH    16
#define NKV   4
#define HD    64
#define QKV_N 1536
#define NZ    256

// GEMM tiling: block 128x128, BK=32, 8 warps (warptile 64x32), 3-stage, 2 CTA/SM
#define BK    32
#define KT    (GDIM/BK)      // 32
#define PLANE_B 8192         // 128x32 bf16
#define STAGE_B 32768        // 4 planes
#define GEMM_SMEM (3*STAGE_B)   // 98304

// Attention smem layout (bf16 planes, rows padded to 72 elems = 144 B)
#define KPAD  272
#define LDP   144
#define KPL   (KPAD*LDP)
#define QPL   (96*LDP)
#define SM_KHI 0
#define SM_KLO (KPL)
#define SM_VHI (2*KPL)
#define SM_VLO (3*KPL)
#define SM_QHI (4*KPL)
#define SM_QLO (4*KPL + QPL)
#define ATT_SMEM (4*KPL + 2*QPL)   // 184320

// ---------------------------------------------------------------------------
// device scratch
// ---------------------------------------------------------------------------
__device__ __align__(16) __nv_bfloat16 g_xhi[(size_t)MROWS * GDIM];
__device__ __align__(16) __nv_bfloat16 g_xlo[(size_t)MROWS * GDIM];
__device__ __align__(16) __nv_bfloat16 g_whi[(size_t)QKV_N * GDIM];
__device__ __align__(16) __nv_bfloat16 g_wlo[(size_t)QKV_N * GDIM];
__device__ __align__(16) __nv_bfloat16 g_wohi[(size_t)GDIM * GDIM];
__device__ __align__(16) __nv_bfloat16 g_wolo[(size_t)GDIM * GDIM];
__device__ __align__(16) __nv_bfloat16 g_ahi[(size_t)MROWS * GDIM];
__device__ __align__(16) __nv_bfloat16 g_alo[(size_t)MROWS * GDIM];
__device__ __align__(16) float         g_qkv[(size_t)MROWS * QKV_N];
// attention operand planes (bf16 hi/lo), written by norm_rope_split
__device__ __align__(16) __nv_bfloat16 g_kphi[(size_t)BTN * NKV * SEQ * HD];
__device__ __align__(16) __nv_bfloat16 g_kplo[(size_t)BTN * NKV * SEQ * HD];
__device__ __align__(16) __nv_bfloat16 g_vphi[(size_t)BTN * NKV * SEQ * HD];
__device__ __align__(16) __nv_bfloat16 g_vplo[(size_t)BTN * NKV * SEQ * HD];
__device__ __align__(16) __nv_bfloat16 g_qphi[(size_t)BTN * NH * SEQ * HD];
__device__ __align__(16) __nv_bfloat16 g_qplo[(size_t)BTN * NH * SEQ * HD];

// ---------------------------------------------------------------------------
// helpers
// ---------------------------------------------------------------------------
__device__ __forceinline__ uint32_t smem_u32(const void* p) {
    uint32_t a;
    asm("{ .reg .u64 t; cvta.to.shared.u64 t, %1; cvt.u32.u64 %0, t; }"
        : "=r"(a) : "l"(p));
    return a;
}
__device__ __forceinline__ void cp16(uint32_t dst, const void* src) {
    asm volatile("cp.async.cg.shared.global [%0], [%1], 16;" :: "r"(dst), "l"(src));
}
#define CP_COMMIT() asm volatile("cp.async.commit_group;" ::: "memory")
#define CP_WAIT(n)  asm volatile("cp.async.wait_group %0;" :: "n"(n) : "memory")

__device__ __forceinline__ void ldsm4(uint32_t* r, uint32_t addr) {
    asm volatile("ldmatrix.sync.aligned.m8n8.x4.shared.b16 {%0,%1,%2,%3}, [%4];"
                 : "=r"(r[0]), "=r"(r[1]), "=r"(r[2]), "=r"(r[3]) : "r"(addr));
}
__device__ __forceinline__ void ldsm4t(uint32_t* r, uint32_t addr) {
    asm volatile("ldmatrix.sync.aligned.m8n8.x4.trans.shared.b16 {%0,%1,%2,%3}, [%4];"
                 : "=r"(r[0]), "=r"(r[1]), "=r"(r[2]), "=r"(r[3]) : "r"(addr));
}
__device__ __forceinline__ void mma16816(float* c, const uint32_t* a, const uint32_t* b) {
    asm volatile(
        "mma.sync.aligned.m16n8k16.row.col.f32.bf16.bf16.f32 "
        "{%0,%1,%2,%3}, {%4,%5,%6,%7}, {%8,%9}, {%0,%1,%2,%3};"
        : "+f"(c[0]), "+f"(c[1]), "+f"(c[2]), "+f"(c[3])
        : "r"(a[0]), "r"(a[1]), "r"(a[2]), "r"(a[3]), "r"(b[0]), "r"(b[1]));
}

// swizzled byte offset of 16B unit (r, u) within an Nx32 bf16 plane (64B rows)
__device__ __forceinline__ uint32_t swz(int r, int u) {
    return (uint32_t)(r * 64 + ((u ^ ((r >> 1) & 3)) << 4));
}

// split two floats -> hi bf16x2 + lo bf16x2
__device__ __forceinline__ void split2(float a, float b, uint32_t& h, uint32_t& l) {
    __nv_bfloat16 ha = __float2bfloat16(a);
    __nv_bfloat16 hb = __float2bfloat16(b);
    float ra = a - __bfloat162float(ha);
    float rb = b - __bfloat162float(hb);
    h = (uint32_t)__bfloat16_as_ushort(ha) | ((uint32_t)__bfloat16_as_ushort(hb) << 16);
    l = (uint32_t)__bfloat16_as_ushort(__float2bfloat16(ra)) |
        ((uint32_t)__bfloat16_as_ushort(__float2bfloat16(rb)) << 16);
}

__device__ __forceinline__ void split8(const float* __restrict__ s, uint4& hv, uint4& lv) {
    float4 f0 = *(const float4*)s;
    float4 f1 = *(const float4*)(s + 4);
    split2(f0.x, f0.y, hv.x, lv.x);
    split2(f0.z, f0.w, hv.y, lv.y);
    split2(f1.x, f1.y, hv.z, lv.z);
    split2(f1.z, f1.w, hv.w, lv.w);
}

// ---------------------------------------------------------------------------
// split kernels (GEMM operands)
// ---------------------------------------------------------------------------
__global__ void split_rm(const float* __restrict__ src, __nv_bfloat16* __restrict__ hi,
                         __nv_bfloat16* __restrict__ lo, int nunits) {
    for (int i = blockIdx.x * blockDim.x + threadIdx.x; i < nunits;
         i += gridDim.x * blockDim.x) {
        uint4 hv, lv;
        split8(src + (size_t)i * 8, hv, lv);
        ((uint4*)hi)[i] = hv;
        ((uint4*)lo)[i] = lv;
    }
}

__global__ void split_w_qkv(const float* __restrict__ wq, const float* __restrict__ wk,
                            const float* __restrict__ wv) {
    int nunits = QKV_N * (GDIM / 8);
    for (int i = blockIdx.x * blockDim.x + threadIdx.x; i < nunits;
         i += gridDim.x * blockDim.x) {
        int row = i >> 7, ur = i & 127;
        const float* srow;
        if (row < NH * HD)                srow = wq + (size_t)row * GDIM;
        else if (row < NH*HD + NKV*HD)    srow = wk + (size_t)(row - NH*HD) * GDIM;
        else                              srow = wv + (size_t)(row - NH*HD - NKV*HD) * GDIM;
        uint4 hv, lv;
        split8(srow + ur * 8, hv, lv);
        ((uint4*)g_whi)[i] = hv;
        ((uint4*)g_wlo)[i] = lv;
    }
}

// ---------------------------------------------------------------------------
// bf16x3 GEMM via mma.sync: 128x128 tile, BK=32, 8 warps, 3-stage, 2 CTA/SM
// ---------------------------------------------------------------------------
__device__ __forceinline__ void load_stage(uint32_t sb, int stage,
        const __nv_bfloat16* __restrict__ Ah, const __nv_bfloat16* __restrict__ Al,
        const __nv_bfloat16* __restrict__ Bh, const __nv_bfloat16* __restrict__ Bl,
        int bm, int bn, int kc, int tid) {
    uint32_t st = sb + stage * STAGE_B;
#pragma unroll
    for (int i = 0; i < 8; i++) {
        int v = i * 256 + tid;
        int op = v >> 9;          // 0:Ah 1:Al 2:Bh 3:Bl
        int w = v & 511;
        int r = w >> 2, u = w & 3;
        const __nv_bfloat16* base = (op == 0) ? Ah : (op == 1) ? Al : (op == 2) ? Bh : Bl;
        int grow = ((op < 2) ? bm : bn) * 128 + r;
        const __nv_bfloat16* g = base + (size_t)grow * GDIM + kc * BK + u * 8;
        cp16(st + op * PLANE_B + swz(r, u), g);
    }
}

__global__ __launch_bounds__(256, 2)
void gemm_mma(const __nv_bfloat16* __restrict__ Ah, const __nv_bfloat16* __restrict__ Al,
              const __nv_bfloat16* __restrict__ Bh, const __nv_bfloat16* __restrict__ Bl,
              float* __restrict__ out, int ldc) {
    extern __shared__ __align__(1024) char smem[];
    uint32_t sb = smem_u32(smem);
    int tid = threadIdx.x, wid = tid >> 5, lane = tid & 31;
    int bm = blockIdx.y, bn = blockIdx.x;
    int wm = wid >> 2;        // 0..1 -> m offset wm*64
    int wn = wid & 3;         // 0..3 -> n offset wn*32

    float acc[4][4][4];
#pragma unroll
    for (int a = 0; a < 4; a++)
#pragma unroll
        for (int b = 0; b < 4; b++)
#pragma unroll
            for (int c = 0; c < 4; c++) acc[a][b][c] = 0.f;

    load_stage(sb, 0, Ah, Al, Bh, Bl, bm, bn, 0, tid); CP_COMMIT();
    load_stage(sb, 1, Ah, Al, Bh, Bl, bm, bn, 1, tid); CP_COMMIT();

    for (int kc = 0; kc < KT; kc++) {
        CP_WAIT(1);
        __syncthreads();
        if (kc + 2 < KT)
            load_stage(sb, (kc + 2) % 3, Ah, Al, Bh, Bl, bm, bn, kc + 2, tid);
        CP_COMMIT();

        uint32_t st = sb + (kc % 3) * STAGE_B;
#pragma unroll
        for (int ks = 0; ks < 2; ks++) {
            uint32_t ahf[4][4], alf[4][4], bhf[4][2], blf[4][2];
#pragma unroll
            for (int mt = 0; mt < 4; mt++) {
                int r = wm * 64 + mt * 16 + (lane & 15);
                int u = 2 * ks + (lane >> 4);
                uint32_t a_addr = st + swz(r, u);
                ldsm4(ahf[mt], a_addr);
                ldsm4(alf[mt], a_addr + PLANE_B);
            }
#pragma unroll
            for (int np = 0; np < 2; np++) {
                int r = wn * 32 + np * 16 + (lane & 7) + ((lane >> 4) & 1) * 8;
                int u = 2 * ks + ((lane >> 3) & 1);
                uint32_t b_addr = st + 2 * PLANE_B + swz(r, u);
                uint32_t t[4];
                ldsm4(t, b_addr);
                bhf[np*2][0] = t[0]; bhf[np*2][1] = t[1];
                bhf[np*2+1][0] = t[2]; bhf[np*2+1][1] = t[3];
                ldsm4(t, b_addr + PLANE_B);
                blf[np*2][0] = t[0]; blf[np*2][1] = t[1];
                blf[np*2+1][0] = t[2]; blf[np*2+1][1] = t[3];
            }
            // three independent passes over 16 accs -> no RAW stalls
#pragma unroll
            for (int mt = 0; mt < 4; mt++)
#pragma unroll
                for (int nt = 0; nt < 4; nt++) mma16816(acc[mt][nt], ahf[mt], bhf[nt]);
#pragma unroll
            for (int mt = 0; mt < 4; mt++)
#pragma unroll
                for (int nt = 0; nt < 4; nt++) mma16816(acc[mt][nt], ahf[mt], blf[nt]);
#pragma unroll
            for (int mt = 0; mt < 4; mt++)
#pragma unroll
                for (int nt = 0; nt < 4; nt++) mma16816(acc[mt][nt], alf[mt], bhf[nt]);
        }
    }

#pragma unroll
    for (int mt = 0; mt < 4; mt++)
#pragma unroll
        for (int nt = 0; nt < 4; nt++) {
            float* c = acc[mt][nt];
            int row = bm * 128 + wm * 64 + mt * 16 + (lane >> 2);
            int col = bn * 128 + wn * 32 + nt * 8 + 2 * (lane & 3);
            *(float2*)(out + (size_t)row * ldc + col) = make_float2(c[0], c[1]);
            *(float2*)(out + (size_t)(row + 8) * ldc + col) = make_float2(c[2], c[3]);
        }
}

// ---------------------------------------------------------------------------
// QKNorm + partial 2D RoPE + split to attn operand planes.
// One warp per (row, vec): vec 0..15 q heads, 16..19 k heads, 20..23 v heads.
// ---------------------------------------------------------------------------
__global__ __launch_bounds__(256)
void norm_rope_split(const float* __restrict__ qw, const float* __restrict__ kw) {
    int vec = blockIdx.x * 8 + (threadIdx.x >> 5);
    int lane = threadIdx.x & 31;
    int hh = vec % 24;
    int row = vec / 24;
    int bt = row / SEQ, s = row - bt * SEQ;

    const float* p;
    __nv_bfloat16 *hip, *lop;
    if (hh < NH) {
        p = g_qkv + (size_t)row * QKV_N + hh * HD;
        size_t o = ((size_t)(bt * NH + hh) * SEQ + s) * HD;
        hip = g_qphi + o; lop = g_qplo + o;
    } else if (hh < NH + NKV) {
        p = g_qkv + (size_t)row * QKV_N + GDIM + (hh - NH) * HD;
        size_t o = ((size_t)(bt * NKV + (hh - NH)) * SEQ + s) * HD;
        hip = g_kphi + o; lop = g_kplo + o;
    } else {
        p = g_qkv + (size_t)row * QKV_N + GDIM + NKV * HD + (hh - NH - NKV) * HD;
        size_t o = ((size_t)(bt * NKV + (hh - NH - NKV)) * SEQ + s) * HD;
        hip = g_vphi + o; lop = g_vplo + o;
    }
    float v0 = p[lane], v1 = p[lane + 32];

    if (hh < NH + NKV) {  // q/k: RMSNorm + RoPE; v: raw
        float sq = v0 * v0 + v1 * v1;
#pragma unroll
        for (int o = 16; o; o >>= 1) sq += __shfl_xor_sync(0xffffffffu, sq, o);
        float scl = rsqrtf(sq * (1.0f / HD) + 1e-6f);
        const float* wv = (hh < NH) ? qw : kw;
        v0 *= scl * wv[lane];
        v1 *= scl * wv[lane + 32];
        if (s < NZ) {
            int j = lane & 15;
            float pos = (lane < 16) ? (float)(s >> 4) : (float)(s & 15);
            float invf = __expf(-(float)j * 0.57564627324851142f);
            float c, sn;
            sincosf(pos * invf, &sn, &c);
            float o0 = v0 * c - v1 * sn;
            float o1 = v1 * c + v0 * sn;
            v0 = o0; v1 = o1;
        }
    }
    __nv_bfloat16 h0 = __float2bfloat16(v0);
    __nv_bfloat16 h1 = __float2bfloat16(v1);
    hip[lane] = h0;
    hip[lane + 32] = h1;
    lop[lane] = __float2bfloat16(v0 - __bfloat162float(h0));
    lop[lane + 32] = __float2bfloat16(v1 - __bfloat162float(h1));
}

// ---------------------------------------------------------------------------
// Flash-style mma attention; operands pre-split in gmem, loaded via cp.async.
// ---------------------------------------------------------------------------
__global__ __launch_bounds__(192, 1) void attn_mma() {
    extern __shared__ __align__(1024) char smem[];
    const int tid = threadIdx.x;
    const int mt = blockIdx.x, h = blockIdx.y, bt = blockIdx.z;
    const int m0 = (mt == 0) ? 0 : (mt == 1 ? 96 : 168);
    const int kvh = h >> 2;
    const uint32_t sb = smem_u32(smem);

    // ---- async load of pre-split planes ----
    {
        size_t kvo = (size_t)(bt * NKV + kvh) * SEQ * HD;
        const __nv_bfloat16* kh = g_kphi + kvo;
        const __nv_bfloat16* kl = g_kplo + kvo;
        const __nv_bfloat16* vh = g_vphi + kvo;
        const __nv_bfloat16* vl = g_vplo + kvo;
        for (int idx = tid; idx < SEQ * 8; idx += 192) {
            int r = idx >> 3, u = idx & 7;
            uint32_t doff = (uint32_t)(r * LDP + u * 16);
            int soff = r * HD + u * 8;
            cp16(sb + SM_KHI + doff, kh + soff);
            cp16(sb + SM_KLO + doff, kl + soff);
            cp16(sb + SM_VHI + doff, vh + soff);
            cp16(sb + SM_VLO + doff, vl + soff);
        }
        size_t qo = ((size_t)(bt * NH + h) * SEQ + m0) * HD;
        const __nv_bfloat16* qh_ = g_qphi + qo;
        const __nv_bfloat16* ql_ = g_qplo + qo;
        for (int idx = tid; idx < 96 * 8; idx += 192) {
            int r = idx >> 3, u = idx & 7;
            uint32_t doff = (uint32_t)(r * LDP + u * 16);
            int soff = r * HD + u * 8;
            cp16(sb + SM_QHI + doff, qh_ + soff);
            cp16(sb + SM_QLO + doff, ql_ + soff);
        }
        CP_COMMIT();
    }
    // zero pad rows 264..271 of K/V planes (regular STS, independent of cp.async)
    for (int idx = tid; idx < 8 * 32; idx += 192) {
        int off = (SEQ + (idx >> 5)) * LDP + (idx & 31) * 4;
        *(uint32_t*)(smem + SM_KHI + off) = 0;
        *(uint32_t*)(smem + SM_KLO + off) = 0;
        *(uint32_t*)(smem + SM_VHI + off) = 0;
        *(uint32_t*)(smem + SM_VLO + off) = 0;
    }
    CP_WAIT(0);
    __syncthreads();

    const int w = tid >> 5, lane = tid & 31;

    uint32_t qh[4][4], ql[4][4];
    {
        int r = w * 16 + (lane & 15);
        int uo = lane >> 4;
#pragma unroll
        for (int kc = 0; kc < 4; kc++) {
            uint32_t off = (uint32_t)(r * LDP + (2 * kc + uo) * 16);
            ldsm4(qh[kc], sb + SM_QHI + off);
            ldsm4(ql[kc], sb + SM_QLO + off);
        }
    }

    float oacc[8][4];
#pragma unroll
    for (int i = 0; i < 8; i++)
#pragma unroll
        for (int j = 0; j < 4; j++) oacc[i][j] = 0.f;
    float lsum0 = 0.f, lsum1 = 0.f;

    const int krow = (lane & 7) + ((lane >> 4) & 1) * 8;
    const int ku = (lane >> 3) & 1;
    const int vrow = (lane & 7) + ((lane >> 3) & 1) * 8;
    const int vu = (lane >> 4) & 1;

    for (int np = 0; np < 17; np++) {
        float sA0[4] = {0,0,0,0}, sA1[4] = {0,0,0,0};
        float sB0[4] = {0,0,0,0}, sB1[4] = {0,0,0,0};
        float sC0[4] = {0,0,0,0}, sC1[4] = {0,0,0,0};
#pragma unroll
        for (int kc = 0; kc < 4; kc++) {
            uint32_t off = (uint32_t)((np * 16 + krow) * LDP + (2 * kc + ku) * 16);
            uint32_t bh[4], bl[4];
            ldsm4(bh, sb + SM_KHI + off);
            ldsm4(bl, sb + SM_KLO + off);
            mma16816(sA0, qh[kc], bh);
            mma16816(sA1, qh[kc], bh + 2);
            mma16816(sB0, qh[kc], bl);
            mma16816(sB1, qh[kc], bl + 2);
            mma16816(sC0, ql[kc], bh);
            mma16816(sC1, ql[kc], bh + 2);
        }
        float pf[2][4];
#pragma unroll
        for (int e = 0; e < 4; e++) {
            float s = (sA0[e] + sB0[e] + sC0[e]) * 0.125f;
            float t = __expf(-0.04f * fabsf(s));
            float th = __fdividef(1.f - t, 1.f + t);
            pf[0][e] = __expf((s >= 0.f) ? 50.f * th : -50.f * th);
            float s1 = (sA1[e] + sB1[e] + sC1[e]) * 0.125f;
            float t1 = __expf(-0.04f * fabsf(s1));
            float th1 = __fdividef(1.f - t1, 1.f + t1);
            pf[1][e] = __expf((s1 >= 0.f) ? 50.f * th1 : -50.f * th1);
        }
        if (np == 16) { pf[1][0] = pf[1][1] = pf[1][2] = pf[1][3] = 0.f; }
        lsum0 += pf[0][0] + pf[0][1] + pf[1][0] + pf[1][1];
        lsum1 += pf[0][2] + pf[0][3] + pf[1][2] + pf[1][3];

        uint32_t ph[4], pl[4];
        split2(pf[0][0], pf[0][1], ph[0], pl[0]);
        split2(pf[0][2], pf[0][3], ph[1], pl[1]);
        split2(pf[1][0], pf[1][1], ph[2], pl[2]);
        split2(pf[1][2], pf[1][3], ph[3], pl[3]);

        uint32_t vh[4][4], vl[4][4];
#pragma unroll
        for (int db = 0; db < 4; db++) {
            uint32_t off = (uint32_t)((np * 16 + vrow) * LDP + (2 * db + vu) * 16);
            ldsm4t(vh[db], sb + SM_VHI + off);
            ldsm4t(vl[db], sb + SM_VLO + off);
        }
#pragma unroll
        for (int db = 0; db < 4; db++) {
            mma16816(oacc[2*db],   ph, vh[db]);
            mma16816(oacc[2*db+1], ph, vh[db] + 2);
        }
#pragma unroll
        for (int db = 0; db < 4; db++) {
            mma16816(oacc[2*db],   ph, vl[db]);
            mma16816(oacc[2*db+1], ph, vl[db] + 2);
        }
#pragma unroll
        for (int db = 0; db < 4; db++) {
            mma16816(oacc[2*db],   pl, vh[db]);
            mma16816(oacc[2*db+1], pl, vh[db] + 2);
        }
    }

    lsum0 += __shfl_xor_sync(0xffffffffu, lsum0, 1);
    lsum0 += __shfl_xor_sync(0xffffffffu, lsum0, 2);
    lsum1 += __shfl_xor_sync(0xffffffffu, lsum1, 1);
    lsum1 += __shfl_xor_sync(0xffffffffu, lsum1, 2);
    float inv0 = __fdividef(1.f, lsum0);
    float inv1 = __fdividef(1.f, lsum1);

    size_t row0 = (size_t)bt * SEQ + m0 + w * 16 + (lane >> 2);
    int colb = h * HD + 2 * (lane & 3);
#pragma unroll
    for (int nb = 0; nb < 8; nb++) {
        int col = colb + nb * 8;
        uint32_t hv, lv;
        split2(oacc[nb][0] * inv0, oacc[nb][1] * inv0, hv, lv);
        *(uint32_t*)(g_ahi + row0 * GDIM + col) = hv;
        *(uint32_t*)(g_alo + row0 * GDIM + col) = lv;
        split2(oacc[nb][2] * inv1, oacc[nb][3] * inv1, hv, lv);
        *(uint32_t*)(g_ahi + (row0 + 8) * GDIM + col) = hv;
        *(uint32_t*)(g_alo + (row0 + 8) * GDIM + col) = lv;
    }
}

// ---------------------------------------------------------------------------
extern "C" void kernel_launch(void* const* d_in, const int* in_sizes, int n_in,
                              void* d_out, int out_size) {
    const float* x   = (const float*)d_in[0];
    const float* wq  = (const float*)d_in[1];
    const float* wk  = (const float*)d_in[2];
    const float* wv  = (const float*)d_in[3];
    const float* wo  = (const float*)d_in[4];
    const float* qnw = (const float*)d_in[5];
    const float* knw = (const float*)d_in[6];
    float* out = (float*)d_out;

    __nv_bfloat16 *xhi, *xlo, *whi, *wlo, *wohi, *wolo, *ahi, *alo;
    float* qkv;
    cudaGetSymbolAddress((void**)&xhi, g_xhi);
    cudaGetSymbolAddress((void**)&xlo, g_xlo);
    cudaGetSymbolAddress((void**)&whi, g_whi);
    cudaGetSymbolAddress((void**)&wlo, g_wlo);
    cudaGetSymbolAddress((void**)&wohi, g_wohi);
    cudaGetSymbolAddress((void**)&wolo, g_wolo);
    cudaGetSymbolAddress((void**)&ahi, g_ahi);
    cudaGetSymbolAddress((void**)&alo, g_alo);
    cudaGetSymbolAddress((void**)&qkv, g_qkv);

    cudaFuncSetAttribute((const void*)gemm_mma,
                         cudaFuncAttributeMaxDynamicSharedMemorySize, GEMM_SMEM);
    cudaFuncSetAttribute((const void*)attn_mma,
                         cudaFuncAttributeMaxDynamicSharedMemorySize, ATT_SMEM);

    // 1) split operands into bf16 hi/lo planes
    split_rm<<<4224, 256>>>(x, xhi, xlo, MROWS * GDIM / 8);
    split_w_qkv<<<768, 256>>>(wq, wk, wv);
    split_rm<<<512, 256>>>(wo, wohi, wolo, GDIM * GDIM / 8);

    // 2) QKV projection (128x128 tiles, 2 CTA/SM)
    gemm_mma<<<dim3(QKV_N / 128, MROWS / 128), 256, GEMM_SMEM>>>(
        xhi, xlo, whi, wlo, qkv, QKV_N);

    // 3) QKNorm + 2D RoPE + split into attention planes
    norm_rope_split<<<MROWS * 3, 256>>>(qnw, knw);

    // 4) tensor-core attention (pure cp.async operand load)
    attn_mma<<<dim3(3, NH, BTN), 192, ATT_SMEM>>>();

    // 5) output projection
    gemm_mma<<<dim3(GDIM / 128, MROWS / 128), 256, GEMM_SMEM>>>(
        ahi, alo, wohi, wolo, out, GDIM);
}

// round 8
// speedup vs baseline: 1.4093x; 1.1241x over previous
#include <cuda_runtime.h>
#include <cuda_bf16.h>
#include <stdint.h>
#include <math.h>

// Problem constants
#define BTN   64
#define SEQ   264
#define MROWS (BTN*SEQ)      // 16896
#define GDIM  1024
#define NH    16
#define NKV   4
#define HD    64
#define QKV_N 1536
#define NZ    256

// GEMM tiling: block 128x128, BK=32, 8 warps (warptile 64x32), 3-stage, 2 CTA/SM
#define BK    32
#define KT    (GDIM/BK)      // 32
#define PLANE_B 8192         // 128x32 bf16
#define STAGE_B 32768        // 4 planes
#define GEMM_SMEM (3*STAGE_B)   // 98304

// Attention smem: chunked K/V (144-key buffer) + Q planes; 2 CTA/SM
#define LDP   144
#define CH_ROWS 144
#define SM_KHI 0
#define SM_KLO (CH_ROWS*LDP)        // 20736
#define SM_VHI (2*CH_ROWS*LDP)
#define SM_VLO (3*CH_ROWS*LDP)
#define SM_QHI (4*CH_ROWS*LDP)     // 82944
#define SM_QLO (SM_QHI + 96*LDP)   // 96768
#define ATT_SMEM (SM_QLO + 96*LDP) // 110592

// ---------------------------------------------------------------------------
// device scratch
// ---------------------------------------------------------------------------
__device__ __align__(16) __nv_bfloat16 g_xhi[(size_t)MROWS * GDIM];
__device__ __align__(16) __nv_bfloat16 g_xlo[(size_t)MROWS * GDIM];
__device__ __align__(16) __nv_bfloat16 g_whi[(size_t)QKV_N * GDIM];
__device__ __align__(16) __nv_bfloat16 g_wlo[(size_t)QKV_N * GDIM];
__device__ __align__(16) __nv_bfloat16 g_wohi[(size_t)GDIM * GDIM];
__device__ __align__(16) __nv_bfloat16 g_wolo[(size_t)GDIM * GDIM];
__device__ __align__(16) __nv_bfloat16 g_ahi[(size_t)MROWS * GDIM];
__device__ __align__(16) __nv_bfloat16 g_alo[(size_t)MROWS * GDIM];
__device__ __align__(16) float         g_qkv[(size_t)MROWS * QKV_N];
// attention operand planes (bf16 hi/lo), written by norm_rope_split
__device__ __align__(16) __nv_bfloat16 g_kphi[(size_t)BTN * NKV * SEQ * HD];
__device__ __align__(16) __nv_bfloat16 g_kplo[(size_t)BTN * NKV * SEQ * HD];
__device__ __align__(16) __nv_bfloat16 g_vphi[(size_t)BTN * NKV * SEQ * HD];
__device__ __align__(16) __nv_bfloat16 g_vplo[(size_t)BTN * NKV * SEQ * HD];
__device__ __align__(16) __nv_bfloat16 g_qphi[(size_t)BTN * NH * SEQ * HD];
__device__ __align__(16) __nv_bfloat16 g_qplo[(size_t)BTN * NH * SEQ * HD];

// ---------------------------------------------------------------------------
// helpers
// ---------------------------------------------------------------------------
__device__ __forceinline__ uint32_t smem_u32(const void* p) {
    uint32_t a;
    asm("{ .reg .u64 t; cvta.to.shared.u64 t, %1; cvt.u32.u64 %0, t; }"
        : "=r"(a) : "l"(p));
    return a;
}
__device__ __forceinline__ void cp16(uint32_t dst, const void* src) {
    asm volatile("cp.async.cg.shared.global [%0], [%1], 16;" :: "r"(dst), "l"(src));
}
#define CP_COMMIT() asm volatile("cp.async.commit_group;" ::: "memory")
#define CP_WAIT(n)  asm volatile("cp.async.wait_group %0;" :: "n"(n) : "memory")

__device__ __forceinline__ void ldsm4(uint32_t* r, uint32_t addr) {
    asm volatile("ldmatrix.sync.aligned.m8n8.x4.shared.b16 {%0,%1,%2,%3}, [%4];"
                 : "=r"(r[0]), "=r"(r[1]), "=r"(r[2]), "=r"(r[3]) : "r"(addr));
}
__device__ __forceinline__ void ldsm4t(uint32_t* r, uint32_t addr) {
    asm volatile("ldmatrix.sync.aligned.m8n8.x4.trans.shared.b16 {%0,%1,%2,%3}, [%4];"
                 : "=r"(r[0]), "=r"(r[1]), "=r"(r[2]), "=r"(r[3]) : "r"(addr));
}
__device__ __forceinline__ void mma16816(float* c, const uint32_t* a, const uint32_t* b) {
    asm volatile(
        "mma.sync.aligned.m16n8k16.row.col.f32.bf16.bf16.f32 "
        "{%0,%1,%2,%3}, {%4,%5,%6,%7}, {%8,%9}, {%0,%1,%2,%3};"
        : "+f"(c[0]), "+f"(c[1]), "+f"(c[2]), "+f"(c[3])
        : "r"(a[0]), "r"(a[1]), "r"(a[2]), "r"(a[3]), "r"(b[0]), "r"(b[1]));
}

// swizzled byte offset of 16B unit (r, u) within an Nx32 bf16 plane (64B rows)
__device__ __forceinline__ uint32_t swz(int r, int u) {
    return (uint32_t)(r * 64 + ((u ^ ((r >> 1) & 3)) << 4));
}

// split two floats -> hi bf16x2 + lo bf16x2
__device__ __forceinline__ void split2(float a, float b, uint32_t& h, uint32_t& l) {
    __nv_bfloat16 ha = __float2bfloat16(a);
    __nv_bfloat16 hb = __float2bfloat16(b);
    float ra = a - __bfloat162float(ha);
    float rb = b - __bfloat162float(hb);
    h = (uint32_t)__bfloat16_as_ushort(ha) | ((uint32_t)__bfloat16_as_ushort(hb) << 16);
    l = (uint32_t)__bfloat16_as_ushort(__float2bfloat16(ra)) |
        ((uint32_t)__bfloat16_as_ushort(__float2bfloat16(rb)) << 16);
}

__device__ __forceinline__ void split8(const float* __restrict__ s, uint4& hv, uint4& lv) {
    float4 f0 = *(const float4*)s;
    float4 f1 = *(const float4*)(s + 4);
    split2(f0.x, f0.y, hv.x, lv.x);
    split2(f0.z, f0.w, hv.y, lv.y);
    split2(f1.x, f1.y, hv.z, lv.z);
    split2(f1.z, f1.w, hv.w, lv.w);
}

// ---------------------------------------------------------------------------
// split kernels (GEMM operands)
// ---------------------------------------------------------------------------
__global__ void split_rm(const float* __restrict__ src, __nv_bfloat16* __restrict__ hi,
                         __nv_bfloat16* __restrict__ lo, int nunits) {
    for (int i = blockIdx.x * blockDim.x + threadIdx.x; i < nunits;
         i += gridDim.x * blockDim.x) {
        uint4 hv, lv;
        split8(src + (size_t)i * 8, hv, lv);
        ((uint4*)hi)[i] = hv;
        ((uint4*)lo)[i] = lv;
    }
}

__global__ void split_w_qkv(const float* __restrict__ wq, const float* __restrict__ wk,
                            const float* __restrict__ wv) {
    int nunits = QKV_N * (GDIM / 8);
    for (int i = blockIdx.x * blockDim.x + threadIdx.x; i < nunits;
         i += gridDim.x * blockDim.x) {
        int row = i >> 7, ur = i & 127;
        const float* srow;
        if (row < NH * HD)                srow = wq + (size_t)row * GDIM;
        else if (row < NH*HD + NKV*HD)    srow = wk + (size_t)(row - NH*HD) * GDIM;
        else                              srow = wv + (size_t)(row - NH*HD - NKV*HD) * GDIM;
        uint4 hv, lv;
        split8(srow + ur * 8, hv, lv);
        ((uint4*)g_whi)[i] = hv;
        ((uint4*)g_wlo)[i] = lv;
    }
}

// ---------------------------------------------------------------------------
// bf16x3 GEMM via mma.sync: 128x128 tile, BK=32, 8 warps, 3-stage, 2 CTA/SM
// ---------------------------------------------------------------------------
__device__ __forceinline__ void load_stage(uint32_t sb, int stage,
        const __nv_bfloat16* __restrict__ Ah, const __nv_bfloat16* __restrict__ Al,
        const __nv_bfloat16* __restrict__ Bh, const __nv_bfloat16* __restrict__ Bl,
        int bm, int bn, int kc, int tid) {
    uint32_t st = sb + stage * STAGE_B;
#pragma unroll
    for (int i = 0; i < 8; i++) {
        int v = i * 256 + tid;
        int op = v >> 9;          // 0:Ah 1:Al 2:Bh 3:Bl
        int w = v & 511;
        int r = w >> 2, u = w & 3;
        const __nv_bfloat16* base = (op == 0) ? Ah : (op == 1) ? Al : (op == 2) ? Bh : Bl;
        int grow = ((op < 2) ? bm : bn) * 128 + r;
        const __nv_bfloat16* g = base + (size_t)grow * GDIM + kc * BK + u * 8;
        cp16(st + op * PLANE_B + swz(r, u), g);
    }
}

__global__ __launch_bounds__(256, 2)
void gemm_mma(const __nv_bfloat16* __restrict__ Ah, const __nv_bfloat16* __restrict__ Al,
              const __nv_bfloat16* __restrict__ Bh, const __nv_bfloat16* __restrict__ Bl,
              float* __restrict__ out, int ldc) {
    extern __shared__ __align__(1024) char smem[];
    uint32_t sb = smem_u32(smem);
    int tid = threadIdx.x, wid = tid >> 5, lane = tid & 31;
    int bm = blockIdx.y, bn = blockIdx.x;
    int wm = wid >> 2;
    int wn = wid & 3;

    float acc[4][4][4];
#pragma unroll
    for (int a = 0; a < 4; a++)
#pragma unroll
        for (int b = 0; b < 4; b++)
#pragma unroll
            for (int c = 0; c < 4; c++) acc[a][b][c] = 0.f;

    load_stage(sb, 0, Ah, Al, Bh, Bl, bm, bn, 0, tid); CP_COMMIT();
    load_stage(sb, 1, Ah, Al, Bh, Bl, bm, bn, 1, tid); CP_COMMIT();

    for (int kc = 0; kc < KT; kc++) {
        CP_WAIT(1);
        __syncthreads();
        if (kc + 2 < KT)
            load_stage(sb, (kc + 2) % 3, Ah, Al, Bh, Bl, bm, bn, kc + 2, tid);
        CP_COMMIT();

        uint32_t st = sb + (kc % 3) * STAGE_B;
#pragma unroll
        for (int ks = 0; ks < 2; ks++) {
            uint32_t ahf[4][4], alf[4][4], bhf[4][2], blf[4][2];
#pragma unroll
            for (int mt = 0; mt < 4; mt++) {
                int r = wm * 64 + mt * 16 + (lane & 15);
                int u = 2 * ks + (lane >> 4);
                uint32_t a_addr = st + swz(r, u);
                ldsm4(ahf[mt], a_addr);
                ldsm4(alf[mt], a_addr + PLANE_B);
            }
#pragma unroll
            for (int np = 0; np < 2; np++) {
                int r = wn * 32 + np * 16 + (lane & 7) + ((lane >> 4) & 1) * 8;
                int u = 2 * ks + ((lane >> 3) & 1);
                uint32_t b_addr = st + 2 * PLANE_B + swz(r, u);
                uint32_t t[4];
                ldsm4(t, b_addr);
                bhf[np*2][0] = t[0]; bhf[np*2][1] = t[1];
                bhf[np*2+1][0] = t[2]; bhf[np*2+1][1] = t[3];
                ldsm4(t, b_addr + PLANE_B);
                blf[np*2][0] = t[0]; blf[np*2][1] = t[1];
                blf[np*2+1][0] = t[2]; blf[np*2+1][1] = t[3];
            }
#pragma unroll
            for (int mt = 0; mt < 4; mt++)
#pragma unroll
                for (int nt = 0; nt < 4; nt++) mma16816(acc[mt][nt], ahf[mt], bhf[nt]);
#pragma unroll
            for (int mt = 0; mt < 4; mt++)
#pragma unroll
                for (int nt = 0; nt < 4; nt++) mma16816(acc[mt][nt], ahf[mt], blf[nt]);
#pragma unroll
            for (int mt = 0; mt < 4; mt++)
#pragma unroll
                for (int nt = 0; nt < 4; nt++) mma16816(acc[mt][nt], alf[mt], bhf[nt]);
        }
    }

#pragma unroll
    for (int mt = 0; mt < 4; mt++)
#pragma unroll
        for (int nt = 0; nt < 4; nt++) {
            float* c = acc[mt][nt];
            int row = bm * 128 + wm * 64 + mt * 16 + (lane >> 2);
            int col = bn * 128 + wn * 32 + nt * 8 + 2 * (lane & 3);
            *(float2*)(out + (size_t)row * ldc + col) = make_float2(c[0], c[1]);
            *(float2*)(out + (size_t)(row + 8) * ldc + col) = make_float2(c[2], c[3]);
        }
}

// ---------------------------------------------------------------------------
// QKNorm + partial 2D RoPE + split to attn operand planes.
// ---------------------------------------------------------------------------
__global__ __launch_bounds__(256)
void norm_rope_split(const float* __restrict__ qw, const float* __restrict__ kw) {
    int vec = blockIdx.x * 8 + (threadIdx.x >> 5);
    int lane = threadIdx.x & 31;
    int hh = vec % 24;
    int row = vec / 24;
    int bt = row / SEQ, s = row - bt * SEQ;

    const float* p;
    __nv_bfloat16 *hip, *lop;
    if (hh < NH) {
        p = g_qkv + (size_t)row * QKV_N + hh * HD;
        size_t o = ((size_t)(bt * NH + hh) * SEQ + s) * HD;
        hip = g_qphi + o; lop = g_qplo + o;
    } else if (hh < NH + NKV) {
        p = g_qkv + (size_t)row * QKV_N + GDIM + (hh - NH) * HD;
        size_t o = ((size_t)(bt * NKV + (hh - NH)) * SEQ + s) * HD;
        hip = g_kphi + o; lop = g_kplo + o;
    } else {
        p = g_qkv + (size_t)row * QKV_N + GDIM + NKV * HD + (hh - NH - NKV) * HD;
        size_t o = ((size_t)(bt * NKV + (hh - NH - NKV)) * SEQ + s) * HD;
        hip = g_vphi + o; lop = g_vplo + o;
    }
    float v0 = p[lane], v1 = p[lane + 32];

    if (hh < NH + NKV) {
        float sq = v0 * v0 + v1 * v1;
#pragma unroll
        for (int o = 16; o; o >>= 1) sq += __shfl_xor_sync(0xffffffffu, sq, o);
        float scl = rsqrtf(sq * (1.0f / HD) + 1e-6f);
        const float* wv = (hh < NH) ? qw : kw;
        v0 *= scl * wv[lane];
        v1 *= scl * wv[lane + 32];
        if (s < NZ) {
            int j = lane & 15;
            float pos = (lane < 16) ? (float)(s >> 4) : (float)(s & 15);
            float invf = __expf(-(float)j * 0.57564627324851142f);
            float c, sn;
            sincosf(pos * invf, &sn, &c);
            float o0 = v0 * c - v1 * sn;
            float o1 = v1 * c + v0 * sn;
            v0 = o0; v1 = o1;
        }
    }
    __nv_bfloat16 h0 = __float2bfloat16(v0);
    __nv_bfloat16 h1 = __float2bfloat16(v1);
    hip[lane] = h0;
    hip[lane + 32] = h1;
    lop[lane] = __float2bfloat16(v0 - __bfloat162float(h0));
    lop[lane + 32] = __float2bfloat16(v1 - __bfloat162float(h1));
}

// ---------------------------------------------------------------------------
// Flash-style mma attention; chunked K/V (144+128 keys) -> 110.6KB smem, 2 CTA/SM
// ---------------------------------------------------------------------------
__device__ __forceinline__ void attn_step(uint32_t sb, int lr0, bool last,
        const uint32_t qh[4][4], const uint32_t ql[4][4],
        float oacc[8][4], float& lsum0, float& lsum1,
        int krow, int ku, int vrow, int vu) {
    float sA0[4] = {0,0,0,0}, sA1[4] = {0,0,0,0};
    float sB0[4] = {0,0,0,0}, sB1[4] = {0,0,0,0};
    float sC0[4] = {0,0,0,0}, sC1[4] = {0,0,0,0};
#pragma unroll
    for (int kc = 0; kc < 4; kc++) {
        uint32_t off = (uint32_t)((lr0 + krow) * LDP + (2 * kc + ku) * 16);
        uint32_t bh[4], bl[4];
        ldsm4(bh, sb + SM_KHI + off);
        ldsm4(bl, sb + SM_KLO + off);
        mma16816(sA0, qh[kc], bh);
        mma16816(sA1, qh[kc], bh + 2);
        mma16816(sB0, qh[kc], bl);
        mma16816(sB1, qh[kc], bl + 2);
        mma16816(sC0, ql[kc], bh);
        mma16816(sC1, ql[kc], bh + 2);
    }
    float pf[2][4];
#pragma unroll
    for (int e = 0; e < 4; e++) {
        float s = (sA0[e] + sB0[e] + sC0[e]) * 0.125f;
        float t = __expf(-0.04f * fabsf(s));
        float th = __fdividef(1.f - t, 1.f + t);
        pf[0][e] = __expf((s >= 0.f) ? 50.f * th : -50.f * th);
        float s1 = (sA1[e] + sB1[e] + sC1[e]) * 0.125f;
        float t1 = __expf(-0.04f * fabsf(s1));
        float th1 = __fdividef(1.f - t1, 1.f + t1);
        pf[1][e] = __expf((s1 >= 0.f) ? 50.f * th1 : -50.f * th1);
    }
    if (last) { pf[1][0] = pf[1][1] = pf[1][2] = pf[1][3] = 0.f; }
    lsum0 += pf[0][0] + pf[0][1] + pf[1][0] + pf[1][1];
    lsum1 += pf[0][2] + pf[0][3] + pf[1][2] + pf[1][3];

    uint32_t ph[4], pl[4];
    split2(pf[0][0], pf[0][1], ph[0], pl[0]);
    split2(pf[0][2], pf[0][3], ph[1], pl[1]);
    split2(pf[1][0], pf[1][1], ph[2], pl[2]);
    split2(pf[1][2], pf[1][3], ph[3], pl[3]);

    uint32_t vh[4][4], vl[4][4];
#pragma unroll
    for (int db = 0; db < 4; db++) {
        uint32_t off = (uint32_t)((lr0 + vrow) * LDP + (2 * db + vu) * 16);
        ldsm4t(vh[db], sb + SM_VHI + off);
        ldsm4t(vl[db], sb + SM_VLO + off);
    }
#pragma unroll
    for (int db = 0; db < 4; db++) {
        mma16816(oacc[2*db],   ph, vh[db]);
        mma16816(oacc[2*db+1], ph, vh[db] + 2);
    }
#pragma unroll
    for (int db = 0; db < 4; db++) {
        mma16816(oacc[2*db],   ph, vl[db]);
        mma16816(oacc[2*db+1], ph, vl[db] + 2);
    }
#pragma unroll
    for (int db = 0; db < 4; db++) {
        mma16816(oacc[2*db],   pl, vh[db]);
        mma16816(oacc[2*db+1], pl, vh[db] + 2);
    }
}

__global__ __launch_bounds__(192, 2) void attn_mma() {
    extern __shared__ __align__(1024) char smem[];
    const int tid = threadIdx.x;
    const int mt = blockIdx.x, h = blockIdx.y, bt = blockIdx.z;
    const int m0 = (mt == 0) ? 0 : (mt == 1 ? 96 : 168);
    const int kvh = h >> 2;
    const uint32_t sb = smem_u32(smem);

    size_t kvo = (size_t)(bt * NKV + kvh) * SEQ * HD;
    const __nv_bfloat16* kh_g = g_kphi + kvo;
    const __nv_bfloat16* kl_g = g_kplo + kvo;
    const __nv_bfloat16* vh_g = g_vphi + kvo;
    const __nv_bfloat16* vl_g = g_vplo + kvo;

    // ---- phase 0: async load Q + chunk A (keys 0..143) ----
    for (int idx = tid; idx < CH_ROWS * 8; idx += 192) {
        int r = idx >> 3, u = idx & 7;
        uint32_t doff = (uint32_t)(r * LDP + u * 16);
        int soff = r * HD + u * 8;
        cp16(sb + SM_KHI + doff, kh_g + soff);
        cp16(sb + SM_KLO + doff, kl_g + soff);
        cp16(sb + SM_VHI + doff, vh_g + soff);
        cp16(sb + SM_VLO + doff, vl_g + soff);
    }
    {
        size_t qo = ((size_t)(bt * NH + h) * SEQ + m0) * HD;
        const __nv_bfloat16* qh_g = g_qphi + qo;
        const __nv_bfloat16* ql_g = g_qplo + qo;
        for (int idx = tid; idx < 96 * 8; idx += 192) {
            int r = idx >> 3, u = idx & 7;
            uint32_t doff = (uint32_t)(r * LDP + u * 16);
            int soff = r * HD + u * 8;
            cp16(sb + SM_QHI + doff, qh_g + soff);
            cp16(sb + SM_QLO + doff, ql_g + soff);
        }
    }
    CP_COMMIT();
    CP_WAIT(0);
    __syncthreads();

    const int w = tid >> 5, lane = tid & 31;

    uint32_t qh[4][4], ql[4][4];
    {
        int r = w * 16 + (lane & 15);
        int uo = lane >> 4;
#pragma unroll
        for (int kc = 0; kc < 4; kc++) {
            uint32_t off = (uint32_t)(r * LDP + (2 * kc + uo) * 16);
            ldsm4(qh[kc], sb + SM_QHI + off);
            ldsm4(ql[kc], sb + SM_QLO + off);
        }
    }

    float oacc[8][4];
#pragma unroll
    for (int i = 0; i < 8; i++)
#pragma unroll
        for (int j = 0; j < 4; j++) oacc[i][j] = 0.f;
    float lsum0 = 0.f, lsum1 = 0.f;

    const int krow = (lane & 7) + ((lane >> 4) & 1) * 8;
    const int ku = (lane >> 3) & 1;
    const int vrow = (lane & 7) + ((lane >> 3) & 1) * 8;
    const int vu = (lane >> 4) & 1;

    // ---- chunk A: np 0..8 (keys 0..143) ----
    for (int np = 0; np < 9; np++)
        attn_step(sb, np * 16, false, qh, ql, oacc, lsum0, lsum1, krow, ku, vrow, vu);

    __syncthreads();   // all warps done reading chunk A

    // ---- phase 1: load chunk B (keys 144..263 -> local rows 0..119; pad 120..127) ----
    for (int idx = tid; idx < 120 * 8; idx += 192) {
        int r = idx >> 3, u = idx & 7;
        uint32_t doff = (uint32_t)(r * LDP + u * 16);
        int soff = (144 + r) * HD + u * 8;
        cp16(sb + SM_KHI + doff, kh_g + soff);
        cp16(sb + SM_KLO + doff, kl_g + soff);
        cp16(sb + SM_VHI + doff, vh_g + soff);
        cp16(sb + SM_VLO + doff, vl_g + soff);
    }
    for (int idx = tid; idx < 8 * 32; idx += 192) {
        int off = (120 + (idx >> 5)) * LDP + (idx & 31) * 4;
        *(uint32_t*)(smem + SM_KHI + off) = 0;
        *(uint32_t*)(smem + SM_KLO + off) = 0;
        *(uint32_t*)(smem + SM_VHI + off) = 0;
        *(uint32_t*)(smem + SM_VLO + off) = 0;
    }
    CP_COMMIT();
    CP_WAIT(0);
    __syncthreads();

    // ---- chunk B: np 0..7 (keys 144..271, last n8 masked) ----
    for (int np = 0; np < 8; np++)
        attn_step(sb, np * 16, np == 7, qh, ql, oacc, lsum0, lsum1, krow, ku, vrow, vu);

    // ---- normalize + write split bf16 output ----
    lsum0 += __shfl_xor_sync(0xffffffffu, lsum0, 1);
    lsum0 += __shfl_xor_sync(0xffffffffu, lsum0, 2);
    lsum1 += __shfl_xor_sync(0xffffffffu, lsum1, 1);
    lsum1 += __shfl_xor_sync(0xffffffffu, lsum1, 2);
    float inv0 = __fdividef(1.f, lsum0);
    float inv1 = __fdividef(1.f, lsum1);

    size_t row0 = (size_t)bt * SEQ + m0 + w * 16 + (lane >> 2);
    int colb = h * HD + 2 * (lane & 3);
#pragma unroll
    for (int nb = 0; nb < 8; nb++) {
        int col = colb + nb * 8;
        uint32_t hv, lv;
        split2(oacc[nb][0] * inv0, oacc[nb][1] * inv0, hv, lv);
        *(uint32_t*)(g_ahi + row0 * GDIM + col) = hv;
        *(uint32_t*)(g_alo + row0 * GDIM + col) = lv;
        split2(oacc[nb][2] * inv1, oacc[nb][3] * inv1, hv, lv);
        *(uint32_t*)(g_ahi + (row0 + 8) * GDIM + col) = hv;
        *(uint32_t*)(g_alo + (row0 + 8) * GDIM + col) = lv;
    }
}

// ---------------------------------------------------------------------------
extern "C" void kernel_launch(void* const* d_in, const int* in_sizes, int n_in,
                              void* d_out, int out_size) {
    const float* x   = (const float*)d_in[0];
    const float* wq  = (const float*)d_in[1];
    const float* wk  = (const float*)d_in[2];
    const float* wv  = (const float*)d_in[3];
    const float* wo  = (const float*)d_in[4];
    const float* qnw = (const float*)d_in[5];
    const float* knw = (const float*)d_in[6];
    float* out = (float*)d_out;

    __nv_bfloat16 *xhi, *xlo, *whi, *wlo, *wohi, *wolo, *ahi, *alo;
    float* qkv;
    cudaGetSymbolAddress((void**)&xhi, g_xhi);
    cudaGetSymbolAddress((void**)&xlo, g_xlo);
    cudaGetSymbolAddress((void**)&whi, g_whi);
    cudaGetSymbolAddress((void**)&wlo, g_wlo);
    cudaGetSymbolAddress((void**)&wohi, g_wohi);
    cudaGetSymbolAddress((void**)&wolo, g_wolo);
    cudaGetSymbolAddress((void**)&ahi, g_ahi);
    cudaGetSymbolAddress((void**)&alo, g_alo);
    cudaGetSymbolAddress((void**)&qkv, g_qkv);

    cudaFuncSetAttribute((const void*)gemm_mma,
                         cudaFuncAttributeMaxDynamicSharedMemorySize, GEMM_SMEM);
    cudaFuncSetAttribute((const void*)attn_mma,
                         cudaFuncAttributeMaxDynamicSharedMemorySize, ATT_SMEM);

    // 1) split operands into bf16 hi/lo planes
    split_rm<<<4224, 256>>>(x, xhi, xlo, MROWS * GDIM / 8);
    split_w_qkv<<<768, 256>>>(wq, wk, wv);
    split_rm<<<512, 256>>>(wo, wohi, wolo, GDIM * GDIM / 8);

    // 2) QKV projection (128x128 tiles, 2 CTA/SM)
    gemm_mma<<<dim3(QKV_N / 128, MROWS / 128), 256, GEMM_SMEM>>>(
        xhi, xlo, whi, wlo, qkv, QKV_N);

    // 3) QKNorm + 2D RoPE + split into attention planes
    norm_rope_split<<<MROWS * 3, 256>>>(qnw, knw);

    // 4) tensor-core attention (chunked KV, 2 CTA/SM)
    attn_mma<<<dim3(3, NH, BTN), 192, ATT_SMEM>>>();

    // 5) output projection
    gemm_mma<<<dim3(GDIM / 128, MROWS / 128), 256, GEMM_SMEM>>>(
        ahi, alo, wohi, wolo, out, GDIM);
}

// round 9
// speedup vs baseline: 1.7682x; 1.2547x over previous
#include <cuda_runtime.h>
#include <cuda_bf16.h>
#include <cuda_fp16.h>
#include <stdint.h>
#include <math.h>

// Problem constants
#define BTN   64
#define SEQ   264
#define MROWS (BTN*SEQ)      // 16896
#define GDIM  1024
#define NH    16
#define NKV   4
#define HD    64
#define QKV_N 1536
#define NZ    256

// GEMM tiling: block 128x128, BK=32, 8 warps, 3-stage, 2 CTA/SM, fp16 2-term
#define BK    32
#define KT    (GDIM/BK)      // 32
#define PLANE_B 8192         // 128x32 fp16
#define STAGE_B (3*PLANE_B)  // A + Bh + Bl = 24576
#define GEMM_SMEM (3*STAGE_B)   // 73728
#define WSCALE 64.0f
#define WINV   0.015625f

// Attention smem: chunked K/V (144-key buffer) + Q planes; 2 CTA/SM
#define LDP   144
#define CH_ROWS 144
#define SM_KHI 0
#define SM_KLO (CH_ROWS*LDP)
#define SM_VHI (2*CH_ROWS*LDP)
#define SM_VLO (3*CH_ROWS*LDP)
#define SM_QHI (4*CH_ROWS*LDP)
#define SM_QLO (SM_QHI + 96*LDP)
#define ATT_SMEM (SM_QLO + 96*LDP) // 110592

// ---------------------------------------------------------------------------
// device scratch
// ---------------------------------------------------------------------------
__device__ __align__(16) __half g_x[(size_t)MROWS * GDIM];       // A of QKV gemm
__device__ __align__(16) __half g_whi[(size_t)QKV_N * GDIM];     // B of QKV (x64)
__device__ __align__(16) __half g_wlo[(size_t)QKV_N * GDIM];
__device__ __align__(16) __half g_wohi[(size_t)GDIM * GDIM];     // B of O (x64)
__device__ __align__(16) __half g_wolo[(size_t)GDIM * GDIM];
__device__ __align__(16) __half g_a[(size_t)MROWS * GDIM];       // A of O gemm
__device__ __align__(16) float  g_qkv[(size_t)MROWS * QKV_N];
// attention operand planes (bf16 hi/lo)
__device__ __align__(16) __nv_bfloat16 g_kphi[(size_t)BTN * NKV * SEQ * HD];
__device__ __align__(16) __nv_bfloat16 g_kplo[(size_t)BTN * NKV * SEQ * HD];
__device__ __align__(16) __nv_bfloat16 g_vphi[(size_t)BTN * NKV * SEQ * HD];
__device__ __align__(16) __nv_bfloat16 g_vplo[(size_t)BTN * NKV * SEQ * HD];
__device__ __align__(16) __nv_bfloat16 g_qphi[(size_t)BTN * NH * SEQ * HD];
__device__ __align__(16) __nv_bfloat16 g_qplo[(size_t)BTN * NH * SEQ * HD];

// ---------------------------------------------------------------------------
// helpers
// ---------------------------------------------------------------------------
__device__ __forceinline__ uint32_t smem_u32(const void* p) {
    uint32_t a;
    asm("{ .reg .u64 t; cvta.to.shared.u64 t, %1; cvt.u32.u64 %0, t; }"
        : "=r"(a) : "l"(p));
    return a;
}
__device__ __forceinline__ void cp16(uint32_t dst, const void* src) {
    asm volatile("cp.async.cg.shared.global [%0], [%1], 16;" :: "r"(dst), "l"(src));
}
#define CP_COMMIT() asm volatile("cp.async.commit_group;" ::: "memory")
#define CP_WAIT(n)  asm volatile("cp.async.wait_group %0;" :: "n"(n) : "memory")

__device__ __forceinline__ void ldsm4(uint32_t* r, uint32_t addr) {
    asm volatile("ldmatrix.sync.aligned.m8n8.x4.shared.b16 {%0,%1,%2,%3}, [%4];"
                 : "=r"(r[0]), "=r"(r[1]), "=r"(r[2]), "=r"(r[3]) : "r"(addr));
}
__device__ __forceinline__ void ldsm4t(uint32_t* r, uint32_t addr) {
    asm volatile("ldmatrix.sync.aligned.m8n8.x4.trans.shared.b16 {%0,%1,%2,%3}, [%4];"
                 : "=r"(r[0]), "=r"(r[1]), "=r"(r[2]), "=r"(r[3]) : "r"(addr));
}
// bf16 mma (attention)
__device__ __forceinline__ void mma16816(float* c, const uint32_t* a, const uint32_t* b) {
    asm volatile(
        "mma.sync.aligned.m16n8k16.row.col.f32.bf16.bf16.f32 "
        "{%0,%1,%2,%3}, {%4,%5,%6,%7}, {%8,%9}, {%0,%1,%2,%3};"
        : "+f"(c[0]), "+f"(c[1]), "+f"(c[2]), "+f"(c[3])
        : "r"(a[0]), "r"(a[1]), "r"(a[2]), "r"(a[3]), "r"(b[0]), "r"(b[1]));
}
// fp16 mma (GEMMs)
__device__ __forceinline__ void mma16816h(float* c, const uint32_t* a, const uint32_t* b) {
    asm volatile(
        "mma.sync.aligned.m16n8k16.row.col.f32.f16.f16.f32 "
        "{%0,%1,%2,%3}, {%4,%5,%6,%7}, {%8,%9}, {%0,%1,%2,%3};"
        : "+f"(c[0]), "+f"(c[1]), "+f"(c[2]), "+f"(c[3])
        : "r"(a[0]), "r"(a[1]), "r"(a[2]), "r"(a[3]), "r"(b[0]), "r"(b[1]));
}

__device__ __forceinline__ uint32_t swz(int r, int u) {
    return (uint32_t)(r * 64 + ((u ^ ((r >> 1) & 3)) << 4));
}

// split two floats -> hi bf16x2 + lo bf16x2 (attention)
__device__ __forceinline__ void split2(float a, float b, uint32_t& h, uint32_t& l) {
    __nv_bfloat16 ha = __float2bfloat16(a);
    __nv_bfloat16 hb = __float2bfloat16(b);
    float ra = a - __bfloat162float(ha);
    float rb = b - __bfloat162float(hb);
    h = (uint32_t)__bfloat16_as_ushort(ha) | ((uint32_t)__bfloat16_as_ushort(hb) << 16);
    l = (uint32_t)__bfloat16_as_ushort(__float2bfloat16(ra)) |
        ((uint32_t)__bfloat16_as_ushort(__float2bfloat16(rb)) << 16);
}

// ---------------------------------------------------------------------------
// conversion kernels
// ---------------------------------------------------------------------------
// fp32 -> fp16 single plane
__global__ void conv_h(const float* __restrict__ src, __half* __restrict__ dst, int nunits) {
    for (int i = blockIdx.x * blockDim.x + threadIdx.x; i < nunits;
         i += gridDim.x * blockDim.x) {
        const float4 f0 = *(const float4*)(src + (size_t)i * 8);
        const float4 f1 = *(const float4*)(src + (size_t)i * 8 + 4);
        __half2 h[4];
        h[0] = __floats2half2_rn(f0.x, f0.y);
        h[1] = __floats2half2_rn(f0.z, f0.w);
        h[2] = __floats2half2_rn(f1.x, f1.y);
        h[3] = __floats2half2_rn(f1.z, f1.w);
        ((uint4*)dst)[i] = *(uint4*)h;
    }
}

// fp32 -> (hi, lo) fp16 planes with x64 scaling
__device__ __forceinline__ void split2h64(float a, float b, uint32_t& h, uint32_t& l) {
    a *= WSCALE; b *= WSCALE;
    __half ha = __float2half_rn(a);
    __half hb = __float2half_rn(b);
    float ra = a - __half2float(ha);
    float rb = b - __half2float(hb);
    h = (uint32_t)__half_as_ushort(ha) | ((uint32_t)__half_as_ushort(hb) << 16);
    l = (uint32_t)__half_as_ushort(__float2half_rn(ra)) |
        ((uint32_t)__half_as_ushort(__float2half_rn(rb)) << 16);
}

__global__ void split_h64(const float* __restrict__ src, __half* __restrict__ hi,
                          __half* __restrict__ lo, int nunits) {
    for (int i = blockIdx.x * blockDim.x + threadIdx.x; i < nunits;
         i += gridDim.x * blockDim.x) {
        const float4 f0 = *(const float4*)(src + (size_t)i * 8);
        const float4 f1 = *(const float4*)(src + (size_t)i * 8 + 4);
        uint4 hv, lv;
        split2h64(f0.x, f0.y, hv.x, lv.x);
        split2h64(f0.z, f0.w, hv.y, lv.y);
        split2h64(f1.x, f1.y, hv.z, lv.z);
        split2h64(f1.z, f1.w, hv.w, lv.w);
        ((uint4*)hi)[i] = hv;
        ((uint4*)lo)[i] = lv;
    }
}

__global__ void split_w_qkv(const float* __restrict__ wq, const float* __restrict__ wk,
                            const float* __restrict__ wv) {
    int nunits = QKV_N * (GDIM / 8);
    for (int i = blockIdx.x * blockDim.x + threadIdx.x; i < nunits;
         i += gridDim.x * blockDim.x) {
        int row = i >> 7, ur = i & 127;
        const float* srow;
        if (row < NH * HD)                srow = wq + (size_t)row * GDIM;
        else if (row < NH*HD + NKV*HD)    srow = wk + (size_t)(row - NH*HD) * GDIM;
        else                              srow = wv + (size_t)(row - NH*HD - NKV*HD) * GDIM;
        const float4 f0 = *(const float4*)(srow + ur * 8);
        const float4 f1 = *(const float4*)(srow + ur * 8 + 4);
        uint4 hv, lv;
        split2h64(f0.x, f0.y, hv.x, lv.x);
        split2h64(f0.z, f0.w, hv.y, lv.y);
        split2h64(f1.x, f1.y, hv.z, lv.z);
        split2h64(f1.z, f1.w, hv.w, lv.w);
        ((uint4*)g_whi)[i] = hv;
        ((uint4*)g_wlo)[i] = lv;
    }
}

// ---------------------------------------------------------------------------
// fp16 2-term GEMM: out[m][n] = (1/64) * sum_k A[m][k]*(Bh+Bl)[n][k]
// 128x128 tile, BK=32, 8 warps, 3-stage cp.async, 2 CTA/SM
// ---------------------------------------------------------------------------
__device__ __forceinline__ void load_stage(uint32_t sb, int stage,
        const __half* __restrict__ A, const __half* __restrict__ Bh,
        const __half* __restrict__ Bl, int bm, int bn, int kc, int tid) {
    uint32_t st = sb + stage * STAGE_B;
#pragma unroll
    for (int i = 0; i < 6; i++) {
        int v = i * 256 + tid;
        int op = v >> 9;          // 0:A 1:Bh 2:Bl
        int w = v & 511;
        int r = w >> 2, u = w & 3;
        const __half* base = (op == 0) ? A : (op == 1) ? Bh : Bl;
        int grow = ((op == 0) ? bm : bn) * 128 + r;
        const __half* g = base + (size_t)grow * GDIM + kc * BK + u * 8;
        cp16(st + op * PLANE_B + swz(r, u), g);
    }
}

__global__ __launch_bounds__(256, 2)
void gemm_mma(const __half* __restrict__ A, const __half* __restrict__ Bh,
              const __half* __restrict__ Bl, float* __restrict__ out, int ldc) {
    extern __shared__ __align__(1024) char smem[];
    uint32_t sb = smem_u32(smem);
    int tid = threadIdx.x, wid = tid >> 5, lane = tid & 31;
    int bm = blockIdx.y, bn = blockIdx.x;
    int wm = wid >> 2;
    int wn = wid & 3;

    float acc[4][4][4];
#pragma unroll
    for (int a = 0; a < 4; a++)
#pragma unroll
        for (int b = 0; b < 4; b++)
#pragma unroll
            for (int c = 0; c < 4; c++) acc[a][b][c] = 0.f;

    load_stage(sb, 0, A, Bh, Bl, bm, bn, 0, tid); CP_COMMIT();
    load_stage(sb, 1, A, Bh, Bl, bm, bn, 1, tid); CP_COMMIT();

    for (int kc = 0; kc < KT; kc++) {
        CP_WAIT(1);
        __syncthreads();
        if (kc + 2 < KT)
            load_stage(sb, (kc + 2) % 3, A, Bh, Bl, bm, bn, kc + 2, tid);
        CP_COMMIT();

        uint32_t st = sb + (kc % 3) * STAGE_B;
#pragma unroll
        for (int ks = 0; ks < 2; ks++) {
            uint32_t af[4][4], bhf[4][2], blf[4][2];
#pragma unroll
            for (int mt = 0; mt < 4; mt++) {
                int r = wm * 64 + mt * 16 + (lane & 15);
                int u = 2 * ks + (lane >> 4);
                ldsm4(af[mt], st + swz(r, u));
            }
#pragma unroll
            for (int np = 0; np < 2; np++) {
                int r = wn * 32 + np * 16 + (lane & 7) + ((lane >> 4) & 1) * 8;
                int u = 2 * ks + ((lane >> 3) & 1);
                uint32_t ba = st + PLANE_B + swz(r, u);
                uint32_t t[4];
                ldsm4(t, ba);
                bhf[np*2][0] = t[0]; bhf[np*2][1] = t[1];
                bhf[np*2+1][0] = t[2]; bhf[np*2+1][1] = t[3];
                ldsm4(t, ba + PLANE_B);
                blf[np*2][0] = t[0]; blf[np*2][1] = t[1];
                blf[np*2+1][0] = t[2]; blf[np*2+1][1] = t[3];
            }
            // two independent passes over 16 accs
#pragma unroll
            for (int mt = 0; mt < 4; mt++)
#pragma unroll
                for (int nt = 0; nt < 4; nt++) mma16816h(acc[mt][nt], af[mt], bhf[nt]);
#pragma unroll
            for (int mt = 0; mt < 4; mt++)
#pragma unroll
                for (int nt = 0; nt < 4; nt++) mma16816h(acc[mt][nt], af[mt], blf[nt]);
        }
    }

#pragma unroll
    for (int mt = 0; mt < 4; mt++)
#pragma unroll
        for (int nt = 0; nt < 4; nt++) {
            float* c = acc[mt][nt];
            int row = bm * 128 + wm * 64 + mt * 16 + (lane >> 2);
            int col = bn * 128 + wn * 32 + nt * 8 + 2 * (lane & 3);
            *(float2*)(out + (size_t)row * ldc + col) =
                make_float2(c[0] * WINV, c[1] * WINV);
            *(float2*)(out + (size_t)(row + 8) * ldc + col) =
                make_float2(c[2] * WINV, c[3] * WINV);
        }
}

// ---------------------------------------------------------------------------
// QKNorm + partial 2D RoPE + split to attn operand planes (bf16, unchanged)
// ---------------------------------------------------------------------------
__global__ __launch_bounds__(256)
void norm_rope_split(const float* __restrict__ qw, const float* __restrict__ kw) {
    int vec = blockIdx.x * 8 + (threadIdx.x >> 5);
    int lane = threadIdx.x & 31;
    int hh = vec % 24;
    int row = vec / 24;
    int bt = row / SEQ, s = row - bt * SEQ;

    const float* p;
    __nv_bfloat16 *hip, *lop;
    if (hh < NH) {
        p = g_qkv + (size_t)row * QKV_N + hh * HD;
        size_t o = ((size_t)(bt * NH + hh) * SEQ + s) * HD;
        hip = g_qphi + o; lop = g_qplo + o;
    } else if (hh < NH + NKV) {
        p = g_qkv + (size_t)row * QKV_N + GDIM + (hh - NH) * HD;
        size_t o = ((size_t)(bt * NKV + (hh - NH)) * SEQ + s) * HD;
        hip = g_kphi + o; lop = g_kplo + o;
    } else {
        p = g_qkv + (size_t)row * QKV_N + GDIM + NKV * HD + (hh - NH - NKV) * HD;
        size_t o = ((size_t)(bt * NKV + (hh - NH - NKV)) * SEQ + s) * HD;
        hip = g_vphi + o; lop = g_vplo + o;
    }
    float v0 = p[lane], v1 = p[lane + 32];

    if (hh < NH + NKV) {
        float sq = v0 * v0 + v1 * v1;
#pragma unroll
        for (int o = 16; o; o >>= 1) sq += __shfl_xor_sync(0xffffffffu, sq, o);
        float scl = rsqrtf(sq * (1.0f / HD) + 1e-6f);
        const float* wv = (hh < NH) ? qw : kw;
        v0 *= scl * wv[lane];
        v1 *= scl * wv[lane + 32];
        if (s < NZ) {
            int j = lane & 15;
            float pos = (lane < 16) ? (float)(s >> 4) : (float)(s & 15);
            float invf = __expf(-(float)j * 0.57564627324851142f);
            float c, sn;
            sincosf(pos * invf, &sn, &c);
            float o0 = v0 * c - v1 * sn;
            float o1 = v1 * c + v0 * sn;
            v0 = o0; v1 = o1;
        }
    }
    __nv_bfloat16 h0 = __float2bfloat16(v0);
    __nv_bfloat16 h1 = __float2bfloat16(v1);
    hip[lane] = h0;
    hip[lane + 32] = h1;
    lop[lane] = __float2bfloat16(v0 - __bfloat162float(h0));
    lop[lane + 32] = __float2bfloat16(v1 - __bfloat162float(h1));
}

// ---------------------------------------------------------------------------
// Flash-style mma attention (bf16x3, chunked KV, 2 CTA/SM) — unchanged math;
// epilogue writes single fp16 plane for the O gemm.
// ---------------------------------------------------------------------------
__device__ __forceinline__ void attn_step(uint32_t sb, int lr0, bool last,
        const uint32_t qh[4][4], const uint32_t ql[4][4],
        float oacc[8][4], float& lsum0, float& lsum1,
        int krow, int ku, int vrow, int vu) {
    float sA0[4] = {0,0,0,0}, sA1[4] = {0,0,0,0};
    float sB0[4] = {0,0,0,0}, sB1[4] = {0,0,0,0};
    float sC0[4] = {0,0,0,0}, sC1[4] = {0,0,0,0};
#pragma unroll
    for (int kc = 0; kc < 4; kc++) {
        uint32_t off = (uint32_t)((lr0 + krow) * LDP + (2 * kc + ku) * 16);
        uint32_t bh[4], bl[4];
        ldsm4(bh, sb + SM_KHI + off);
        ldsm4(bl, sb + SM_KLO + off);
        mma16816(sA0, qh[kc], bh);
        mma16816(sA1, qh[kc], bh + 2);
        mma16816(sB0, qh[kc], bl);
        mma16816(sB1, qh[kc], bl + 2);
        mma16816(sC0, ql[kc], bh);
        mma16816(sC1, ql[kc], bh + 2);
    }
    float pf[2][4];
#pragma unroll
    for (int e = 0; e < 4; e++) {
        float s = (sA0[e] + sB0[e] + sC0[e]) * 0.125f;
        float t = __expf(-0.04f * fabsf(s));
        float th = __fdividef(1.f - t, 1.f + t);
        pf[0][e] = __expf((s >= 0.f) ? 50.f * th : -50.f * th);
        float s1 = (sA1[e] + sB1[e] + sC1[e]) * 0.125f;
        float t1 = __expf(-0.04f * fabsf(s1));
        float th1 = __fdividef(1.f - t1, 1.f + t1);
        pf[1][e] = __expf((s1 >= 0.f) ? 50.f * th1 : -50.f * th1);
    }
    if (last) { pf[1][0] = pf[1][1] = pf[1][2] = pf[1][3] = 0.f; }
    lsum0 += pf[0][0] + pf[0][1] + pf[1][0] + pf[1][1];
    lsum1 += pf[0][2] + pf[0][3] + pf[1][2] + pf[1][3];

    uint32_t ph[4], pl[4];
    split2(pf[0][0], pf[0][1], ph[0], pl[0]);
    split2(pf[0][2], pf[0][3], ph[1], pl[1]);
    split2(pf[1][0], pf[1][1], ph[2], pl[2]);
    split2(pf[1][2], pf[1][3], ph[3], pl[3]);

    uint32_t vh[4][4], vl[4][4];
#pragma unroll
    for (int db = 0; db < 4; db++) {
        uint32_t off = (uint32_t)((lr0 + vrow) * LDP + (2 * db + vu) * 16);
        ldsm4t(vh[db], sb + SM_VHI + off);
        ldsm4t(vl[db], sb + SM_VLO + off);
    }
#pragma unroll
    for (int db = 0; db < 4; db++) {
        mma16816(oacc[2*db],   ph, vh[db]);
        mma16816(oacc[2*db+1], ph, vh[db] + 2);
    }
#pragma unroll
    for (int db = 0; db < 4; db++) {
        mma16816(oacc[2*db],   ph, vl[db]);
        mma16816(oacc[2*db+1], ph, vl[db] + 2);
    }
#pragma unroll
    for (int db = 0; db < 4; db++) {
        mma16816(oacc[2*db],   pl, vh[db]);
        mma16816(oacc[2*db+1], pl, vh[db] + 2);
    }
}

__global__ __launch_bounds__(192, 2) void attn_mma() {
    extern __shared__ __align__(1024) char smem[];
    const int tid = threadIdx.x;
    const int mt = blockIdx.x, h = blockIdx.y, bt = blockIdx.z;
    const int m0 = (mt == 0) ? 0 : (mt == 1 ? 96 : 168);
    const int kvh = h >> 2;
    const uint32_t sb = smem_u32(smem);

    size_t kvo = (size_t)(bt * NKV + kvh) * SEQ * HD;
    const __nv_bfloat16* kh_g = g_kphi + kvo;
    const __nv_bfloat16* kl_g = g_kplo + kvo;
    const __nv_bfloat16* vh_g = g_vphi + kvo;
    const __nv_bfloat16* vl_g = g_vplo + kvo;

    // ---- phase 0: async load Q + chunk A (keys 0..143) ----
    for (int idx = tid; idx < CH_ROWS * 8; idx += 192) {
        int r = idx >> 3, u = idx & 7;
        uint32_t doff = (uint32_t)(r * LDP + u * 16);
        int soff = r * HD + u * 8;
        cp16(sb + SM_KHI + doff, kh_g + soff);
        cp16(sb + SM_KLO + doff, kl_g + soff);
        cp16(sb + SM_VHI + doff, vh_g + soff);
        cp16(sb + SM_VLO + doff, vl_g + soff);
    }
    {
        size_t qo = ((size_t)(bt * NH + h) * SEQ + m0) * HD;
        const __nv_bfloat16* qh_g = g_qphi + qo;
        const __nv_bfloat16* ql_g = g_qplo + qo;
        for (int idx = tid; idx < 96 * 8; idx += 192) {
            int r = idx >> 3, u = idx & 7;
            uint32_t doff = (uint32_t)(r * LDP + u * 16);
            int soff = r * HD + u * 8;
            cp16(sb + SM_QHI + doff, qh_g + soff);
            cp16(sb + SM_QLO + doff, ql_g + soff);
        }
    }
    CP_COMMIT();
    CP_WAIT(0);
    __syncthreads();

    const int w = tid >> 5, lane = tid & 31;

    uint32_t qh[4][4], ql[4][4];
    {
        int r = w * 16 + (lane & 15);
        int uo = lane >> 4;
#pragma unroll
        for (int kc = 0; kc < 4; kc++) {
            uint32_t off = (uint32_t)(r * LDP + (2 * kc + uo) * 16);
            ldsm4(qh[kc], sb + SM_QHI + off);
            ldsm4(ql[kc], sb + SM_QLO + off);
        }
    }

    float oacc[8][4];
#pragma unroll
    for (int i = 0; i < 8; i++)
#pragma unroll
        for (int j = 0; j < 4; j++) oacc[i][j] = 0.f;
    float lsum0 = 0.f, lsum1 = 0.f;

    const int krow = (lane & 7) + ((lane >> 4) & 1) * 8;
    const int ku = (lane >> 3) & 1;
    const int vrow = (lane & 7) + ((lane >> 3) & 1) * 8;
    const int vu = (lane >> 4) & 1;

    for (int np = 0; np < 9; np++)
        attn_step(sb, np * 16, false, qh, ql, oacc, lsum0, lsum1, krow, ku, vrow, vu);

    __syncthreads();

    // ---- phase 1: load chunk B (keys 144..263; pad 120..127) ----
    for (int idx = tid; idx < 120 * 8; idx += 192) {
        int r = idx >> 3, u = idx & 7;
        uint32_t doff = (uint32_t)(r * LDP + u * 16);
        int soff = (144 + r) * HD + u * 8;
        cp16(sb + SM_KHI + doff, kh_g + soff);
        cp16(sb + SM_KLO + doff, kl_g + soff);
        cp16(sb + SM_VHI + doff, vh_g + soff);
        cp16(sb + SM_VLO + doff, vl_g + soff);
    }
    for (int idx = tid; idx < 8 * 32; idx += 192) {
        int off = (120 + (idx >> 5)) * LDP + (idx & 31) * 4;
        *(uint32_t*)(smem + SM_KHI + off) = 0;
        *(uint32_t*)(smem + SM_KLO + off) = 0;
        *(uint32_t*)(smem + SM_VHI + off) = 0;
        *(uint32_t*)(smem + SM_VLO + off) = 0;
    }
    CP_COMMIT();
    CP_WAIT(0);
    __syncthreads();

    for (int np = 0; np < 8; np++)
        attn_step(sb, np * 16, np == 7, qh, ql, oacc, lsum0, lsum1, krow, ku, vrow, vu);

    // ---- normalize + write single fp16 plane for O gemm ----
    lsum0 += __shfl_xor_sync(0xffffffffu, lsum0, 1);
    lsum0 += __shfl_xor_sync(0xffffffffu, lsum0, 2);
    lsum1 += __shfl_xor_sync(0xffffffffu, lsum1, 1);
    lsum1 += __shfl_xor_sync(0xffffffffu, lsum1, 2);
    float inv0 = __fdividef(1.f, lsum0);
    float inv1 = __fdividef(1.f, lsum1);

    size_t row0 = (size_t)bt * SEQ + m0 + w * 16 + (lane >> 2);
    int colb = h * HD + 2 * (lane & 3);
#pragma unroll
    for (int nb = 0; nb < 8; nb++) {
        int col = colb + nb * 8;
        *(__half2*)(g_a + row0 * GDIM + col) =
            __floats2half2_rn(oacc[nb][0] * inv0, oacc[nb][1] * inv0);
        *(__half2*)(g_a + (row0 + 8) * GDIM + col) =
            __floats2half2_rn(oacc[nb][2] * inv1, oacc[nb][3] * inv1);
    }
}

// ---------------------------------------------------------------------------
extern "C" void kernel_launch(void* const* d_in, const int* in_sizes, int n_in,
                              void* d_out, int out_size) {
    const float* x   = (const float*)d_in[0];
    const float* wq  = (const float*)d_in[1];
    const float* wk  = (const float*)d_in[2];
    const float* wv  = (const float*)d_in[3];
    const float* wo  = (const float*)d_in[4];
    const float* qnw = (const float*)d_in[5];
    const float* knw = (const float*)d_in[6];
    float* out = (float*)d_out;

    __half *xh, *whi, *wlo, *wohi, *wolo, *ah;
    float* qkv;
    cudaGetSymbolAddress((void**)&xh, g_x);
    cudaGetSymbolAddress((void**)&whi, g_whi);
    cudaGetSymbolAddress((void**)&wlo, g_wlo);
    cudaGetSymbolAddress((void**)&wohi, g_wohi);
    cudaGetSymbolAddress((void**)&wolo, g_wolo);
    cudaGetSymbolAddress((void**)&ah, g_a);
    cudaGetSymbolAddress((void**)&qkv, g_qkv);

    cudaFuncSetAttribute((const void*)gemm_mma,
                         cudaFuncAttributeMaxDynamicSharedMemorySize, GEMM_SMEM);
    cudaFuncSetAttribute((const void*)attn_mma,
                         cudaFuncAttributeMaxDynamicSharedMemorySize, ATT_SMEM);

    // 1) operand conversion: A planes fp16, W planes fp16 hi/lo (x64)
    conv_h<<<4224, 256>>>(x, xh, MROWS * GDIM / 8);
    split_w_qkv<<<768, 256>>>(wq, wk, wv);
    split_h64<<<512, 256>>>(wo, wohi, wolo, GDIM * GDIM / 8);

    // 2) QKV projection (fp16 2-term)
    gemm_mma<<<dim3(QKV_N / 128, MROWS / 128), 256, GEMM_SMEM>>>(
        xh, whi, wlo, qkv, QKV_N);

    // 3) QKNorm + 2D RoPE + split into attention planes
    norm_rope_split<<<MROWS * 3, 256>>>(qnw, knw);

    // 4) tensor-core attention (bf16x3, chunked KV, 2 CTA/SM)
    attn_mma<<<dim3(3, NH, BTN), 192, ATT_SMEM>>>();

    // 5) output projection (fp16 2-term)
    gemm_mma<<<dim3(GDIM / 128, MROWS / 128), 256, GEMM_SMEM>>>(
        ah, wohi, wolo, out, GDIM);
}

// round 10
// speedup vs baseline: 1.8085x; 1.0228x over previous
#include <cuda_runtime.h>
#include <cuda_bf16.h>
#include <cuda_fp16.h>
#include <stdint.h>
#include <math.h>

// Problem constants
#define BTN   64
#define SEQ   264
#define MROWS (BTN*SEQ)      // 16896
#define GDIM  1024
#define NH    16
#define NKV   4
#define HD    64
#define QKV_N 1536
#define NZ    256

// GEMM tiling: block 128x128, BK=32, 8 warps, 4-stage, 2 CTA/SM, fp16 2-term
#define BK    32
#define KT    (GDIM/BK)      // 32
#define PLANE_B 8192         // 128x32 fp16
#define STAGE_B (3*PLANE_B)  // A + Bh + Bl = 24576
#define NSTG  4
#define GEMM_SMEM (NSTG*STAGE_B)   // 98304
#define WSCALE 64.0f
#define WINV   0.015625f

// Attention smem: chunked K/V (144-key buffer) + Q planes; 2 CTA/SM
#define LDP   144
#define CH_ROWS 144
#define SM_KHI 0
#define SM_KLO (CH_ROWS*LDP)
#define SM_VHI (2*CH_ROWS*LDP)
#define SM_VLO (3*CH_ROWS*LDP)
#define SM_QHI (4*CH_ROWS*LDP)
#define SM_QLO (SM_QHI + 96*LDP)
#define ATT_SMEM (SM_QLO + 96*LDP) // 110592

// ---------------------------------------------------------------------------
// device scratch
// ---------------------------------------------------------------------------
__device__ __align__(16) __half g_x[(size_t)MROWS * GDIM];       // A of QKV gemm
__device__ __align__(16) __half g_whi[(size_t)QKV_N * GDIM];     // B of QKV (x64)
__device__ __align__(16) __half g_wlo[(size_t)QKV_N * GDIM];
__device__ __align__(16) __half g_wohi[(size_t)GDIM * GDIM];     // B of O (x64)
__device__ __align__(16) __half g_wolo[(size_t)GDIM * GDIM];
__device__ __align__(16) __half g_a[(size_t)MROWS * GDIM];       // A of O gemm
__device__ __align__(16) float  g_qkv[(size_t)MROWS * QKV_N];
// attention operand planes (bf16 hi/lo)
__device__ __align__(16) __nv_bfloat16 g_kphi[(size_t)BTN * NKV * SEQ * HD];
__device__ __align__(16) __nv_bfloat16 g_kplo[(size_t)BTN * NKV * SEQ * HD];
__device__ __align__(16) __nv_bfloat16 g_vphi[(size_t)BTN * NKV * SEQ * HD];
__device__ __align__(16) __nv_bfloat16 g_vplo[(size_t)BTN * NKV * SEQ * HD];
__device__ __align__(16) __nv_bfloat16 g_qphi[(size_t)BTN * NH * SEQ * HD];
__device__ __align__(16) __nv_bfloat16 g_qplo[(size_t)BTN * NH * SEQ * HD];

// ---------------------------------------------------------------------------
// helpers
// ---------------------------------------------------------------------------
__device__ __forceinline__ uint32_t smem_u32(const void* p) {
    uint32_t a;
    asm("{ .reg .u64 t; cvta.to.shared.u64 t, %1; cvt.u32.u64 %0, t; }"
        : "=r"(a) : "l"(p));
    return a;
}
__device__ __forceinline__ void cp16(uint32_t dst, const void* src) {
    asm volatile("cp.async.cg.shared.global [%0], [%1], 16;" :: "r"(dst), "l"(src));
}
#define CP_COMMIT() asm volatile("cp.async.commit_group;" ::: "memory")
#define CP_WAIT(n)  asm volatile("cp.async.wait_group %0;" :: "n"(n) : "memory")

__device__ __forceinline__ void ldsm4(uint32_t* r, uint32_t addr) {
    asm volatile("ldmatrix.sync.aligned.m8n8.x4.shared.b16 {%0,%1,%2,%3}, [%4];"
                 : "=r"(r[0]), "=r"(r[1]), "=r"(r[2]), "=r"(r[3]) : "r"(addr));
}
__device__ __forceinline__ void ldsm4t(uint32_t* r, uint32_t addr) {
    asm volatile("ldmatrix.sync.aligned.m8n8.x4.trans.shared.b16 {%0,%1,%2,%3}, [%4];"
                 : "=r"(r[0]), "=r"(r[1]), "=r"(r[2]), "=r"(r[3]) : "r"(addr));
}
// bf16 mma (attention)
__device__ __forceinline__ void mma16816(float* c, const uint32_t* a, const uint32_t* b) {
    asm volatile(
        "mma.sync.aligned.m16n8k16.row.col.f32.bf16.bf16.f32 "
        "{%0,%1,%2,%3}, {%4,%5,%6,%7}, {%8,%9}, {%0,%1,%2,%3};"
        : "+f"(c[0]), "+f"(c[1]), "+f"(c[2]), "+f"(c[3])
        : "r"(a[0]), "r"(a[1]), "r"(a[2]), "r"(a[3]), "r"(b[0]), "r"(b[1]));
}
// fp16 mma (GEMMs)
__device__ __forceinline__ void mma16816h(float* c, const uint32_t* a, const uint32_t* b) {
    asm volatile(
        "mma.sync.aligned.m16n8k16.row.col.f32.f16.f16.f32 "
        "{%0,%1,%2,%3}, {%4,%5,%6,%7}, {%8,%9}, {%0,%1,%2,%3};"
        : "+f"(c[0]), "+f"(c[1]), "+f"(c[2]), "+f"(c[3])
        : "r"(a[0]), "r"(a[1]), "r"(a[2]), "r"(a[3]), "r"(b[0]), "r"(b[1]));
}

__device__ __forceinline__ uint32_t swz(int r, int u) {
    return (uint32_t)(r * 64 + ((u ^ ((r >> 1) & 3)) << 4));
}

// split two floats -> hi bf16x2 + lo bf16x2 (attention)
__device__ __forceinline__ void split2(float a, float b, uint32_t& h, uint32_t& l) {
    __nv_bfloat16 ha = __float2bfloat16(a);
    __nv_bfloat16 hb = __float2bfloat16(b);
    float ra = a - __bfloat162float(ha);
    float rb = b - __bfloat162float(hb);
    h = (uint32_t)__bfloat16_as_ushort(ha) | ((uint32_t)__bfloat16_as_ushort(hb) << 16);
    l = (uint32_t)__bfloat16_as_ushort(__float2bfloat16(ra)) |
        ((uint32_t)__bfloat16_as_ushort(__float2bfloat16(rb)) << 16);
}

// softcap+exp on |s|<=8 (Cauchy-Schwarz bound from unit-RMS q,k):
// exp(50*tanh(s/50)) = exp(s)*exp(u), u = -s^3/7500 + 2 s^5/9.375e7
__device__ __forceinline__ float softcap_exp(float s) {
    float s2 = s * s;
    float u = s * s2 * (-1.33333333e-4f + s2 * 2.13333333e-8f);
    float corr = 1.f + u * (1.f + 0.5f * u);
    return __expf(s) * corr;
}

// ---------------------------------------------------------------------------
// conversion kernels
// ---------------------------------------------------------------------------
__global__ void conv_h(const float* __restrict__ src, __half* __restrict__ dst, int nunits) {
    for (int i = blockIdx.x * blockDim.x + threadIdx.x; i < nunits;
         i += gridDim.x * blockDim.x) {
        const float4 f0 = *(const float4*)(src + (size_t)i * 8);
        const float4 f1 = *(const float4*)(src + (size_t)i * 8 + 4);
        __half2 h[4];
        h[0] = __floats2half2_rn(f0.x, f0.y);
        h[1] = __floats2half2_rn(f0.z, f0.w);
        h[2] = __floats2half2_rn(f1.x, f1.y);
        h[3] = __floats2half2_rn(f1.z, f1.w);
        ((uint4*)dst)[i] = *(uint4*)h;
    }
}

__device__ __forceinline__ void split2h64(float a, float b, uint32_t& h, uint32_t& l) {
    a *= WSCALE; b *= WSCALE;
    __half ha = __float2half_rn(a);
    __half hb = __float2half_rn(b);
    float ra = a - __half2float(ha);
    float rb = b - __half2float(hb);
    h = (uint32_t)__half_as_ushort(ha) | ((uint32_t)__half_as_ushort(hb) << 16);
    l = (uint32_t)__half_as_ushort(__float2half_rn(ra)) |
        ((uint32_t)__half_as_ushort(__float2half_rn(rb)) << 16);
}

__global__ void split_h64(const float* __restrict__ src, __half* __restrict__ hi,
                          __half* __restrict__ lo, int nunits) {
    for (int i = blockIdx.x * blockDim.x + threadIdx.x; i < nunits;
         i += gridDim.x * blockDim.x) {
        const float4 f0 = *(const float4*)(src + (size_t)i * 8);
        const float4 f1 = *(const float4*)(src + (size_t)i * 8 + 4);
        uint4 hv, lv;
        split2h64(f0.x, f0.y, hv.x, lv.x);
        split2h64(f0.z, f0.w, hv.y, lv.y);
        split2h64(f1.x, f1.y, hv.z, lv.z);
        split2h64(f1.z, f1.w, hv.w, lv.w);
        ((uint4*)hi)[i] = hv;
        ((uint4*)lo)[i] = lv;
    }
}

__global__ void split_w_qkv(const float* __restrict__ wq, const float* __restrict__ wk,
                            const float* __restrict__ wv) {
    int nunits = QKV_N * (GDIM / 8);
    for (int i = blockIdx.x * blockDim.x + threadIdx.x; i < nunits;
         i += gridDim.x * blockDim.x) {
        int row = i >> 7, ur = i & 127;
        const float* srow;
        if (row < NH * HD)                srow = wq + (size_t)row * GDIM;
        else if (row < NH*HD + NKV*HD)    srow = wk + (size_t)(row - NH*HD) * GDIM;
        else                              srow = wv + (size_t)(row - NH*HD - NKV*HD) * GDIM;
        const float4 f0 = *(const float4*)(srow + ur * 8);
        const float4 f1 = *(const float4*)(srow + ur * 8 + 4);
        uint4 hv, lv;
        split2h64(f0.x, f0.y, hv.x, lv.x);
        split2h64(f0.z, f0.w, hv.y, lv.y);
        split2h64(f1.x, f1.y, hv.z, lv.z);
        split2h64(f1.z, f1.w, hv.w, lv.w);
        ((uint4*)g_whi)[i] = hv;
        ((uint4*)g_wlo)[i] = lv;
    }
}

// ---------------------------------------------------------------------------
// fp16 2-term GEMM: out = (1/64) * A*(Bh+Bl)^T, 128x128 tile, 4-stage, 2 CTA/SM
// ---------------------------------------------------------------------------
__device__ __forceinline__ void load_stage(uint32_t sb, int stage,
        const __half* __restrict__ A, const __half* __restrict__ Bh,
        const __half* __restrict__ Bl, int bm, int bn, int kc, int tid) {
    uint32_t st = sb + stage * STAGE_B;
#pragma unroll
    for (int i = 0; i < 6; i++) {
        int v = i * 256 + tid;
        int op = v >> 9;          // 0:A 1:Bh 2:Bl
        int w = v & 511;
        int r = w >> 2, u = w & 3;
        const __half* base = (op == 0) ? A : (op == 1) ? Bh : Bl;
        int grow = ((op == 0) ? bm : bn) * 128 + r;
        const __half* g = base + (size_t)grow * GDIM + kc * BK + u * 8;
        cp16(st + op * PLANE_B + swz(r, u), g);
    }
}

__global__ __launch_bounds__(256, 2)
void gemm_mma(const __half* __restrict__ A, const __half* __restrict__ Bh,
              const __half* __restrict__ Bl, float* __restrict__ out, int ldc) {
    extern __shared__ __align__(1024) char smem[];
    uint32_t sb = smem_u32(smem);
    int tid = threadIdx.x, wid = tid >> 5, lane = tid & 31;
    int bm = blockIdx.y, bn = blockIdx.x;
    int wm = wid >> 2;
    int wn = wid & 3;

    float acc[4][4][4];
#pragma unroll
    for (int a = 0; a < 4; a++)
#pragma unroll
        for (int b = 0; b < 4; b++)
#pragma unroll
            for (int c = 0; c < 4; c++) acc[a][b][c] = 0.f;

    load_stage(sb, 0, A, Bh, Bl, bm, bn, 0, tid); CP_COMMIT();
    load_stage(sb, 1, A, Bh, Bl, bm, bn, 1, tid); CP_COMMIT();
    load_stage(sb, 2, A, Bh, Bl, bm, bn, 2, tid); CP_COMMIT();

    for (int kc = 0; kc < KT; kc++) {
        CP_WAIT(2);
        __syncthreads();
        if (kc + 3 < KT)
            load_stage(sb, (kc + 3) % NSTG, A, Bh, Bl, bm, bn, kc + 3, tid);
        CP_COMMIT();

        uint32_t st = sb + (kc % NSTG) * STAGE_B;
#pragma unroll
        for (int ks = 0; ks < 2; ks++) {
            uint32_t af[4][4], bhf[4][2], blf[4][2];
#pragma unroll
            for (int mt = 0; mt < 4; mt++) {
                int r = wm * 64 + mt * 16 + (lane & 15);
                int u = 2 * ks + (lane >> 4);
                ldsm4(af[mt], st + swz(r, u));
            }
#pragma unroll
            for (int np = 0; np < 2; np++) {
                int r = wn * 32 + np * 16 + (lane & 7) + ((lane >> 4) & 1) * 8;
                int u = 2 * ks + ((lane >> 3) & 1);
                uint32_t ba = st + PLANE_B + swz(r, u);
                uint32_t t[4];
                ldsm4(t, ba);
                bhf[np*2][0] = t[0]; bhf[np*2][1] = t[1];
                bhf[np*2+1][0] = t[2]; bhf[np*2+1][1] = t[3];
                ldsm4(t, ba + PLANE_B);
                blf[np*2][0] = t[0]; blf[np*2][1] = t[1];
                blf[np*2+1][0] = t[2]; blf[np*2+1][1] = t[3];
            }
#pragma unroll
            for (int mt = 0; mt < 4; mt++)
#pragma unroll
                for (int nt = 0; nt < 4; nt++) mma16816h(acc[mt][nt], af[mt], bhf[nt]);
#pragma unroll
            for (int mt = 0; mt < 4; mt++)
#pragma unroll
                for (int nt = 0; nt < 4; nt++) mma16816h(acc[mt][nt], af[mt], blf[nt]);
        }
    }

#pragma unroll
    for (int mt = 0; mt < 4; mt++)
#pragma unroll
        for (int nt = 0; nt < 4; nt++) {
            float* c = acc[mt][nt];
            int row = bm * 128 + wm * 64 + mt * 16 + (lane >> 2);
            int col = bn * 128 + wn * 32 + nt * 8 + 2 * (lane & 3);
            *(float2*)(out + (size_t)row * ldc + col) =
                make_float2(c[0] * WINV, c[1] * WINV);
            *(float2*)(out + (size_t)(row + 8) * ldc + col) =
                make_float2(c[2] * WINV, c[3] * WINV);
        }
}

// ---------------------------------------------------------------------------
// QKNorm + partial 2D RoPE + split to attn operand planes (bf16)
// ---------------------------------------------------------------------------
__global__ __launch_bounds__(256)
void norm_rope_split(const float* __restrict__ qw, const float* __restrict__ kw) {
    int vec = blockIdx.x * 8 + (threadIdx.x >> 5);
    int lane = threadIdx.x & 31;
    int hh = vec % 24;
    int row = vec / 24;
    int bt = row / SEQ, s = row - bt * SEQ;

    const float* p;
    __nv_bfloat16 *hip, *lop;
    if (hh < NH) {
        p = g_qkv + (size_t)row * QKV_N + hh * HD;
        size_t o = ((size_t)(bt * NH + hh) * SEQ + s) * HD;
        hip = g_qphi + o; lop = g_qplo + o;
    } else if (hh < NH + NKV) {
        p = g_qkv + (size_t)row * QKV_N + GDIM + (hh - NH) * HD;
        size_t o = ((size_t)(bt * NKV + (hh - NH)) * SEQ + s) * HD;
        hip = g_kphi + o; lop = g_kplo + o;
    } else {
        p = g_qkv + (size_t)row * QKV_N + GDIM + NKV * HD + (hh - NH - NKV) * HD;
        size_t o = ((size_t)(bt * NKV + (hh - NH - NKV)) * SEQ + s) * HD;
        hip = g_vphi + o; lop = g_vplo + o;
    }
    float v0 = p[lane], v1 = p[lane + 32];

    if (hh < NH + NKV) {
        float sq = v0 * v0 + v1 * v1;
#pragma unroll
        for (int o = 16; o; o >>= 1) sq += __shfl_xor_sync(0xffffffffu, sq, o);
        float scl = rsqrtf(sq * (1.0f / HD) + 1e-6f);
        const float* wv = (hh < NH) ? qw : kw;
        v0 *= scl * wv[lane];
        v1 *= scl * wv[lane + 32];
        if (s < NZ) {
            int j = lane & 15;
            float pos = (lane < 16) ? (float)(s >> 4) : (float)(s & 15);
            float invf = __expf(-(float)j * 0.57564627324851142f);
            float c, sn;
            sincosf(pos * invf, &sn, &c);
            float o0 = v0 * c - v1 * sn;
            float o1 = v1 * c + v0 * sn;
            v0 = o0; v1 = o1;
        }
    }
    __nv_bfloat16 h0 = __float2bfloat16(v0);
    __nv_bfloat16 h1 = __float2bfloat16(v1);
    hip[lane] = h0;
    hip[lane + 32] = h1;
    lop[lane] = __float2bfloat16(v0 - __bfloat162float(h0));
    lop[lane + 32] = __float2bfloat16(v1 - __bfloat162float(h1));
}

// ---------------------------------------------------------------------------
// Flash-style mma attention (bf16x3, chunked KV, 2 CTA/SM); 1-MUFU softcap.
// ---------------------------------------------------------------------------
__device__ __forceinline__ void attn_step(uint32_t sb, int lr0, bool last,
        const uint32_t qh[4][4], const uint32_t ql[4][4],
        float oacc[8][4], float& lsum0, float& lsum1,
        int krow, int ku, int vrow, int vu) {
    float sA0[4] = {0,0,0,0}, sA1[4] = {0,0,0,0};
    float sB0[4] = {0,0,0,0}, sB1[4] = {0,0,0,0};
    float sC0[4] = {0,0,0,0}, sC1[4] = {0,0,0,0};
#pragma unroll
    for (int kc = 0; kc < 4; kc++) {
        uint32_t off = (uint32_t)((lr0 + krow) * LDP + (2 * kc + ku) * 16);
        uint32_t bh[4], bl[4];
        ldsm4(bh, sb + SM_KHI + off);
        ldsm4(bl, sb + SM_KLO + off);
        mma16816(sA0, qh[kc], bh);
        mma16816(sA1, qh[kc], bh + 2);
        mma16816(sB0, qh[kc], bl);
        mma16816(sB1, qh[kc], bl + 2);
        mma16816(sC0, ql[kc], bh);
        mma16816(sC1, ql[kc], bh + 2);
    }
    float pf[2][4];
#pragma unroll
    for (int e = 0; e < 4; e++) {
        pf[0][e] = softcap_exp((sA0[e] + sB0[e] + sC0[e]) * 0.125f);
        pf[1][e] = softcap_exp((sA1[e] + sB1[e] + sC1[e]) * 0.125f);
    }
    if (last) { pf[1][0] = pf[1][1] = pf[1][2] = pf[1][3] = 0.f; }
    lsum0 += pf[0][0] + pf[0][1] + pf[1][0] + pf[1][1];
    lsum1 += pf[0][2] + pf[0][3] + pf[1][2] + pf[1][3];

    uint32_t ph[4], pl[4];
    split2(pf[0][0], pf[0][1], ph[0], pl[0]);
    split2(pf[0][2], pf[0][3], ph[1], pl[1]);
    split2(pf[1][0], pf[1][1], ph[2], pl[2]);
    split2(pf[1][2], pf[1][3], ph[3], pl[3]);

    uint32_t vh[4][4], vl[4][4];
#pragma unroll
    for (int db = 0; db < 4; db++) {
        uint32_t off = (uint32_t)((lr0 + vrow) * LDP + (2 * db + vu) * 16);
        ldsm4t(vh[db], sb + SM_VHI + off);
        ldsm4t(vl[db], sb + SM_VLO + off);
    }
#pragma unroll
    for (int db = 0; db < 4; db++) {
        mma16816(oacc[2*db],   ph, vh[db]);
        mma16816(oacc[2*db+1], ph, vh[db] + 2);
    }
#pragma unroll
    for (int db = 0; db < 4; db++) {
        mma16816(oacc[2*db],   ph, vl[db]);
        mma16816(oacc[2*db+1], ph, vl[db] + 2);
    }
#pragma unroll
    for (int db = 0; db < 4; db++) {
        mma16816(oacc[2*db],   pl, vh[db]);
        mma16816(oacc[2*db+1], pl, vh[db] + 2);
    }
}

__global__ __launch_bounds__(192, 2) void attn_mma() {
    extern __shared__ __align__(1024) char smem[];
    const int tid = threadIdx.x;
    const int mt = blockIdx.x, h = blockIdx.y, bt = blockIdx.z;
    const int m0 = (mt == 0) ? 0 : (mt == 1 ? 96 : 168);
    const int kvh = h >> 2;
    const uint32_t sb = smem_u32(smem);

    size_t kvo = (size_t)(bt * NKV + kvh) * SEQ * HD;
    const __nv_bfloat16* kh_g = g_kphi + kvo;
    const __nv_bfloat16* kl_g = g_kplo + kvo;
    const __nv_bfloat16* vh_g = g_vphi + kvo;
    const __nv_bfloat16* vl_g = g_vplo + kvo;

    // ---- phase 0: async load Q + chunk A (keys 0..143) ----
    for (int idx = tid; idx < CH_ROWS * 8; idx += 192) {
        int r = idx >> 3, u = idx & 7;
        uint32_t doff = (uint32_t)(r * LDP + u * 16);
        int soff = r * HD + u * 8;
        cp16(sb + SM_KHI + doff, kh_g + soff);
        cp16(sb + SM_KLO + doff, kl_g + soff);
        cp16(sb + SM_VHI + doff, vh_g + soff);
        cp16(sb + SM_VLO + doff, vl_g + soff);
    }
    {
        size_t qo = ((size_t)(bt * NH + h) * SEQ + m0) * HD;
        const __nv_bfloat16* qh_g = g_qphi + qo;
        const __nv_bfloat16* ql_g = g_qplo + qo;
        for (int idx = tid; idx < 96 * 8; idx += 192) {
            int r = idx >> 3, u = idx & 7;
            uint32_t doff = (uint32_t)(r * LDP + u * 16);
            int soff = r * HD + u * 8;
            cp16(sb + SM_QHI + doff, qh_g + soff);
            cp16(sb + SM_QLO + doff, ql_g + soff);
        }
    }
    CP_COMMIT();
    CP_WAIT(0);
    __syncthreads();

    const int w = tid >> 5, lane = tid & 31;

    uint32_t qh[4][4], ql[4][4];
    {
        int r = w * 16 + (lane & 15);
        int uo = lane >> 4;
#pragma unroll
        for (int kc = 0; kc < 4; kc++) {
            uint32_t off = (uint32_t)(r * LDP + (2 * kc + uo) * 16);
            ldsm4(qh[kc], sb + SM_QHI + off);
            ldsm4(ql[kc], sb + SM_QLO + off);
        }
    }

    float oacc[8][4];
#pragma unroll
    for (int i = 0; i < 8; i++)
#pragma unroll
        for (int j = 0; j < 4; j++) oacc[i][j] = 0.f;
    float lsum0 = 0.f, lsum1 = 0.f;

    const int krow = (lane & 7) + ((lane >> 4) & 1) * 8;
    const int ku = (lane >> 3) & 1;
    const int vrow = (lane & 7) + ((lane >> 3) & 1) * 8;
    const int vu = (lane >> 4) & 1;

    for (int np = 0; np < 9; np++)
        attn_step(sb, np * 16, false, qh, ql, oacc, lsum0, lsum1, krow, ku, vrow, vu);

    __syncthreads();

    // ---- phase 1: load chunk B (keys 144..263; pad 120..127) ----
    for (int idx = tid; idx < 120 * 8; idx += 192) {
        int r = idx >> 3, u = idx & 7;
        uint32_t doff = (uint32_t)(r * LDP + u * 16);
        int soff = (144 + r) * HD + u * 8;
        cp16(sb + SM_KHI + doff, kh_g + soff);
        cp16(sb + SM_KLO + doff, kl_g + soff);
        cp16(sb + SM_VHI + doff, vh_g + soff);
        cp16(sb + SM_VLO + doff, vl_g + soff);
    }
    for (int idx = tid; idx < 8 * 32; idx += 192) {
        int off = (120 + (idx >> 5)) * LDP + (idx & 31) * 4;
        *(uint32_t*)(smem + SM_KHI + off) = 0;
        *(uint32_t*)(smem + SM_KLO + off) = 0;
        *(uint32_t*)(smem + SM_VHI + off) = 0;
        *(uint32_t*)(smem + SM_VLO + off) = 0;
    }
    CP_COMMIT();
    CP_WAIT(0);
    __syncthreads();

    for (int np = 0; np < 8; np++)
        attn_step(sb, np * 16, np == 7, qh, ql, oacc, lsum0, lsum1, krow, ku, vrow, vu);

    // ---- normalize + write single fp16 plane for O gemm ----
    lsum0 += __shfl_xor_sync(0xffffffffu, lsum0, 1);
    lsum0 += __shfl_xor_sync(0xffffffffu, lsum0, 2);
    lsum1 += __shfl_xor_sync(0xffffffffu, lsum1, 1);
    lsum1 += __shfl_xor_sync(0xffffffffu, lsum1, 2);
    float inv0 = __fdividef(1.f, lsum0);
    float inv1 = __fdividef(1.f, lsum1);

    size_t row0 = (size_t)bt * SEQ + m0 + w * 16 + (lane >> 2);
    int colb = h * HD + 2 * (lane & 3);
#pragma unroll
    for (int nb = 0; nb < 8; nb++) {
        int col = colb + nb * 8;
        *(__half2*)(g_a + row0 * GDIM + col) =
            __floats2half2_rn(oacc[nb][0] * inv0, oacc[nb][1] * inv0);
        *(__half2*)(g_a + (row0 + 8) * GDIM + col) =
            __floats2half2_rn(oacc[nb][2] * inv1, oacc[nb][3] * inv1);
    }
}

// ---------------------------------------------------------------------------
extern "C" void kernel_launch(void* const* d_in, const int* in_sizes, int n_in,
                              void* d_out, int out_size) {
    const float* x   = (const float*)d_in[0];
    const float* wq  = (const float*)d_in[1];
    const float* wk  = (const float*)d_in[2];
    const float* wv  = (const float*)d_in[3];
    const float* wo  = (const float*)d_in[4];
    const float* qnw = (const float*)d_in[5];
    const float* knw = (const float*)d_in[6];
    float* out = (float*)d_out;

    __half *xh, *whi, *wlo, *wohi, *wolo, *ah;
    float* qkv;
    cudaGetSymbolAddress((void**)&xh, g_x);
    cudaGetSymbolAddress((void**)&whi, g_whi);
    cudaGetSymbolAddress((void**)&wlo, g_wlo);
    cudaGetSymbolAddress((void**)&wohi, g_wohi);
    cudaGetSymbolAddress((void**)&wolo, g_wolo);
    cudaGetSymbolAddress((void**)&ah, g_a);
    cudaGetSymbolAddress((void**)&qkv, g_qkv);

    cudaFuncSetAttribute((const void*)gemm_mma,
                         cudaFuncAttributeMaxDynamicSharedMemorySize, GEMM_SMEM);
    cudaFuncSetAttribute((const void*)attn_mma,
                         cudaFuncAttributeMaxDynamicSharedMemorySize, ATT_SMEM);

    // 1) operand conversion
    conv_h<<<4224, 256>>>(x, xh, MROWS * GDIM / 8);
    split_w_qkv<<<768, 256>>>(wq, wk, wv);
    split_h64<<<512, 256>>>(wo, wohi, wolo, GDIM * GDIM / 8);

    // 2) QKV projection (fp16 2-term, 4-stage)
    gemm_mma<<<dim3(QKV_N / 128, MROWS / 128), 256, GEMM_SMEM>>>(
        xh, whi, wlo, qkv, QKV_N);

    // 3) QKNorm + 2D RoPE + split into attention planes
    norm_rope_split<<<MROWS * 3, 256>>>(qnw, knw);

    // 4) tensor-core attention (bf16x3, chunked KV, 2 CTA/SM, 1-MUFU softcap)
    attn_mma<<<dim3(3, NH, BTN), 192, ATT_SMEM>>>();

    // 5) output projection (fp16 2-term, 4-stage)
    gemm_mma<<<dim3(GDIM / 128, MROWS / 128), 256, GEMM_SMEM>>>(
        ah, wohi, wolo, out, GDIM);
}

// round 11
// speedup vs baseline: 2.0951x; 1.1585x over previous
#include <cuda_runtime.h>
#include <cuda_bf16.h>
#include <cuda_fp16.h>
#include <stdint.h>
#include <math.h>

// Problem constants
#define BTN   64
#define SEQ   264
#define MROWS (BTN*SEQ)      // 16896
#define GDIM  1024
#define NH    16
#define NKV   4
#define HD    64
#define QKV_N 1536
#define NZ    256

// GEMM tiling: block 128x128, BK=32, 8 warps, 4-stage, 2 CTA/SM
#define BK    32
#define KT    (GDIM/BK)      // 32
#define PLANE_B 8192         // 128x32 fp16
#define STAGE_B (3*PLANE_B)  // QKV gemm: A + Bh + Bl
#define NSTG  4
#define GEMM_SMEM (NSTG*STAGE_B)    // 98304
#define STAGE1_B (2*PLANE_B)        // O gemm: A + B
#define GEMM1_SMEM (NSTG*STAGE1_B)  // 65536
#define WSCALE 64.0f
#define WINV   0.015625f

// Attention smem: chunked K/V (144-key buffer) + Q planes; 2 CTA/SM
#define LDP   144
#define CH_ROWS 144
#define SM_KHI 0
#define SM_KLO (CH_ROWS*LDP)
#define SM_VHI (2*CH_ROWS*LDP)
#define SM_VLO (3*CH_ROWS*LDP)
#define SM_QHI (4*CH_ROWS*LDP)
#define SM_QLO (SM_QHI + 96*LDP)
#define ATT_SMEM (SM_QLO + 96*LDP) // 110592

// ---------------------------------------------------------------------------
// device scratch
// ---------------------------------------------------------------------------
__device__ __align__(16) __half g_x[(size_t)MROWS * GDIM];       // A of QKV gemm
__device__ __align__(16) __half g_whi[(size_t)QKV_N * GDIM];     // B of QKV (x64)
__device__ __align__(16) __half g_wlo[(size_t)QKV_N * GDIM];
__device__ __align__(16) __half g_wo[(size_t)GDIM * GDIM];       // B of O (single)
__device__ __align__(16) __half g_a[(size_t)MROWS * GDIM];       // A of O gemm
__device__ __align__(16) float  g_qkv[(size_t)MROWS * QKV_N];
// attention operand planes: q,k bf16 hi/lo; v fp16 hi/lo
__device__ __align__(16) __nv_bfloat16 g_kphi[(size_t)BTN * NKV * SEQ * HD];
__device__ __align__(16) __nv_bfloat16 g_kplo[(size_t)BTN * NKV * SEQ * HD];
__device__ __align__(16) __half        g_vphi[(size_t)BTN * NKV * SEQ * HD];
__device__ __align__(16) __half        g_vplo[(size_t)BTN * NKV * SEQ * HD];
__device__ __align__(16) __nv_bfloat16 g_qphi[(size_t)BTN * NH * SEQ * HD];
__device__ __align__(16) __nv_bfloat16 g_qplo[(size_t)BTN * NH * SEQ * HD];

// ---------------------------------------------------------------------------
// helpers
// ---------------------------------------------------------------------------
__device__ __forceinline__ uint32_t smem_u32(const void* p) {
    uint32_t a;
    asm("{ .reg .u64 t; cvta.to.shared.u64 t, %1; cvt.u32.u64 %0, t; }"
        : "=r"(a) : "l"(p));
    return a;
}
__device__ __forceinline__ void cp16(uint32_t dst, const void* src) {
    asm volatile("cp.async.cg.shared.global [%0], [%1], 16;" :: "r"(dst), "l"(src));
}
#define CP_COMMIT() asm volatile("cp.async.commit_group;" ::: "memory")
#define CP_WAIT(n)  asm volatile("cp.async.wait_group %0;" :: "n"(n) : "memory")

__device__ __forceinline__ void ldsm4(uint32_t* r, uint32_t addr) {
    asm volatile("ldmatrix.sync.aligned.m8n8.x4.shared.b16 {%0,%1,%2,%3}, [%4];"
                 : "=r"(r[0]), "=r"(r[1]), "=r"(r[2]), "=r"(r[3]) : "r"(addr));
}
__device__ __forceinline__ void ldsm4t(uint32_t* r, uint32_t addr) {
    asm volatile("ldmatrix.sync.aligned.m8n8.x4.trans.shared.b16 {%0,%1,%2,%3}, [%4];"
                 : "=r"(r[0]), "=r"(r[1]), "=r"(r[2]), "=r"(r[3]) : "r"(addr));
}
// bf16 mma (attention QK)
__device__ __forceinline__ void mma16816(float* c, const uint32_t* a, const uint32_t* b) {
    asm volatile(
        "mma.sync.aligned.m16n8k16.row.col.f32.bf16.bf16.f32 "
        "{%0,%1,%2,%3}, {%4,%5,%6,%7}, {%8,%9}, {%0,%1,%2,%3};"
        : "+f"(c[0]), "+f"(c[1]), "+f"(c[2]), "+f"(c[3])
        : "r"(a[0]), "r"(a[1]), "r"(a[2]), "r"(a[3]), "r"(b[0]), "r"(b[1]));
}
// fp16 mma (GEMMs + PV)
__device__ __forceinline__ void mma16816h(float* c, const uint32_t* a, const uint32_t* b) {
    asm volatile(
        "mma.sync.aligned.m16n8k16.row.col.f32.f16.f16.f32 "
        "{%0,%1,%2,%3}, {%4,%5,%6,%7}, {%8,%9}, {%0,%1,%2,%3};"
        : "+f"(c[0]), "+f"(c[1]), "+f"(c[2]), "+f"(c[3])
        : "r"(a[0]), "r"(a[1]), "r"(a[2]), "r"(a[3]), "r"(b[0]), "r"(b[1]));
}

__device__ __forceinline__ uint32_t swz(int r, int u) {
    return (uint32_t)(r * 64 + ((u ^ ((r >> 1) & 3)) << 4));
}

// split two floats -> hi bf16x2 + lo bf16x2
__device__ __forceinline__ void split2(float a, float b, uint32_t& h, uint32_t& l) {
    __nv_bfloat16 ha = __float2bfloat16(a);
    __nv_bfloat16 hb = __float2bfloat16(b);
    float ra = a - __bfloat162float(ha);
    float rb = b - __bfloat162float(hb);
    h = (uint32_t)__bfloat16_as_ushort(ha) | ((uint32_t)__bfloat16_as_ushort(hb) << 16);
    l = (uint32_t)__bfloat16_as_ushort(__float2bfloat16(ra)) |
        ((uint32_t)__bfloat16_as_ushort(__float2bfloat16(rb)) << 16);
}

// softcap+exp on |s|<=8: exp(50*tanh(s/50)) = exp(s)*exp(u)
__device__ __forceinline__ float softcap_exp(float s) {
    float s2 = s * s;
    float u = s * s2 * (-1.33333333e-4f + s2 * 2.13333333e-8f);
    float corr = 1.f + u * (1.f + 0.5f * u);
    return __expf(s) * corr;
}

// ---------------------------------------------------------------------------
// conversion kernels
// ---------------------------------------------------------------------------
__global__ void conv_h(const float* __restrict__ src, __half* __restrict__ dst, int nunits) {
    for (int i = blockIdx.x * blockDim.x + threadIdx.x; i < nunits;
         i += gridDim.x * blockDim.x) {
        const float4 f0 = *(const float4*)(src + (size_t)i * 8);
        const float4 f1 = *(const float4*)(src + (size_t)i * 8 + 4);
        __half2 h[4];
        h[0] = __floats2half2_rn(f0.x, f0.y);
        h[1] = __floats2half2_rn(f0.z, f0.w);
        h[2] = __floats2half2_rn(f1.x, f1.y);
        h[3] = __floats2half2_rn(f1.z, f1.w);
        ((uint4*)dst)[i] = *(uint4*)h;
    }
}

__device__ __forceinline__ void split2h64(float a, float b, uint32_t& h, uint32_t& l) {
    a *= WSCALE; b *= WSCALE;
    __half ha = __float2half_rn(a);
    __half hb = __float2half_rn(b);
    float ra = a - __half2float(ha);
    float rb = b - __half2float(hb);
    h = (uint32_t)__half_as_ushort(ha) | ((uint32_t)__half_as_ushort(hb) << 16);
    l = (uint32_t)__half_as_ushort(__float2half_rn(ra)) |
        ((uint32_t)__half_as_ushort(__float2half_rn(rb)) << 16);
}

__global__ void split_w_qkv(const float* __restrict__ wq, const float* __restrict__ wk,
                            const float* __restrict__ wv) {
    int nunits = QKV_N * (GDIM / 8);
    for (int i = blockIdx.x * blockDim.x + threadIdx.x; i < nunits;
         i += gridDim.x * blockDim.x) {
        int row = i >> 7, ur = i & 127;
        const float* srow;
        if (row < NH * HD)                srow = wq + (size_t)row * GDIM;
        else if (row < NH*HD + NKV*HD)    srow = wk + (size_t)(row - NH*HD) * GDIM;
        else                              srow = wv + (size_t)(row - NH*HD - NKV*HD) * GDIM;
        const float4 f0 = *(const float4*)(srow + ur * 8);
        const float4 f1 = *(const float4*)(srow + ur * 8 + 4);
        uint4 hv, lv;
        split2h64(f0.x, f0.y, hv.x, lv.x);
        split2h64(f0.z, f0.w, hv.y, lv.y);
        split2h64(f1.x, f1.y, hv.z, lv.z);
        split2h64(f1.z, f1.w, hv.w, lv.w);
        ((uint4*)g_whi)[i] = hv;
        ((uint4*)g_wlo)[i] = lv;
    }
}

// ---------------------------------------------------------------------------
// fp16 2-term GEMM (QKV): out = (1/64) * A*(Bh+Bl)^T
// ---------------------------------------------------------------------------
__device__ __forceinline__ void load_stage(uint32_t sb, int stage,
        const __half* __restrict__ A, const __half* __restrict__ Bh,
        const __half* __restrict__ Bl, int bm, int bn, int kc, int tid) {
    uint32_t st = sb + stage * STAGE_B;
#pragma unroll
    for (int i = 0; i < 6; i++) {
        int v = i * 256 + tid;
        int op = v >> 9;          // 0:A 1:Bh 2:Bl
        int w = v & 511;
        int r = w >> 2, u = w & 3;
        const __half* base = (op == 0) ? A : (op == 1) ? Bh : Bl;
        int grow = ((op == 0) ? bm : bn) * 128 + r;
        const __half* g = base + (size_t)grow * GDIM + kc * BK + u * 8;
        cp16(st + op * PLANE_B + swz(r, u), g);
    }
}

__global__ __launch_bounds__(256, 2)
void gemm_mma(const __half* __restrict__ A, const __half* __restrict__ Bh,
              const __half* __restrict__ Bl, float* __restrict__ out, int ldc) {
    extern __shared__ __align__(1024) char smem[];
    uint32_t sb = smem_u32(smem);
    int tid = threadIdx.x, wid = tid >> 5, lane = tid & 31;
    int bm = blockIdx.y, bn = blockIdx.x;
    int wm = wid >> 2;
    int wn = wid & 3;

    float acc[4][4][4];
#pragma unroll
    for (int a = 0; a < 4; a++)
#pragma unroll
        for (int b = 0; b < 4; b++)
#pragma unroll
            for (int c = 0; c < 4; c++) acc[a][b][c] = 0.f;

    load_stage(sb, 0, A, Bh, Bl, bm, bn, 0, tid); CP_COMMIT();
    load_stage(sb, 1, A, Bh, Bl, bm, bn, 1, tid); CP_COMMIT();
    load_stage(sb, 2, A, Bh, Bl, bm, bn, 2, tid); CP_COMMIT();

    for (int kc = 0; kc < KT; kc++) {
        CP_WAIT(2);
        __syncthreads();
        if (kc + 3 < KT)
            load_stage(sb, (kc + 3) % NSTG, A, Bh, Bl, bm, bn, kc + 3, tid);
        CP_COMMIT();

        uint32_t st = sb + (kc % NSTG) * STAGE_B;
#pragma unroll
        for (int ks = 0; ks < 2; ks++) {
            uint32_t af[4][4], bhf[4][2], blf[4][2];
#pragma unroll
            for (int mt = 0; mt < 4; mt++) {
                int r = wm * 64 + mt * 16 + (lane & 15);
                int u = 2 * ks + (lane >> 4);
                ldsm4(af[mt], st + swz(r, u));
            }
#pragma unroll
            for (int np = 0; np < 2; np++) {
                int r = wn * 32 + np * 16 + (lane & 7) + ((lane >> 4) & 1) * 8;
                int u = 2 * ks + ((lane >> 3) & 1);
                uint32_t ba = st + PLANE_B + swz(r, u);
                uint32_t t[4];
                ldsm4(t, ba);
                bhf[np*2][0] = t[0]; bhf[np*2][1] = t[1];
                bhf[np*2+1][0] = t[2]; bhf[np*2+1][1] = t[3];
                ldsm4(t, ba + PLANE_B);
                blf[np*2][0] = t[0]; blf[np*2][1] = t[1];
                blf[np*2+1][0] = t[2]; blf[np*2+1][1] = t[3];
            }
#pragma unroll
            for (int mt = 0; mt < 4; mt++)
#pragma unroll
                for (int nt = 0; nt < 4; nt++) mma16816h(acc[mt][nt], af[mt], bhf[nt]);
#pragma unroll
            for (int mt = 0; mt < 4; mt++)
#pragma unroll
                for (int nt = 0; nt < 4; nt++) mma16816h(acc[mt][nt], af[mt], blf[nt]);
        }
    }

#pragma unroll
    for (int mt = 0; mt < 4; mt++)
#pragma unroll
        for (int nt = 0; nt < 4; nt++) {
            float* c = acc[mt][nt];
            int row = bm * 128 + wm * 64 + mt * 16 + (lane >> 2);
            int col = bn * 128 + wn * 32 + nt * 8 + 2 * (lane & 3);
            *(float2*)(out + (size_t)row * ldc + col) =
                make_float2(c[0] * WINV, c[1] * WINV);
            *(float2*)(out + (size_t)(row + 8) * ldc + col) =
                make_float2(c[2] * WINV, c[3] * WINV);
        }
}

// ---------------------------------------------------------------------------
// fp16 single-plane GEMM (O projection): out = A*B^T
// ---------------------------------------------------------------------------
__device__ __forceinline__ void load_stage1(uint32_t sb, int stage,
        const __half* __restrict__ A, const __half* __restrict__ B,
        int bm, int bn, int kc, int tid) {
    uint32_t st = sb + stage * STAGE1_B;
#pragma unroll
    for (int i = 0; i < 4; i++) {
        int v = i * 256 + tid;
        int op = v >> 9;          // 0:A 1:B
        int w = v & 511;
        int r = w >> 2, u = w & 3;
        const __half* base = (op == 0) ? A : B;
        int grow = ((op == 0) ? bm : bn) * 128 + r;
        const __half* g = base + (size_t)grow * GDIM + kc * BK + u * 8;
        cp16(st + op * PLANE_B + swz(r, u), g);
    }
}

__global__ __launch_bounds__(256, 2)
void gemm_mma1(const __half* __restrict__ A, const __half* __restrict__ B,
               float* __restrict__ out, int ldc) {
    extern __shared__ __align__(1024) char smem[];
    uint32_t sb = smem_u32(smem);
    int tid = threadIdx.x, wid = tid >> 5, lane = tid & 31;
    int bm = blockIdx.y, bn = blockIdx.x;
    int wm = wid >> 2;
    int wn = wid & 3;

    float acc[4][4][4];
#pragma unroll
    for (int a = 0; a < 4; a++)
#pragma unroll
        for (int b = 0; b < 4; b++)
#pragma unroll
            for (int c = 0; c < 4; c++) acc[a][b][c] = 0.f;

    load_stage1(sb, 0, A, B, bm, bn, 0, tid); CP_COMMIT();
    load_stage1(sb, 1, A, B, bm, bn, 1, tid); CP_COMMIT();
    load_stage1(sb, 2, A, B, bm, bn, 2, tid); CP_COMMIT();

    for (int kc = 0; kc < KT; kc++) {
        CP_WAIT(2);
        __syncthreads();
        if (kc + 3 < KT)
            load_stage1(sb, (kc + 3) % NSTG, A, B, bm, bn, kc + 3, tid);
        CP_COMMIT();

        uint32_t st = sb + (kc % NSTG) * STAGE1_B;
#pragma unroll
        for (int ks = 0; ks < 2; ks++) {
            uint32_t af[4][4], bf[4][2];
#pragma unroll
            for (int mt = 0; mt < 4; mt++) {
                int r = wm * 64 + mt * 16 + (lane & 15);
                int u = 2 * ks + (lane >> 4);
                ldsm4(af[mt], st + swz(r, u));
            }
#pragma unroll
            for (int np = 0; np < 2; np++) {
                int r = wn * 32 + np * 16 + (lane & 7) + ((lane >> 4) & 1) * 8;
                int u = 2 * ks + ((lane >> 3) & 1);
                uint32_t t[4];
                ldsm4(t, st + PLANE_B + swz(r, u));
                bf[np*2][0] = t[0]; bf[np*2][1] = t[1];
                bf[np*2+1][0] = t[2]; bf[np*2+1][1] = t[3];
            }
#pragma unroll
            for (int mt = 0; mt < 4; mt++)
#pragma unroll
                for (int nt = 0; nt < 4; nt++) mma16816h(acc[mt][nt], af[mt], bf[nt]);
        }
    }

#pragma unroll
    for (int mt = 0; mt < 4; mt++)
#pragma unroll
        for (int nt = 0; nt < 4; nt++) {
            float* c = acc[mt][nt];
            int row = bm * 128 + wm * 64 + mt * 16 + (lane >> 2);
            int col = bn * 128 + wn * 32 + nt * 8 + 2 * (lane & 3);
            *(float2*)(out + (size_t)row * ldc + col) = make_float2(c[0], c[1]);
            *(float2*)(out + (size_t)(row + 8) * ldc + col) = make_float2(c[2], c[3]);
        }
}

// ---------------------------------------------------------------------------
// QKNorm + partial 2D RoPE + split to attn operand planes
// q,k -> bf16 hi/lo; v -> fp16 hi/lo
// ---------------------------------------------------------------------------
__global__ __launch_bounds__(256)
void norm_rope_split(const float* __restrict__ qw, const float* __restrict__ kw) {
    int vec = blockIdx.x * 8 + (threadIdx.x >> 5);
    int lane = threadIdx.x & 31;
    int hh = vec % 24;
    int row = vec / 24;
    int bt = row / SEQ, s = row - bt * SEQ;

    if (hh >= NH + NKV) {
        // V path: raw, fp16 split
        const float* p = g_qkv + (size_t)row * QKV_N + GDIM + NKV * HD + (hh - NH - NKV) * HD;
        size_t o = ((size_t)(bt * NKV + (hh - NH - NKV)) * SEQ + s) * HD;
        float v0 = p[lane], v1 = p[lane + 32];
        __half h0 = __float2half_rn(v0);
        __half h1 = __float2half_rn(v1);
        g_vphi[o + lane] = h0;
        g_vphi[o + lane + 32] = h1;
        g_vplo[o + lane] = __float2half_rn(v0 - __half2float(h0));
        g_vplo[o + lane + 32] = __float2half_rn(v1 - __half2float(h1));
        return;
    }

    const float* p;
    __nv_bfloat16 *hip, *lop;
    if (hh < NH) {
        p = g_qkv + (size_t)row * QKV_N + hh * HD;
        size_t o = ((size_t)(bt * NH + hh) * SEQ + s) * HD;
        hip = g_qphi + o; lop = g_qplo + o;
    } else {
        p = g_qkv + (size_t)row * QKV_N + GDIM + (hh - NH) * HD;
        size_t o = ((size_t)(bt * NKV + (hh - NH)) * SEQ + s) * HD;
        hip = g_kphi + o; lop = g_kplo + o;
    }
    float v0 = p[lane], v1 = p[lane + 32];

    float sq = v0 * v0 + v1 * v1;
#pragma unroll
    for (int o = 16; o; o >>= 1) sq += __shfl_xor_sync(0xffffffffu, sq, o);
    float scl = rsqrtf(sq * (1.0f / HD) + 1e-6f);
    const float* wv = (hh < NH) ? qw : kw;
    v0 *= scl * wv[lane];
    v1 *= scl * wv[lane + 32];
    if (s < NZ) {
        int j = lane & 15;
        float pos = (lane < 16) ? (float)(s >> 4) : (float)(s & 15);
        float invf = __expf(-(float)j * 0.57564627324851142f);
        float c, sn;
        sincosf(pos * invf, &sn, &c);
        float o0 = v0 * c - v1 * sn;
        float o1 = v1 * c + v0 * sn;
        v0 = o0; v1 = o1;
    }
    __nv_bfloat16 h0 = __float2bfloat16(v0);
    __nv_bfloat16 h1 = __float2bfloat16(v1);
    hip[lane] = h0;
    hip[lane + 32] = h1;
    lop[lane] = __float2bfloat16(v0 - __bfloat162float(h0));
    lop[lane + 32] = __float2bfloat16(v1 - __bfloat162float(h1));
}

// ---------------------------------------------------------------------------
// Flash-style mma attention: QK bf16x3, PV fp16 2-term (p single fp16)
// ---------------------------------------------------------------------------
__device__ __forceinline__ void attn_step(uint32_t sb, int lr0, bool last,
        const uint32_t qh[4][4], const uint32_t ql[4][4],
        float oacc[8][4], float& lsum0, float& lsum1,
        int krow, int ku, int vrow, int vu) {
    float sA0[4] = {0,0,0,0}, sA1[4] = {0,0,0,0};
    float sB0[4] = {0,0,0,0}, sB1[4] = {0,0,0,0};
    float sC0[4] = {0,0,0,0}, sC1[4] = {0,0,0,0};
#pragma unroll
    for (int kc = 0; kc < 4; kc++) {
        uint32_t off = (uint32_t)((lr0 + krow) * LDP + (2 * kc + ku) * 16);
        uint32_t bh[4], bl[4];
        ldsm4(bh, sb + SM_KHI + off);
        ldsm4(bl, sb + SM_KLO + off);
        mma16816(sA0, qh[kc], bh);
        mma16816(sA1, qh[kc], bh + 2);
        mma16816(sB0, qh[kc], bl);
        mma16816(sB1, qh[kc], bl + 2);
        mma16816(sC0, ql[kc], bh);
        mma16816(sC1, ql[kc], bh + 2);
    }
    float pf[2][4];
#pragma unroll
    for (int e = 0; e < 4; e++) {
        pf[0][e] = softcap_exp((sA0[e] + sB0[e] + sC0[e]) * 0.125f);
        pf[1][e] = softcap_exp((sA1[e] + sB1[e] + sC1[e]) * 0.125f);
    }
    if (last) { pf[1][0] = pf[1][1] = pf[1][2] = pf[1][3] = 0.f; }
    lsum0 += pf[0][0] + pf[0][1] + pf[1][0] + pf[1][1];
    lsum1 += pf[0][2] + pf[0][3] + pf[1][2] + pf[1][3];

    // p -> single fp16 A-fragment (p <= e^8 < 65504, exact fit)
    uint32_t ph[4];
    __half2 p0 = __floats2half2_rn(pf[0][0], pf[0][1]);
    __half2 p1 = __floats2half2_rn(pf[0][2], pf[0][3]);
    __half2 p2 = __floats2half2_rn(pf[1][0], pf[1][1]);
    __half2 p3 = __floats2half2_rn(pf[1][2], pf[1][3]);
    ph[0] = *(uint32_t*)&p0; ph[1] = *(uint32_t*)&p1;
    ph[2] = *(uint32_t*)&p2; ph[3] = *(uint32_t*)&p3;

    uint32_t vh[4][4], vl[4][4];
#pragma unroll
    for (int db = 0; db < 4; db++) {
        uint32_t off = (uint32_t)((lr0 + vrow) * LDP + (2 * db + vu) * 16);
        ldsm4t(vh[db], sb + SM_VHI + off);
        ldsm4t(vl[db], sb + SM_VLO + off);
    }
#pragma unroll
    for (int db = 0; db < 4; db++) {
        mma16816h(oacc[2*db],   ph, vh[db]);
        mma16816h(oacc[2*db+1], ph, vh[db] + 2);
    }
#pragma unroll
    for (int db = 0; db < 4; db++) {
        mma16816h(oacc[2*db],   ph, vl[db]);
        mma16816h(oacc[2*db+1], ph, vl[db] + 2);
    }
}

__global__ __launch_bounds__(192, 2) void attn_mma() {
    extern __shared__ __align__(1024) char smem[];
    const int tid = threadIdx.x;
    const int mt = blockIdx.x, h = blockIdx.y, bt = blockIdx.z;
    const int m0 = (mt == 0) ? 0 : (mt == 1 ? 96 : 168);
    const int kvh = h >> 2;
    const uint32_t sb = smem_u32(smem);

    size_t kvo = (size_t)(bt * NKV + kvh) * SEQ * HD;
    const __nv_bfloat16* kh_g = g_kphi + kvo;
    const __nv_bfloat16* kl_g = g_kplo + kvo;
    const __half* vh_g = g_vphi + kvo;
    const __half* vl_g = g_vplo + kvo;

    // ---- phase 0: async load Q + chunk A (keys 0..143) ----
    for (int idx = tid; idx < CH_ROWS * 8; idx += 192) {
        int r = idx >> 3, u = idx & 7;
        uint32_t doff = (uint32_t)(r * LDP + u * 16);
        int soff = r * HD + u * 8;
        cp16(sb + SM_KHI + doff, kh_g + soff);
        cp16(sb + SM_KLO + doff, kl_g + soff);
        cp16(sb + SM_VHI + doff, vh_g + soff);
        cp16(sb + SM_VLO + doff, vl_g + soff);
    }
    {
        size_t qo = ((size_t)(bt * NH + h) * SEQ + m0) * HD;
        const __nv_bfloat16* qh_g = g_qphi + qo;
        const __nv_bfloat16* ql_g = g_qplo + qo;
        for (int idx = tid; idx < 96 * 8; idx += 192) {
            int r = idx >> 3, u = idx & 7;
            uint32_t doff = (uint32_t)(r * LDP + u * 16);
            int soff = r * HD + u * 8;
            cp16(sb + SM_QHI + doff, qh_g + soff);
            cp16(sb + SM_QLO + doff, ql_g + soff);
        }
    }
    CP_COMMIT();
    CP_WAIT(0);
    __syncthreads();

    const int w = tid >> 5, lane = tid & 31;

    uint32_t qh[4][4], ql[4][4];
    {
        int r = w * 16 + (lane & 15);
        int uo = lane >> 4;
#pragma unroll
        for (int kc = 0; kc < 4; kc++) {
            uint32_t off = (uint32_t)(r * LDP + (2 * kc + uo) * 16);
            ldsm4(qh[kc], sb + SM_QHI + off);
            ldsm4(ql[kc], sb + SM_QLO + off);
        }
    }

    float oacc[8][4];
#pragma unroll
    for (int i = 0; i < 8; i++)
#pragma unroll
        for (int j = 0; j < 4; j++) oacc[i][j] = 0.f;
    float lsum0 = 0.f, lsum1 = 0.f;

    const int krow = (lane & 7) + ((lane >> 4) & 1) * 8;
    const int ku = (lane >> 3) & 1;
    const int vrow = (lane & 7) + ((lane >> 3) & 1) * 8;
    const int vu = (lane >> 4) & 1;

    for (int np = 0; np < 9; np++)
        attn_step(sb, np * 16, false, qh, ql, oacc, lsum0, lsum1, krow, ku, vrow, vu);

    __syncthreads();

    // ---- phase 1: load chunk B (keys 144..263; pad 120..127) ----
    for (int idx = tid; idx < 120 * 8; idx += 192) {
        int r = idx >> 3, u = idx & 7;
        uint32_t doff = (uint32_t)(r * LDP + u * 16);
        int soff = (144 + r) * HD + u * 8;
        cp16(sb + SM_KHI + doff, kh_g + soff);
        cp16(sb + SM_KLO + doff, kl_g + soff);
        cp16(sb + SM_VHI + doff, vh_g + soff);
        cp16(sb + SM_VLO + doff, vl_g + soff);
    }
    for (int idx = tid; idx < 8 * 32; idx += 192) {
        int off = (120 + (idx >> 5)) * LDP + (idx & 31) * 4;
        *(uint32_t*)(smem + SM_KHI + off) = 0;
        *(uint32_t*)(smem + SM_KLO + off) = 0;
        *(uint32_t*)(smem + SM_VHI + off) = 0;
        *(uint32_t*)(smem + SM_VLO + off) = 0;
    }
    CP_COMMIT();
    CP_WAIT(0);
    __syncthreads();

    for (int np = 0; np < 8; np++)
        attn_step(sb, np * 16, np == 7, qh, ql, oacc, lsum0, lsum1, krow, ku, vrow, vu);

    // ---- normalize + write single fp16 plane for O gemm ----
    lsum0 += __shfl_xor_sync(0xffffffffu, lsum0, 1);
    lsum0 += __shfl_xor_sync(0xffffffffu, lsum0, 2);
    lsum1 += __shfl_xor_sync(0xffffffffu, lsum1, 1);
    lsum1 += __shfl_xor_sync(0xffffffffu, lsum1, 2);
    float inv0 = __fdividef(1.f, lsum0);
    float inv1 = __fdividef(1.f, lsum1);

    size_t row0 = (size_t)bt * SEQ + m0 + w * 16 + (lane >> 2);
    int colb = h * HD + 2 * (lane & 3);
#pragma unroll
    for (int nb = 0; nb < 8; nb++) {
        int col = colb + nb * 8;
        *(__half2*)(g_a + row0 * GDIM + col) =
            __floats2half2_rn(oacc[nb][0] * inv0, oacc[nb][1] * inv0);
        *(__half2*)(g_a + (row0 + 8) * GDIM + col) =
            __floats2half2_rn(oacc[nb][2] * inv1, oacc[nb][3] * inv1);
    }
}

// ---------------------------------------------------------------------------
extern "C" void kernel_launch(void* const* d_in, const int* in_sizes, int n_in,
                              void* d_out, int out_size) {
    const float* x   = (const float*)d_in[0];
    const float* wq  = (const float*)d_in[1];
    const float* wk  = (const float*)d_in[2];
    const float* wv  = (const float*)d_in[3];
    const float* wo  = (const float*)d_in[4];
    const float* qnw = (const float*)d_in[5];
    const float* knw = (const float*)d_in[6];
    float* out = (float*)d_out;

    __half *xh, *whi, *wlo, *woh, *ah;
    float* qkv;
    cudaGetSymbolAddress((void**)&xh, g_x);
    cudaGetSymbolAddress((void**)&whi, g_whi);
    cudaGetSymbolAddress((void**)&wlo, g_wlo);
    cudaGetSymbolAddress((void**)&woh, g_wo);
    cudaGetSymbolAddress((void**)&ah, g_a);
    cudaGetSymbolAddress((void**)&qkv, g_qkv);

    cudaFuncSetAttribute((const void*)gemm_mma,
                         cudaFuncAttributeMaxDynamicSharedMemorySize, GEMM_SMEM);
    cudaFuncSetAttribute((const void*)gemm_mma1,
                         cudaFuncAttributeMaxDynamicSharedMemorySize, GEMM1_SMEM);
    cudaFuncSetAttribute((const void*)attn_mma,
                         cudaFuncAttributeMaxDynamicSharedMemorySize, ATT_SMEM);

    // 1) operand conversion
    conv_h<<<4224, 256>>>(x, xh, MROWS * GDIM / 8);
    split_w_qkv<<<768, 256>>>(wq, wk, wv);
    conv_h<<<512, 256>>>(wo, woh, GDIM * GDIM / 8);

    // 2) QKV projection (fp16 2-term, 4-stage)
    gemm_mma<<<dim3(QKV_N / 128, MROWS / 128), 256, GEMM_SMEM>>>(
        xh, whi, wlo, qkv, QKV_N);

    // 3) QKNorm + 2D RoPE + split into attention planes
    norm_rope_split<<<MROWS * 3, 256>>>(qnw, knw);

    // 4) tensor-core attention (QK bf16x3, PV fp16 2-term)
    attn_mma<<<dim3(3, NH, BTN), 192, ATT_SMEM>>>();

    // 5) output projection (fp16 single-plane)
    gemm_mma1<<<dim3(GDIM / 128, MROWS / 128), 256, GEMM1_SMEM>>>(
        ah, woh, out, GDIM);
}

// round 12
// speedup vs baseline: 2.5693x; 1.2263x over previous
#include <cuda_runtime.h>
#include <cuda_bf16.h>
#include <cuda_fp16.h>
#include <stdint.h>
#include <math.h>

// Problem constants
#define BTN   64
#define SEQ   264
#define MROWS (BTN*SEQ)      // 16896
#define GDIM  1024
#define NH    16
#define NKV   4
#define HD    64
#define QKV_N 1536
#define NZ    256

// GEMM tiling: block 128x128, BK=32, 8 warps, 4-stage, 2 CTA/SM, single fp16
#define BK    32
#define KT    (GDIM/BK)      // 32
#define PLANE_B 8192         // 128x32 fp16
#define NSTG  4
#define STAGE1_B (2*PLANE_B)        // A + B
#define GEMM1_SMEM (NSTG*STAGE1_B)  // 65536

// Attention smem: chunked K/V (144-key buffer) + Q planes; 2 CTA/SM
#define LDP   144
#define CH_ROWS 144
#define SM_KHI 0
#define SM_KLO (CH_ROWS*LDP)
#define SM_VHI (2*CH_ROWS*LDP)
#define SM_VLO (3*CH_ROWS*LDP)
#define SM_QHI (4*CH_ROWS*LDP)
#define SM_QLO (SM_QHI + 96*LDP)
#define ATT_SMEM (SM_QLO + 96*LDP) // 110592

// ---------------------------------------------------------------------------
// device scratch
// ---------------------------------------------------------------------------
__device__ __align__(16) __half g_x[(size_t)MROWS * GDIM];       // A of QKV gemm
__device__ __align__(16) __half g_wqkv[(size_t)QKV_N * GDIM];    // B of QKV
__device__ __align__(16) __half g_wo[(size_t)GDIM * GDIM];       // B of O
__device__ __align__(16) __half g_a[(size_t)MROWS * GDIM];       // A of O gemm
__device__ __align__(16) float  g_qkv[(size_t)MROWS * QKV_N];
// attention operand planes: q,k bf16 hi/lo; v fp16 hi/lo
__device__ __align__(16) __nv_bfloat16 g_kphi[(size_t)BTN * NKV * SEQ * HD];
__device__ __align__(16) __nv_bfloat16 g_kplo[(size_t)BTN * NKV * SEQ * HD];
__device__ __align__(16) __half        g_vphi[(size_t)BTN * NKV * SEQ * HD];
__device__ __align__(16) __half        g_vplo[(size_t)BTN * NKV * SEQ * HD];
__device__ __align__(16) __nv_bfloat16 g_qphi[(size_t)BTN * NH * SEQ * HD];
__device__ __align__(16) __nv_bfloat16 g_qplo[(size_t)BTN * NH * SEQ * HD];

// ---------------------------------------------------------------------------
// helpers
// ---------------------------------------------------------------------------
__device__ __forceinline__ uint32_t smem_u32(const void* p) {
    uint32_t a;
    asm("{ .reg .u64 t; cvta.to.shared.u64 t, %1; cvt.u32.u64 %0, t; }"
        : "=r"(a) : "l"(p));
    return a;
}
__device__ __forceinline__ void cp16(uint32_t dst, const void* src) {
    asm volatile("cp.async.cg.shared.global [%0], [%1], 16;" :: "r"(dst), "l"(src));
}
#define CP_COMMIT() asm volatile("cp.async.commit_group;" ::: "memory")
#define CP_WAIT(n)  asm volatile("cp.async.wait_group %0;" :: "n"(n) : "memory")

__device__ __forceinline__ void ldsm4(uint32_t* r, uint32_t addr) {
    asm volatile("ldmatrix.sync.aligned.m8n8.x4.shared.b16 {%0,%1,%2,%3}, [%4];"
                 : "=r"(r[0]), "=r"(r[1]), "=r"(r[2]), "=r"(r[3]) : "r"(addr));
}
__device__ __forceinline__ void ldsm4t(uint32_t* r, uint32_t addr) {
    asm volatile("ldmatrix.sync.aligned.m8n8.x4.trans.shared.b16 {%0,%1,%2,%3}, [%4];"
                 : "=r"(r[0]), "=r"(r[1]), "=r"(r[2]), "=r"(r[3]) : "r"(addr));
}
// bf16 mma (attention QK)
__device__ __forceinline__ void mma16816(float* c, const uint32_t* a, const uint32_t* b) {
    asm volatile(
        "mma.sync.aligned.m16n8k16.row.col.f32.bf16.bf16.f32 "
        "{%0,%1,%2,%3}, {%4,%5,%6,%7}, {%8,%9}, {%0,%1,%2,%3};"
        : "+f"(c[0]), "+f"(c[1]), "+f"(c[2]), "+f"(c[3])
        : "r"(a[0]), "r"(a[1]), "r"(a[2]), "r"(a[3]), "r"(b[0]), "r"(b[1]));
}
// fp16 mma (GEMMs + PV)
__device__ __forceinline__ void mma16816h(float* c, const uint32_t* a, const uint32_t* b) {
    asm volatile(
        "mma.sync.aligned.m16n8k16.row.col.f32.f16.f16.f32 "
        "{%0,%1,%2,%3}, {%4,%5,%6,%7}, {%8,%9}, {%0,%1,%2,%3};"
        : "+f"(c[0]), "+f"(c[1]), "+f"(c[2]), "+f"(c[3])
        : "r"(a[0]), "r"(a[1]), "r"(a[2]), "r"(a[3]), "r"(b[0]), "r"(b[1]));
}

__device__ __forceinline__ uint32_t swz(int r, int u) {
    return (uint32_t)(r * 64 + ((u ^ ((r >> 1) & 3)) << 4));
}

// split two floats -> hi bf16x2 + lo bf16x2
__device__ __forceinline__ void split2(float a, float b, uint32_t& h, uint32_t& l) {
    __nv_bfloat16 ha = __float2bfloat16(a);
    __nv_bfloat16 hb = __float2bfloat16(b);
    float ra = a - __bfloat162float(ha);
    float rb = b - __bfloat162float(hb);
    h = (uint32_t)__bfloat16_as_ushort(ha) | ((uint32_t)__bfloat16_as_ushort(hb) << 16);
    l = (uint32_t)__bfloat16_as_ushort(__float2bfloat16(ra)) |
        ((uint32_t)__bfloat16_as_ushort(__float2bfloat16(rb)) << 16);
}

// softcap+exp on |s|<=8: exp(50*tanh(s/50)) = exp(s)*exp(u)
__device__ __forceinline__ float softcap_exp(float s) {
    float s2 = s * s;
    float u = s * s2 * (-1.33333333e-4f + s2 * 2.13333333e-8f);
    float corr = 1.f + u * (1.f + 0.5f * u);
    return __expf(s) * corr;
}

// ---------------------------------------------------------------------------
// conversion kernels
// ---------------------------------------------------------------------------
__global__ void conv_h(const float* __restrict__ src, __half* __restrict__ dst, int nunits) {
    for (int i = blockIdx.x * blockDim.x + threadIdx.x; i < nunits;
         i += gridDim.x * blockDim.x) {
        const float4 f0 = *(const float4*)(src + (size_t)i * 8);
        const float4 f1 = *(const float4*)(src + (size_t)i * 8 + 4);
        __half2 h[4];
        h[0] = __floats2half2_rn(f0.x, f0.y);
        h[1] = __floats2half2_rn(f0.z, f0.w);
        h[2] = __floats2half2_rn(f1.x, f1.y);
        h[3] = __floats2half2_rn(f1.z, f1.w);
        ((uint4*)dst)[i] = *(uint4*)h;
    }
}

// pack wq/wk/wv into one fp16 buffer (1536 x 1024)
__global__ void pack_w_qkv(const float* __restrict__ wq, const float* __restrict__ wk,
                           const float* __restrict__ wv) {
    int nunits = QKV_N * (GDIM / 8);
    for (int i = blockIdx.x * blockDim.x + threadIdx.x; i < nunits;
         i += gridDim.x * blockDim.x) {
        int row = i >> 7, ur = i & 127;
        const float* srow;
        if (row < NH * HD)                srow = wq + (size_t)row * GDIM;
        else if (row < NH*HD + NKV*HD)    srow = wk + (size_t)(row - NH*HD) * GDIM;
        else                              srow = wv + (size_t)(row - NH*HD - NKV*HD) * GDIM;
        const float4 f0 = *(const float4*)(srow + ur * 8);
        const float4 f1 = *(const float4*)(srow + ur * 8 + 4);
        __half2 h[4];
        h[0] = __floats2half2_rn(f0.x, f0.y);
        h[1] = __floats2half2_rn(f0.z, f0.w);
        h[2] = __floats2half2_rn(f1.x, f1.y);
        h[3] = __floats2half2_rn(f1.z, f1.w);
        ((uint4*)g_wqkv)[i] = *(uint4*)h;
    }
}

// ---------------------------------------------------------------------------
// fp16 single-plane GEMM: out = A*B^T, 128x128 tile, 4-stage, 2 CTA/SM
// ---------------------------------------------------------------------------
__device__ __forceinline__ void load_stage1(uint32_t sb, int stage,
        const __half* __restrict__ A, const __half* __restrict__ B,
        int bm, int bn, int kc, int tid) {
    uint32_t st = sb + stage * STAGE1_B;
#pragma unroll
    for (int i = 0; i < 4; i++) {
        int v = i * 256 + tid;
        int op = v >> 9;          // 0:A 1:B
        int w = v & 511;
        int r = w >> 2, u = w & 3;
        const __half* base = (op == 0) ? A : B;
        int grow = ((op == 0) ? bm : bn) * 128 + r;
        const __half* g = base + (size_t)grow * GDIM + kc * BK + u * 8;
        cp16(st + op * PLANE_B + swz(r, u), g);
    }
}

__global__ __launch_bounds__(256, 2)
void gemm_mma1(const __half* __restrict__ A, const __half* __restrict__ B,
               float* __restrict__ out, int ldc) {
    extern __shared__ __align__(1024) char smem[];
    uint32_t sb = smem_u32(smem);
    int tid = threadIdx.x, wid = tid >> 5, lane = tid & 31;
    int bm = blockIdx.y, bn = blockIdx.x;
    int wm = wid >> 2;
    int wn = wid & 3;

    float acc[4][4][4];
#pragma unroll
    for (int a = 0; a < 4; a++)
#pragma unroll
        for (int b = 0; b < 4; b++)
#pragma unroll
            for (int c = 0; c < 4; c++) acc[a][b][c] = 0.f;

    load_stage1(sb, 0, A, B, bm, bn, 0, tid); CP_COMMIT();
    load_stage1(sb, 1, A, B, bm, bn, 1, tid); CP_COMMIT();
    load_stage1(sb, 2, A, B, bm, bn, 2, tid); CP_COMMIT();

    for (int kc = 0; kc < KT; kc++) {
        CP_WAIT(2);
        __syncthreads();
        if (kc + 3 < KT)
            load_stage1(sb, (kc + 3) % NSTG, A, B, bm, bn, kc + 3, tid);
        CP_COMMIT();

        uint32_t st = sb + (kc % NSTG) * STAGE1_B;
#pragma unroll
        for (int ks = 0; ks < 2; ks++) {
            uint32_t af[4][4], bf[4][2];
#pragma unroll
            for (int mt = 0; mt < 4; mt++) {
                int r = wm * 64 + mt * 16 + (lane & 15);
                int u = 2 * ks + (lane >> 4);
                ldsm4(af[mt], st + swz(r, u));
            }
#pragma unroll
            for (int np = 0; np < 2; np++) {
                int r = wn * 32 + np * 16 + (lane & 7) + ((lane >> 4) & 1) * 8;
                int u = 2 * ks + ((lane >> 3) & 1);
                uint32_t t[4];
                ldsm4(t, st + PLANE_B + swz(r, u));
                bf[np*2][0] = t[0]; bf[np*2][1] = t[1];
                bf[np*2+1][0] = t[2]; bf[np*2+1][1] = t[3];
            }
#pragma unroll
            for (int mt = 0; mt < 4; mt++)
#pragma unroll
                for (int nt = 0; nt < 4; nt++) mma16816h(acc[mt][nt], af[mt], bf[nt]);
        }
    }

#pragma unroll
    for (int mt = 0; mt < 4; mt++)
#pragma unroll
        for (int nt = 0; nt < 4; nt++) {
            float* c = acc[mt][nt];
            int row = bm * 128 + wm * 64 + mt * 16 + (lane >> 2);
            int col = bn * 128 + wn * 32 + nt * 8 + 2 * (lane & 3);
            *(float2*)(out + (size_t)row * ldc + col) = make_float2(c[0], c[1]);
            *(float2*)(out + (size_t)(row + 8) * ldc + col) = make_float2(c[2], c[3]);
        }
}

// ---------------------------------------------------------------------------
// QKNorm + partial 2D RoPE + split to attn operand planes
// q,k -> bf16 hi/lo; v -> fp16 hi/lo
// ---------------------------------------------------------------------------
__global__ __launch_bounds__(256)
void norm_rope_split(const float* __restrict__ qw, const float* __restrict__ kw) {
    int vec = blockIdx.x * 8 + (threadIdx.x >> 5);
    int lane = threadIdx.x & 31;
    int hh = vec % 24;
    int row = vec / 24;
    int bt = row / SEQ, s = row - bt * SEQ;

    if (hh >= NH + NKV) {
        const float* p = g_qkv + (size_t)row * QKV_N + GDIM + NKV * HD + (hh - NH - NKV) * HD;
        size_t o = ((size_t)(bt * NKV + (hh - NH - NKV)) * SEQ + s) * HD;
        float v0 = p[lane], v1 = p[lane + 32];
        __half h0 = __float2half_rn(v0);
        __half h1 = __float2half_rn(v1);
        g_vphi[o + lane] = h0;
        g_vphi[o + lane + 32] = h1;
        g_vplo[o + lane] = __float2half_rn(v0 - __half2float(h0));
        g_vplo[o + lane + 32] = __float2half_rn(v1 - __half2float(h1));
        return;
    }

    const float* p;
    __nv_bfloat16 *hip, *lop;
    if (hh < NH) {
        p = g_qkv + (size_t)row * QKV_N + hh * HD;
        size_t o = ((size_t)(bt * NH + hh) * SEQ + s) * HD;
        hip = g_qphi + o; lop = g_qplo + o;
    } else {
        p = g_qkv + (size_t)row * QKV_N + GDIM + (hh - NH) * HD;
        size_t o = ((size_t)(bt * NKV + (hh - NH)) * SEQ + s) * HD;
        hip = g_kphi + o; lop = g_kplo + o;
    }
    float v0 = p[lane], v1 = p[lane + 32];

    float sq = v0 * v0 + v1 * v1;
#pragma unroll
    for (int o = 16; o; o >>= 1) sq += __shfl_xor_sync(0xffffffffu, sq, o);
    float scl = rsqrtf(sq * (1.0f / HD) + 1e-6f);
    const float* wv = (hh < NH) ? qw : kw;
    v0 *= scl * wv[lane];
    v1 *= scl * wv[lane + 32];
    if (s < NZ) {
        int j = lane & 15;
        float pos = (lane < 16) ? (float)(s >> 4) : (float)(s & 15);
        float invf = __expf(-(float)j * 0.57564627324851142f);
        float c, sn;
        sincosf(pos * invf, &sn, &c);
        float o0 = v0 * c - v1 * sn;
        float o1 = v1 * c + v0 * sn;
        v0 = o0; v1 = o1;
    }
    __nv_bfloat16 h0 = __float2bfloat16(v0);
    __nv_bfloat16 h1 = __float2bfloat16(v1);
    hip[lane] = h0;
    hip[lane + 32] = h1;
    lop[lane] = __float2bfloat16(v0 - __bfloat162float(h0));
    lop[lane + 32] = __float2bfloat16(v1 - __bfloat162float(h1));
}

// ---------------------------------------------------------------------------
// Flash-style mma attention: QK bf16x3, PV fp16 2-term (p single fp16)
// ---------------------------------------------------------------------------
__device__ __forceinline__ void attn_step(uint32_t sb, int lr0, bool last,
        const uint32_t qh[4][4], const uint32_t ql[4][4],
        float oacc[8][4], float& lsum0, float& lsum1,
        int krow, int ku, int vrow, int vu) {
    float sA0[4] = {0,0,0,0}, sA1[4] = {0,0,0,0};
    float sB0[4] = {0,0,0,0}, sB1[4] = {0,0,0,0};
    float sC0[4] = {0,0,0,0}, sC1[4] = {0,0,0,0};
#pragma unroll
    for (int kc = 0; kc < 4; kc++) {
        uint32_t off = (uint32_t)((lr0 + krow) * LDP + (2 * kc + ku) * 16);
        uint32_t bh[4], bl[4];
        ldsm4(bh, sb + SM_KHI + off);
        ldsm4(bl, sb + SM_KLO + off);
        mma16816(sA0, qh[kc], bh);
        mma16816(sA1, qh[kc], bh + 2);
        mma16816(sB0, qh[kc], bl);
        mma16816(sB1, qh[kc], bl + 2);
        mma16816(sC0, ql[kc], bh);
        mma16816(sC1, ql[kc], bh + 2);
    }
    float pf[2][4];
#pragma unroll
    for (int e = 0; e < 4; e++) {
        pf[0][e] = softcap_exp((sA0[e] + sB0[e] + sC0[e]) * 0.125f);
        pf[1][e] = softcap_exp((sA1[e] + sB1[e] + sC1[e]) * 0.125f);
    }
    if (last) { pf[1][0] = pf[1][1] = pf[1][2] = pf[1][3] = 0.f; }
    lsum0 += pf[0][0] + pf[0][1] + pf[1][0] + pf[1][1];
    lsum1 += pf[0][2] + pf[0][3] + pf[1][2] + pf[1][3];

    uint32_t ph[4];
    __half2 p0 = __floats2half2_rn(pf[0][0], pf[0][1]);
    __half2 p1 = __floats2half2_rn(pf[0][2], pf[0][3]);
    __half2 p2 = __floats2half2_rn(pf[1][0], pf[1][1]);
    __half2 p3 = __floats2half2_rn(pf[1][2], pf[1][3]);
    ph[0] = *(uint32_t*)&p0; ph[1] = *(uint32_t*)&p1;
    ph[2] = *(uint32_t*)&p2; ph[3] = *(uint32_t*)&p3;

    uint32_t vh[4][4], vl[4][4];
#pragma unroll
    for (int db = 0; db < 4; db++) {
        uint32_t off = (uint32_t)((lr0 + vrow) * LDP + (2 * db + vu) * 16);
        ldsm4t(vh[db], sb + SM_VHI + off);
        ldsm4t(vl[db], sb + SM_VLO + off);
    }
#pragma unroll
    for (int db = 0; db < 4; db++) {
        mma16816h(oacc[2*db],   ph, vh[db]);
        mma16816h(oacc[2*db+1], ph, vh[db] + 2);
    }
#pragma unroll
    for (int db = 0; db < 4; db++) {
        mma16816h(oacc[2*db],   ph, vl[db]);
        mma16816h(oacc[2*db+1], ph, vl[db] + 2);
    }
}

__global__ __launch_bounds__(192, 2) void attn_mma() {
    extern __shared__ __align__(1024) char smem[];
    const int tid = threadIdx.x;
    const int mt = blockIdx.x, h = blockIdx.y, bt = blockIdx.z;
    const int m0 = (mt == 0) ? 0 : (mt == 1 ? 96 : 168);
    const int kvh = h >> 2;
    const uint32_t sb = smem_u32(smem);

    size_t kvo = (size_t)(bt * NKV + kvh) * SEQ * HD;
    const __nv_bfloat16* kh_g = g_kphi + kvo;
    const __nv_bfloat16* kl_g = g_kplo + kvo;
    const __half* vh_g = g_vphi + kvo;
    const __half* vl_g = g_vplo + kvo;

    // ---- phase 0: async load Q + chunk A (keys 0..143) ----
    for (int idx = tid; idx < CH_ROWS * 8; idx += 192) {
        int r = idx >> 3, u = idx & 7;
        uint32_t doff = (uint32_t)(r * LDP + u * 16);
        int soff = r * HD + u * 8;
        cp16(sb + SM_KHI + doff, kh_g + soff);
        cp16(sb + SM_KLO + doff, kl_g + soff);
        cp16(sb + SM_VHI + doff, vh_g + soff);
        cp16(sb + SM_VLO + doff, vl_g + soff);
    }
    {
        size_t qo = ((size_t)(bt * NH + h) * SEQ + m0) * HD;
        const __nv_bfloat16* qh_g = g_qphi + qo;
        const __nv_bfloat16* ql_g = g_qplo + qo;
        for (int idx = tid; idx < 96 * 8; idx += 192) {
            int r = idx >> 3, u = idx & 7;
            uint32_t doff = (uint32_t)(r * LDP + u * 16);
            int soff = r * HD + u * 8;
            cp16(sb + SM_QHI + doff, qh_g + soff);
            cp16(sb + SM_QLO + doff, ql_g + soff);
        }
    }
    CP_COMMIT();
    CP_WAIT(0);
    __syncthreads();

    const int w = tid >> 5, lane = tid & 31;

    uint32_t qh[4][4], ql[4][4];
    {
        int r = w * 16 + (lane & 15);
        int uo = lane >> 4;
#pragma unroll
        for (int kc = 0; kc < 4; kc++) {
            uint32_t off = (uint32_t)(r * LDP + (2 * kc + uo) * 16);
            ldsm4(qh[kc], sb + SM_QHI + off);
            ldsm4(ql[kc], sb + SM_QLO + off);
        }
    }

    float oacc[8][4];
#pragma unroll
    for (int i = 0; i < 8; i++)
#pragma unroll
        for (int j = 0; j < 4; j++) oacc[i][j] = 0.f;
    float lsum0 = 0.f, lsum1 = 0.f;

    const int krow = (lane & 7) + ((lane >> 4) & 1) * 8;
    const int ku = (lane >> 3) & 1;
    const int vrow = (lane & 7) + ((lane >> 3) & 1) * 8;
    const int vu = (lane >> 4) & 1;

    for (int np = 0; np < 9; np++)
        attn_step(sb, np * 16, false, qh, ql, oacc, lsum0, lsum1, krow, ku, vrow, vu);

    __syncthreads();

    // ---- phase 1: load chunk B (keys 144..263; pad 120..127) ----
    for (int idx = tid; idx < 120 * 8; idx += 192) {
        int r = idx >> 3, u = idx & 7;
        uint32_t doff = (uint32_t)(r * LDP + u * 16);
        int soff = (144 + r) * HD + u * 8;
        cp16(sb + SM_KHI + doff, kh_g + soff);
        cp16(sb + SM_KLO + doff, kl_g + soff);
        cp16(sb + SM_VHI + doff, vh_g + soff);
        cp16(sb + SM_VLO + doff, vl_g + soff);
    }
    for (int idx = tid; idx < 8 * 32; idx += 192) {
        int off = (120 + (idx >> 5)) * LDP + (idx & 31) * 4;
        *(uint32_t*)(smem + SM_KHI + off) = 0;
        *(uint32_t*)(smem + SM_KLO + off) = 0;
        *(uint32_t*)(smem + SM_VHI + off) = 0;
        *(uint32_t*)(smem + SM_VLO + off) = 0;
    }
    CP_COMMIT();
    CP_WAIT(0);
    __syncthreads();

    for (int np = 0; np < 8; np++)
        attn_step(sb, np * 16, np == 7, qh, ql, oacc, lsum0, lsum1, krow, ku, vrow, vu);

    // ---- normalize + write single fp16 plane for O gemm ----
    lsum0 += __shfl_xor_sync(0xffffffffu, lsum0, 1);
    lsum0 += __shfl_xor_sync(0xffffffffu, lsum0, 2);
    lsum1 += __shfl_xor_sync(0xffffffffu, lsum1, 1);
    lsum1 += __shfl_xor_sync(0xffffffffu, lsum1, 2);
    float inv0 = __fdividef(1.f, lsum0);
    float inv1 = __fdividef(1.f, lsum1);

    size_t row0 = (size_t)bt * SEQ + m0 + w * 16 + (lane >> 2);
    int colb = h * HD + 2 * (lane & 3);
#pragma unroll
    for (int nb = 0; nb < 8; nb++) {
        int col = colb + nb * 8;
        *(__half2*)(g_a + row0 * GDIM + col) =
            __floats2half2_rn(oacc[nb][0] * inv0, oacc[nb][1] * inv0);
        *(__half2*)(g_a + (row0 + 8) * GDIM + col) =
            __floats2half2_rn(oacc[nb][2] * inv1, oacc[nb][3] * inv1);
    }
}

// ---------------------------------------------------------------------------
extern "C" void kernel_launch(void* const* d_in, const int* in_sizes, int n_in,
                              void* d_out, int out_size) {
    const float* x   = (const float*)d_in[0];
    const float* wq  = (const float*)d_in[1];
    const float* wk  = (const float*)d_in[2];
    const float* wv  = (const float*)d_in[3];
    const float* wo  = (const float*)d_in[4];
    const float* qnw = (const float*)d_in[5];
    const float* knw = (const float*)d_in[6];
    float* out = (float*)d_out;

    __half *xh, *wqkvh, *woh, *ah;
    float* qkv;
    cudaGetSymbolAddress((void**)&xh, g_x);
    cudaGetSymbolAddress((void**)&wqkvh, g_wqkv);
    cudaGetSymbolAddress((void**)&woh, g_wo);
    cudaGetSymbolAddress((void**)&ah, g_a);
    cudaGetSymbolAddress((void**)&qkv, g_qkv);

    cudaFuncSetAttribute((const void*)gemm_mma1,
                         cudaFuncAttributeMaxDynamicSharedMemorySize, GEMM1_SMEM);
    cudaFuncSetAttribute((const void*)attn_mma,
                         cudaFuncAttributeMaxDynamicSharedMemorySize, ATT_SMEM);

    // 1) operand conversion (all single fp16)
    conv_h<<<4224, 256>>>(x, xh, MROWS * GDIM / 8);
    pack_w_qkv<<<768, 256>>>(wq, wk, wv);
    conv_h<<<512, 256>>>(wo, woh, GDIM * GDIM / 8);

    // 2) QKV projection (fp16 single-plane)
    gemm_mma1<<<dim3(QKV_N / 128, MROWS / 128), 256, GEMM1_SMEM>>>(
        xh, wqkvh, qkv, QKV_N);

    // 3) QKNorm + 2D RoPE + split into attention planes
    norm_rope_split<<<MROWS * 3, 256>>>(qnw, knw);

    // 4) tensor-core attention (QK bf16x3, PV fp16 2-term)
    attn_mma<<<dim3(3, NH, BTN), 192, ATT_SMEM>>>();

    // 5) output projection (fp16 single-plane)
    gemm_mma1<<<dim3(GDIM / 128, MROWS / 128), 256, GEMM1_SMEM>>>(
        ah, woh, out, GDIM);
}

// round 13
// speedup vs baseline: 2.8480x; 1.1085x over previous
#include <cuda_runtime.h>
#include <cuda_bf16.h>
#include <cuda_fp16.h>
#include <stdint.h>
#include <math.h>

// Problem constants
#define BTN   64
#define SEQ   264
#define MROWS (BTN*SEQ)      // 16896
#define GDIM  1024
#define NH    16
#define NKV   4
#define HD    64
#define QKV_N 1536
#define NZ    256

// GEMM tiling: block 128x128, BK=64, 8 warps, 3-stage, 2 CTA/SM, single fp16
#define BK    64
#define KT    (GDIM/BK)      // 16
#define PLANE_B 16384        // 128x64 fp16 (128B rows)
#define NSTG  3
#define STAGE1_B (2*PLANE_B)        // A + B = 32768
#define GEMM1_SMEM (NSTG*STAGE1_B)  // 98304

// Attention smem: chunked K/V (144-key buffer) + single Q plane; 2 CTA/SM
#define LDP   144
#define CH_ROWS 144
#define SM_KHI 0
#define SM_KLO (CH_ROWS*LDP)
#define SM_VHI (2*CH_ROWS*LDP)
#define SM_VLO (3*CH_ROWS*LDP)
#define SM_QHI (4*CH_ROWS*LDP)
#define ATT_SMEM (SM_QHI + 96*LDP) // 96768

// ---------------------------------------------------------------------------
// device scratch
// ---------------------------------------------------------------------------
__device__ __align__(16) __half g_x[(size_t)MROWS * GDIM];       // A of QKV gemm
__device__ __align__(16) __half g_wqkv[(size_t)QKV_N * GDIM];    // B of QKV
__device__ __align__(16) __half g_wo[(size_t)GDIM * GDIM];       // B of O
__device__ __align__(16) __half g_a[(size_t)MROWS * GDIM];       // A of O gemm
__device__ __align__(16) float  g_qkv[(size_t)MROWS * QKV_N];
// attention operand planes: q fp16 single; k,v fp16 hi/lo
__device__ __align__(16) __half g_kphi[(size_t)BTN * NKV * SEQ * HD];
__device__ __align__(16) __half g_kplo[(size_t)BTN * NKV * SEQ * HD];
__device__ __align__(16) __half g_vphi[(size_t)BTN * NKV * SEQ * HD];
__device__ __align__(16) __half g_vplo[(size_t)BTN * NKV * SEQ * HD];
__device__ __align__(16) __half g_qp[(size_t)BTN * NH * SEQ * HD];

// ---------------------------------------------------------------------------
// helpers
// ---------------------------------------------------------------------------
__device__ __forceinline__ uint32_t smem_u32(const void* p) {
    uint32_t a;
    asm("{ .reg .u64 t; cvta.to.shared.u64 t, %1; cvt.u32.u64 %0, t; }"
        : "=r"(a) : "l"(p));
    return a;
}
__device__ __forceinline__ void cp16(uint32_t dst, const void* src) {
    asm volatile("cp.async.cg.shared.global [%0], [%1], 16;" :: "r"(dst), "l"(src));
}
#define CP_COMMIT() asm volatile("cp.async.commit_group;" ::: "memory")
#define CP_WAIT(n)  asm volatile("cp.async.wait_group %0;" :: "n"(n) : "memory")

__device__ __forceinline__ void ldsm4(uint32_t* r, uint32_t addr) {
    asm volatile("ldmatrix.sync.aligned.m8n8.x4.shared.b16 {%0,%1,%2,%3}, [%4];"
                 : "=r"(r[0]), "=r"(r[1]), "=r"(r[2]), "=r"(r[3]) : "r"(addr));
}
__device__ __forceinline__ void ldsm4t(uint32_t* r, uint32_t addr) {
    asm volatile("ldmatrix.sync.aligned.m8n8.x4.trans.shared.b16 {%0,%1,%2,%3}, [%4];"
                 : "=r"(r[0]), "=r"(r[1]), "=r"(r[2]), "=r"(r[3]) : "r"(addr));
}
// fp16 mma
__device__ __forceinline__ void mma16816h(float* c, const uint32_t* a, const uint32_t* b) {
    asm volatile(
        "mma.sync.aligned.m16n8k16.row.col.f32.f16.f16.f32 "
        "{%0,%1,%2,%3}, {%4,%5,%6,%7}, {%8,%9}, {%0,%1,%2,%3};"
        : "+f"(c[0]), "+f"(c[1]), "+f"(c[2]), "+f"(c[3])
        : "r"(a[0]), "r"(a[1]), "r"(a[2]), "r"(a[3]), "r"(b[0]), "r"(b[1]));
}

// swizzled byte offset within a 128x64 fp16 plane (128B rows, 8 x 16B units)
__device__ __forceinline__ uint32_t swz(int r, int u) {
    return (uint32_t)(r * 128 + ((u ^ (r & 7)) << 4));
}

// softcap+exp on |s|<=8: exp(50*tanh(s/50)) = exp(s)*exp(u)
__device__ __forceinline__ float softcap_exp(float s) {
    float s2 = s * s;
    float u = s * s2 * (-1.33333333e-4f + s2 * 2.13333333e-8f);
    float corr = 1.f + u * (1.f + 0.5f * u);
    return __expf(s) * corr;
}

// ---------------------------------------------------------------------------
// conversion kernels
// ---------------------------------------------------------------------------
__global__ void conv_h(const float* __restrict__ src, __half* __restrict__ dst, int nunits) {
    for (int i = blockIdx.x * blockDim.x + threadIdx.x; i < nunits;
         i += gridDim.x * blockDim.x) {
        const float4 f0 = *(const float4*)(src + (size_t)i * 8);
        const float4 f1 = *(const float4*)(src + (size_t)i * 8 + 4);
        __half2 h[4];
        h[0] = __floats2half2_rn(f0.x, f0.y);
        h[1] = __floats2half2_rn(f0.z, f0.w);
        h[2] = __floats2half2_rn(f1.x, f1.y);
        h[3] = __floats2half2_rn(f1.z, f1.w);
        ((uint4*)dst)[i] = *(uint4*)h;
    }
}

__global__ void pack_w_qkv(const float* __restrict__ wq, const float* __restrict__ wk,
                           const float* __restrict__ wv) {
    int nunits = QKV_N * (GDIM / 8);
    for (int i = blockIdx.x * blockDim.x + threadIdx.x; i < nunits;
         i += gridDim.x * blockDim.x) {
        int row = i >> 7, ur = i & 127;
        const float* srow;
        if (row < NH * HD)                srow = wq + (size_t)row * GDIM;
        else if (row < NH*HD + NKV*HD)    srow = wk + (size_t)(row - NH*HD) * GDIM;
        else                              srow = wv + (size_t)(row - NH*HD - NKV*HD) * GDIM;
        const float4 f0 = *(const float4*)(srow + ur * 8);
        const float4 f1 = *(const float4*)(srow + ur * 8 + 4);
        __half2 h[4];
        h[0] = __floats2half2_rn(f0.x, f0.y);
        h[1] = __floats2half2_rn(f0.z, f0.w);
        h[2] = __floats2half2_rn(f1.x, f1.y);
        h[3] = __floats2half2_rn(f1.z, f1.w);
        ((uint4*)g_wqkv)[i] = *(uint4*)h;
    }
}

// ---------------------------------------------------------------------------
// fp16 single-plane GEMM: out = A*B^T, 128x128 tile, BK=64, 3-stage, 2 CTA/SM
// ---------------------------------------------------------------------------
__device__ __forceinline__ void load_stage1(uint32_t sb, int stage,
        const __half* __restrict__ A, const __half* __restrict__ B,
        int bm, int bn, int kc, int tid) {
    uint32_t st = sb + stage * STAGE1_B;
#pragma unroll
    for (int i = 0; i < 8; i++) {
        int v = i * 256 + tid;
        int op = v >> 10;         // 0:A 1:B
        int w = v & 1023;
        int r = w >> 3, u = w & 7;
        const __half* base = (op == 0) ? A : B;
        int grow = ((op == 0) ? bm : bn) * 128 + r;
        const __half* g = base + (size_t)grow * GDIM + kc * BK + u * 8;
        cp16(st + op * PLANE_B + swz(r, u), g);
    }
}

__global__ __launch_bounds__(256, 2)
void gemm_mma1(const __half* __restrict__ A, const __half* __restrict__ B,
               float* __restrict__ out, int ldc) {
    extern __shared__ __align__(1024) char smem[];
    uint32_t sb = smem_u32(smem);
    int tid = threadIdx.x, wid = tid >> 5, lane = tid & 31;
    int bm = blockIdx.y, bn = blockIdx.x;
    int wm = wid >> 2;
    int wn = wid & 3;

    float acc[4][4][4];
#pragma unroll
    for (int a = 0; a < 4; a++)
#pragma unroll
        for (int b = 0; b < 4; b++)
#pragma unroll
            for (int c = 0; c < 4; c++) acc[a][b][c] = 0.f;

    load_stage1(sb, 0, A, B, bm, bn, 0, tid); CP_COMMIT();
    load_stage1(sb, 1, A, B, bm, bn, 1, tid); CP_COMMIT();

    for (int kc = 0; kc < KT; kc++) {
        CP_WAIT(1);
        __syncthreads();
        if (kc + 2 < KT)
            load_stage1(sb, (kc + 2) % NSTG, A, B, bm, bn, kc + 2, tid);
        CP_COMMIT();

        uint32_t st = sb + (kc % NSTG) * STAGE1_B;
#pragma unroll
        for (int ks = 0; ks < 4; ks++) {
            uint32_t af[4][4], bf[4][2];
#pragma unroll
            for (int mt = 0; mt < 4; mt++) {
                int r = wm * 64 + mt * 16 + (lane & 15);
                int u = 2 * ks + (lane >> 4);
                ldsm4(af[mt], st + swz(r, u));
            }
#pragma unroll
            for (int np = 0; np < 2; np++) {
                int r = wn * 32 + np * 16 + (lane & 7) + ((lane >> 4) & 1) * 8;
                int u = 2 * ks + ((lane >> 3) & 1);
                uint32_t t[4];
                ldsm4(t, st + PLANE_B + swz(r, u));
                bf[np*2][0] = t[0]; bf[np*2][1] = t[1];
                bf[np*2+1][0] = t[2]; bf[np*2+1][1] = t[3];
            }
#pragma unroll
            for (int mt = 0; mt < 4; mt++)
#pragma unroll
                for (int nt = 0; nt < 4; nt++) mma16816h(acc[mt][nt], af[mt], bf[nt]);
        }
    }

#pragma unroll
    for (int mt = 0; mt < 4; mt++)
#pragma unroll
        for (int nt = 0; nt < 4; nt++) {
            float* c = acc[mt][nt];
            int row = bm * 128 + wm * 64 + mt * 16 + (lane >> 2);
            int col = bn * 128 + wn * 32 + nt * 8 + 2 * (lane & 3);
            *(float2*)(out + (size_t)row * ldc + col) = make_float2(c[0], c[1]);
            *(float2*)(out + (size_t)(row + 8) * ldc + col) = make_float2(c[2], c[3]);
        }
}

// ---------------------------------------------------------------------------
// QKNorm + partial 2D RoPE + split to attn operand planes
// q -> fp16 single; k,v -> fp16 hi/lo
// ---------------------------------------------------------------------------
__global__ __launch_bounds__(256)
void norm_rope_split(const float* __restrict__ qw, const float* __restrict__ kw) {
    int vec = blockIdx.x * 8 + (threadIdx.x >> 5);
    int lane = threadIdx.x & 31;
    int hh = vec % 24;
    int row = vec / 24;
    int bt = row / SEQ, s = row - bt * SEQ;

    if (hh >= NH + NKV) {
        // V: raw fp16 split
        const float* p = g_qkv + (size_t)row * QKV_N + GDIM + NKV * HD + (hh - NH - NKV) * HD;
        size_t o = ((size_t)(bt * NKV + (hh - NH - NKV)) * SEQ + s) * HD;
        float v0 = p[lane], v1 = p[lane + 32];
        __half h0 = __float2half_rn(v0);
        __half h1 = __float2half_rn(v1);
        g_vphi[o + lane] = h0;
        g_vphi[o + lane + 32] = h1;
        g_vplo[o + lane] = __float2half_rn(v0 - __half2float(h0));
        g_vplo[o + lane + 32] = __float2half_rn(v1 - __half2float(h1));
        return;
    }

    const float* p;
    bool is_q = hh < NH;
    size_t o;
    if (is_q) {
        p = g_qkv + (size_t)row * QKV_N + hh * HD;
        o = ((size_t)(bt * NH + hh) * SEQ + s) * HD;
    } else {
        p = g_qkv + (size_t)row * QKV_N + GDIM + (hh - NH) * HD;
        o = ((size_t)(bt * NKV + (hh - NH)) * SEQ + s) * HD;
    }
    float v0 = p[lane], v1 = p[lane + 32];

    float sq = v0 * v0 + v1 * v1;
#pragma unroll
    for (int of = 16; of; of >>= 1) sq += __shfl_xor_sync(0xffffffffu, sq, of);
    float scl = rsqrtf(sq * (1.0f / HD) + 1e-6f);
    const float* wv = is_q ? qw : kw;
    v0 *= scl * wv[lane];
    v1 *= scl * wv[lane + 32];
    if (s < NZ) {
        int j = lane & 15;
        float pos = (lane < 16) ? (float)(s >> 4) : (float)(s & 15);
        float invf = __expf(-(float)j * 0.57564627324851142f);
        float c, sn;
        sincosf(pos * invf, &sn, &c);
        float o0 = v0 * c - v1 * sn;
        float o1 = v1 * c + v0 * sn;
        v0 = o0; v1 = o1;
    }
    if (is_q) {
        g_qp[o + lane] = __float2half_rn(v0);
        g_qp[o + lane + 32] = __float2half_rn(v1);
    } else {
        __half h0 = __float2half_rn(v0);
        __half h1 = __float2half_rn(v1);
        g_kphi[o + lane] = h0;
        g_kphi[o + lane + 32] = h1;
        g_kplo[o + lane] = __float2half_rn(v0 - __half2float(h0));
        g_kplo[o + lane + 32] = __float2half_rn(v1 - __half2float(h1));
    }
}

// ---------------------------------------------------------------------------
// Flash-style mma attention: QK fp16 2-term, PV fp16 2-term (p single fp16)
// ---------------------------------------------------------------------------
__device__ __forceinline__ void attn_step(uint32_t sb, int lr0, bool last,
        const uint32_t qh[4][4],
        float oacc[8][4], float& lsum0, float& lsum1,
        int krow, int ku, int vrow, int vu) {
    float sA0[4] = {0,0,0,0}, sA1[4] = {0,0,0,0};
    float sB0[4] = {0,0,0,0}, sB1[4] = {0,0,0,0};
#pragma unroll
    for (int kc = 0; kc < 4; kc++) {
        uint32_t off = (uint32_t)((lr0 + krow) * LDP + (2 * kc + ku) * 16);
        uint32_t bh[4], bl[4];
        ldsm4(bh, sb + SM_KHI + off);
        ldsm4(bl, sb + SM_KLO + off);
        mma16816h(sA0, qh[kc], bh);
        mma16816h(sA1, qh[kc], bh + 2);
        mma16816h(sB0, qh[kc], bl);
        mma16816h(sB1, qh[kc], bl + 2);
    }
    float pf[2][4];
#pragma unroll
    for (int e = 0; e < 4; e++) {
        pf[0][e] = softcap_exp((sA0[e] + sB0[e]) * 0.125f);
        pf[1][e] = softcap_exp((sA1[e] + sB1[e]) * 0.125f);
    }
    if (last) { pf[1][0] = pf[1][1] = pf[1][2] = pf[1][3] = 0.f; }
    lsum0 += pf[0][0] + pf[0][1] + pf[1][0] + pf[1][1];
    lsum1 += pf[0][2] + pf[0][3] + pf[1][2] + pf[1][3];

    uint32_t ph[4];
    __half2 p0 = __floats2half2_rn(pf[0][0], pf[0][1]);
    __half2 p1 = __floats2half2_rn(pf[0][2], pf[0][3]);
    __half2 p2 = __floats2half2_rn(pf[1][0], pf[1][1]);
    __half2 p3 = __floats2half2_rn(pf[1][2], pf[1][3]);
    ph[0] = *(uint32_t*)&p0; ph[1] = *(uint32_t*)&p1;
    ph[2] = *(uint32_t*)&p2; ph[3] = *(uint32_t*)&p3;

    uint32_t vh[4][4], vl[4][4];
#pragma unroll
    for (int db = 0; db < 4; db++) {
        uint32_t off = (uint32_t)((lr0 + vrow) * LDP + (2 * db + vu) * 16);
        ldsm4t(vh[db], sb + SM_VHI + off);
        ldsm4t(vl[db], sb + SM_VLO + off);
    }
#pragma unroll
    for (int db = 0; db < 4; db++) {
        mma16816h(oacc[2*db],   ph, vh[db]);
        mma16816h(oacc[2*db+1], ph, vh[db] + 2);
    }
#pragma unroll
    for (int db = 0; db < 4; db++) {
        mma16816h(oacc[2*db],   ph, vl[db]);
        mma16816h(oacc[2*db+1], ph, vl[db] + 2);
    }
}

__global__ __launch_bounds__(192, 2) void attn_mma() {
    extern __shared__ __align__(1024) char smem[];
    const int tid = threadIdx.x;
    const int mt = blockIdx.x, h = blockIdx.y, bt = blockIdx.z;
    const int m0 = (mt == 0) ? 0 : (mt == 1 ? 96 : 168);
    const int kvh = h >> 2;
    const uint32_t sb = smem_u32(smem);

    size_t kvo = (size_t)(bt * NKV + kvh) * SEQ * HD;
    const __half* kh_g = g_kphi + kvo;
    const __half* kl_g = g_kplo + kvo;
    const __half* vh_g = g_vphi + kvo;
    const __half* vl_g = g_vplo + kvo;

    // ---- phase 0: async load Q + chunk A (keys 0..143) ----
    for (int idx = tid; idx < CH_ROWS * 8; idx += 192) {
        int r = idx >> 3, u = idx & 7;
        uint32_t doff = (uint32_t)(r * LDP + u * 16);
        int soff = r * HD + u * 8;
        cp16(sb + SM_KHI + doff, kh_g + soff);
        cp16(sb + SM_KLO + doff, kl_g + soff);
        cp16(sb + SM_VHI + doff, vh_g + soff);
        cp16(sb + SM_VLO + doff, vl_g + soff);
    }
    {
        size_t qo = ((size_t)(bt * NH + h) * SEQ + m0) * HD;
        const __half* qh_g = g_qp + qo;
        for (int idx = tid; idx < 96 * 8; idx += 192) {
            int r = idx >> 3, u = idx & 7;
            uint32_t doff = (uint32_t)(r * LDP + u * 16);
            cp16(sb + SM_QHI + doff, qh_g + r * HD + u * 8);
        }
    }
    CP_COMMIT();
    CP_WAIT(0);
    __syncthreads();

    const int w = tid >> 5, lane = tid & 31;

    uint32_t qh[4][4];
    {
        int r = w * 16 + (lane & 15);
        int uo = lane >> 4;
#pragma unroll
        for (int kc = 0; kc < 4; kc++) {
            uint32_t off = (uint32_t)(r * LDP + (2 * kc + uo) * 16);
            ldsm4(qh[kc], sb + SM_QHI + off);
        }
    }

    float oacc[8][4];
#pragma unroll
    for (int i = 0; i < 8; i++)
#pragma unroll
        for (int j = 0; j < 4; j++) oacc[i][j] = 0.f;
    float lsum0 = 0.f, lsum1 = 0.f;

    const int krow = (lane & 7) + ((lane >> 4) & 1) * 8;
    const int ku = (lane >> 3) & 1;
    const int vrow = (lane & 7) + ((lane >> 3) & 1) * 8;
    const int vu = (lane >> 4) & 1;

    for (int np = 0; np < 9; np++)
        attn_step(sb, np * 16, false, qh, oacc, lsum0, lsum1, krow, ku, vrow, vu);

    __syncthreads();

    // ---- phase 1: load chunk B (keys 144..263; pad 120..127) ----
    for (int idx = tid; idx < 120 * 8; idx += 192) {
        int r = idx >> 3, u = idx & 7;
        uint32_t doff = (uint32_t)(r * LDP + u * 16);
        int soff = (144 + r) * HD + u * 8;
        cp16(sb + SM_KHI + doff, kh_g + soff);
        cp16(sb + SM_KLO + doff, kl_g + soff);
        cp16(sb + SM_VHI + doff, vh_g + soff);
        cp16(sb + SM_VLO + doff, vl_g + soff);
    }
    for (int idx = tid; idx < 8 * 32; idx += 192) {
        int off = (120 + (idx >> 5)) * LDP + (idx & 31) * 4;
        *(uint32_t*)(smem + SM_KHI + off) = 0;
        *(uint32_t*)(smem + SM_KLO + off) = 0;
        *(uint32_t*)(smem + SM_VHI + off) = 0;
        *(uint32_t*)(smem + SM_VLO + off) = 0;
    }
    CP_COMMIT();
    CP_WAIT(0);
    __syncthreads();

    for (int np = 0; np < 8; np++)
        attn_step(sb, np * 16, np == 7, qh, oacc, lsum0, lsum1, krow, ku, vrow, vu);

    // ---- normalize + write single fp16 plane for O gemm ----
    lsum0 += __shfl_xor_sync(0xffffffffu, lsum0, 1);
    lsum0 += __shfl_xor_sync(0xffffffffu, lsum0, 2);
    lsum1 += __shfl_xor_sync(0xffffffffu, lsum1, 1);
    lsum1 += __shfl_xor_sync(0xffffffffu, lsum1, 2);
    float inv0 = __fdividef(1.f, lsum0);
    float inv1 = __fdividef(1.f, lsum1);

    size_t row0 = (size_t)bt * SEQ + m0 + w * 16 + (lane >> 2);
    int colb = h * HD + 2 * (lane & 3);
#pragma unroll
    for (int nb = 0; nb < 8; nb++) {
        int col = colb + nb * 8;
        *(__half2*)(g_a + row0 * GDIM + col) =
            __floats2half2_rn(oacc[nb][0] * inv0, oacc[nb][1] * inv0);
        *(__half2*)(g_a + (row0 + 8) * GDIM + col) =
            __floats2half2_rn(oacc[nb][2] * inv1, oacc[nb][3] * inv1);
    }
}

// ---------------------------------------------------------------------------
extern "C" void kernel_launch(void* const* d_in, const int* in_sizes, int n_in,
                              void* d_out, int out_size) {
    const float* x   = (const float*)d_in[0];
    const float* wq  = (const float*)d_in[1];
    const float* wk  = (const float*)d_in[2];
    const float* wv  = (const float*)d_in[3];
    const float* wo  = (const float*)d_in[4];
    const float* qnw = (const float*)d_in[5];
    const float* knw = (const float*)d_in[6];
    float* out = (float*)d_out;

    __half *xh, *wqkvh, *woh, *ah;
    float* qkv;
    cudaGetSymbolAddress((void**)&xh, g_x);
    cudaGetSymbolAddress((void**)&wqkvh, g_wqkv);
    cudaGetSymbolAddress((void**)&woh, g_wo);
    cudaGetSymbolAddress((void**)&ah, g_a);
    cudaGetSymbolAddress((void**)&qkv, g_qkv);

    cudaFuncSetAttribute((const void*)gemm_mma1,
                         cudaFuncAttributeMaxDynamicSharedMemorySize, GEMM1_SMEM);
    cudaFuncSetAttribute((const void*)attn_mma,
                         cudaFuncAttributeMaxDynamicSharedMemorySize, ATT_SMEM);

    // 1) operand conversion (all single fp16)
    conv_h<<<4224, 256>>>(x, xh, MROWS * GDIM / 8);
    pack_w_qkv<<<768, 256>>>(wq, wk, wv);
    conv_h<<<512, 256>>>(wo, woh, GDIM * GDIM / 8);

    // 2) QKV projection (fp16 single-plane, BK=64)
    gemm_mma1<<<dim3(QKV_N / 128, MROWS / 128), 256, GEMM1_SMEM>>>(
        xh, wqkvh, qkv, QKV_N);

    // 3) QKNorm + 2D RoPE + split into attention planes
    norm_rope_split<<<MROWS * 3, 256>>>(qnw, knw);

    // 4) tensor-core attention (QK fp16 2-term, PV fp16 2-term)
    attn_mma<<<dim3(3, NH, BTN), 192, ATT_SMEM>>>();

    // 5) output projection (fp16 single-plane, BK=64)
    gemm_mma1<<<dim3(GDIM / 128, MROWS / 128), 256, GEMM1_SMEM>>>(
        ah, woh, out, GDIM);
}

// round 14
// speedup vs baseline: 3.2427x; 1.1386x over previous
#include <cuda_runtime.h>
#include <cuda_bf16.h>
#include <cuda_fp16.h>
#include <stdint.h>
#include <math.h>

// Problem constants
#define BTN   64
#define SEQ   264
#define MROWS (BTN*SEQ)      // 16896
#define GDIM  1024
#define NH    16
#define NKV   4
#define HD    64
#define QKV_N 1536
#define NZ    256

// GEMM tiling: block 128x128, BK=64, 8 warps, 3-stage, 2 CTA/SM, single fp16
#define BK    64
#define KT    (GDIM/BK)      // 16
#define PLANE_B 16384        // 128x64 fp16 (128B rows)
#define NSTG  3
#define STAGE1_B (2*PLANE_B)        // A + B = 32768
#define GEMM1_SMEM (NSTG*STAGE1_B)  // 98304

// Attention smem: full-K/V single fp16 planes + Q; 2 CTA/SM
#define LDP   144
#define KPAD  272
#define SM_K  0
#define SM_V  (KPAD*LDP)            // 39168
#define SM_Q  (2*KPAD*LDP)          // 78336
#define ATT_SMEM (SM_Q + 96*LDP)    // 92160

// ---------------------------------------------------------------------------
// device scratch
// ---------------------------------------------------------------------------
__device__ __align__(16) __half g_x[(size_t)MROWS * GDIM];       // A of QKV gemm
__device__ __align__(16) __half g_wqkv[(size_t)QKV_N * GDIM];    // B of QKV
__device__ __align__(16) __half g_wo[(size_t)GDIM * GDIM];       // B of O
__device__ __align__(16) __half g_a[(size_t)MROWS * GDIM];       // A of O gemm
__device__ __align__(16) float  g_qkv[(size_t)MROWS * QKV_N];
// attention operand planes (all single fp16)
__device__ __align__(16) __half g_kp[(size_t)BTN * NKV * SEQ * HD];
__device__ __align__(16) __half g_vp[(size_t)BTN * NKV * SEQ * HD];
__device__ __align__(16) __half g_qp[(size_t)BTN * NH * SEQ * HD];

// ---------------------------------------------------------------------------
// helpers
// ---------------------------------------------------------------------------
__device__ __forceinline__ uint32_t smem_u32(const void* p) {
    uint32_t a;
    asm("{ .reg .u64 t; cvta.to.shared.u64 t, %1; cvt.u32.u64 %0, t; }"
        : "=r"(a) : "l"(p));
    return a;
}
__device__ __forceinline__ void cp16(uint32_t dst, const void* src) {
    asm volatile("cp.async.cg.shared.global [%0], [%1], 16;" :: "r"(dst), "l"(src));
}
#define CP_COMMIT() asm volatile("cp.async.commit_group;" ::: "memory")
#define CP_WAIT(n)  asm volatile("cp.async.wait_group %0;" :: "n"(n) : "memory")

__device__ __forceinline__ void ldsm4(uint32_t* r, uint32_t addr) {
    asm volatile("ldmatrix.sync.aligned.m8n8.x4.shared.b16 {%0,%1,%2,%3}, [%4];"
                 : "=r"(r[0]), "=r"(r[1]), "=r"(r[2]), "=r"(r[3]) : "r"(addr));
}
__device__ __forceinline__ void ldsm4t(uint32_t* r, uint32_t addr) {
    asm volatile("ldmatrix.sync.aligned.m8n8.x4.trans.shared.b16 {%0,%1,%2,%3}, [%4];"
                 : "=r"(r[0]), "=r"(r[1]), "=r"(r[2]), "=r"(r[3]) : "r"(addr));
}
__device__ __forceinline__ void mma16816h(float* c, const uint32_t* a, const uint32_t* b) {
    asm volatile(
        "mma.sync.aligned.m16n8k16.row.col.f32.f16.f16.f32 "
        "{%0,%1,%2,%3}, {%4,%5,%6,%7}, {%8,%9}, {%0,%1,%2,%3};"
        : "+f"(c[0]), "+f"(c[1]), "+f"(c[2]), "+f"(c[3])
        : "r"(a[0]), "r"(a[1]), "r"(a[2]), "r"(a[3]), "r"(b[0]), "r"(b[1]));
}

// swizzled byte offset within a 128x64 fp16 plane (128B rows, 8 x 16B units)
__device__ __forceinline__ uint32_t swz(int r, int u) {
    return (uint32_t)(r * 128 + ((u ^ (r & 7)) << 4));
}

// softcap+exp on |s|<=8: exp(50*tanh(s/50)) = exp(s)*exp(u)
__device__ __forceinline__ float softcap_exp(float s) {
    float s2 = s * s;
    float u = s * s2 * (-1.33333333e-4f + s2 * 2.13333333e-8f);
    float corr = 1.f + u * (1.f + 0.5f * u);
    return __expf(s) * corr;
}

// ---------------------------------------------------------------------------
// conversion kernels
// ---------------------------------------------------------------------------
__global__ void conv_h(const float* __restrict__ src, __half* __restrict__ dst, int nunits) {
    for (int i = blockIdx.x * blockDim.x + threadIdx.x; i < nunits;
         i += gridDim.x * blockDim.x) {
        const float4 f0 = *(const float4*)(src + (size_t)i * 8);
        const float4 f1 = *(const float4*)(src + (size_t)i * 8 + 4);
        __half2 h[4];
        h[0] = __floats2half2_rn(f0.x, f0.y);
        h[1] = __floats2half2_rn(f0.z, f0.w);
        h[2] = __floats2half2_rn(f1.x, f1.y);
        h[3] = __floats2half2_rn(f1.z, f1.w);
        ((uint4*)dst)[i] = *(uint4*)h;
    }
}

__global__ void pack_w_qkv(const float* __restrict__ wq, const float* __restrict__ wk,
                           const float* __restrict__ wv) {
    int nunits = QKV_N * (GDIM / 8);
    for (int i = blockIdx.x * blockDim.x + threadIdx.x; i < nunits;
         i += gridDim.x * blockDim.x) {
        int row = i >> 7, ur = i & 127;
        const float* srow;
        if (row < NH * HD)                srow = wq + (size_t)row * GDIM;
        else if (row < NH*HD + NKV*HD)    srow = wk + (size_t)(row - NH*HD) * GDIM;
        else                              srow = wv + (size_t)(row - NH*HD - NKV*HD) * GDIM;
        const float4 f0 = *(const float4*)(srow + ur * 8);
        const float4 f1 = *(const float4*)(srow + ur * 8 + 4);
        __half2 h[4];
        h[0] = __floats2half2_rn(f0.x, f0.y);
        h[1] = __floats2half2_rn(f0.z, f0.w);
        h[2] = __floats2half2_rn(f1.x, f1.y);
        h[3] = __floats2half2_rn(f1.z, f1.w);
        ((uint4*)g_wqkv)[i] = *(uint4*)h;
    }
}

// ---------------------------------------------------------------------------
// fp16 single-plane GEMM: out = A*B^T, 128x128 tile, BK=64, 3-stage, 2 CTA/SM
// ---------------------------------------------------------------------------
__device__ __forceinline__ void load_stage1(uint32_t sb, int stage,
        const __half* __restrict__ A, const __half* __restrict__ B,
        int bm, int bn, int kc, int tid) {
    uint32_t st = sb + stage * STAGE1_B;
#pragma unroll
    for (int i = 0; i < 8; i++) {
        int v = i * 256 + tid;
        int op = v >> 10;         // 0:A 1:B
        int w = v & 1023;
        int r = w >> 3, u = w & 7;
        const __half* base = (op == 0) ? A : B;
        int grow = ((op == 0) ? bm : bn) * 128 + r;
        const __half* g = base + (size_t)grow * GDIM + kc * BK + u * 8;
        cp16(st + op * PLANE_B + swz(r, u), g);
    }
}

__global__ __launch_bounds__(256, 2)
void gemm_mma1(const __half* __restrict__ A, const __half* __restrict__ B,
               float* __restrict__ out, int ldc) {
    extern __shared__ __align__(1024) char smem[];
    uint32_t sb = smem_u32(smem);
    int tid = threadIdx.x, wid = tid >> 5, lane = tid & 31;
    int bm = blockIdx.y, bn = blockIdx.x;
    int wm = wid >> 2;
    int wn = wid & 3;

    float acc[4][4][4];
#pragma unroll
    for (int a = 0; a < 4; a++)
#pragma unroll
        for (int b = 0; b < 4; b++)
#pragma unroll
            for (int c = 0; c < 4; c++) acc[a][b][c] = 0.f;

    load_stage1(sb, 0, A, B, bm, bn, 0, tid); CP_COMMIT();
    load_stage1(sb, 1, A, B, bm, bn, 1, tid); CP_COMMIT();

    for (int kc = 0; kc < KT; kc++) {
        CP_WAIT(1);
        __syncthreads();
        if (kc + 2 < KT)
            load_stage1(sb, (kc + 2) % NSTG, A, B, bm, bn, kc + 2, tid);
        CP_COMMIT();

        uint32_t st = sb + (kc % NSTG) * STAGE1_B;
#pragma unroll
        for (int ks = 0; ks < 4; ks++) {
            uint32_t af[4][4], bf[4][2];
#pragma unroll
            for (int mt = 0; mt < 4; mt++) {
                int r = wm * 64 + mt * 16 + (lane & 15);
                int u = 2 * ks + (lane >> 4);
                ldsm4(af[mt], st + swz(r, u));
            }
#pragma unroll
            for (int np = 0; np < 2; np++) {
                int r = wn * 32 + np * 16 + (lane & 7) + ((lane >> 4) & 1) * 8;
                int u = 2 * ks + ((lane >> 3) & 1);
                uint32_t t[4];
                ldsm4(t, st + PLANE_B + swz(r, u));
                bf[np*2][0] = t[0]; bf[np*2][1] = t[1];
                bf[np*2+1][0] = t[2]; bf[np*2+1][1] = t[3];
            }
#pragma unroll
            for (int mt = 0; mt < 4; mt++)
#pragma unroll
                for (int nt = 0; nt < 4; nt++) mma16816h(acc[mt][nt], af[mt], bf[nt]);
        }
    }

#pragma unroll
    for (int mt = 0; mt < 4; mt++)
#pragma unroll
        for (int nt = 0; nt < 4; nt++) {
            float* c = acc[mt][nt];
            int row = bm * 128 + wm * 64 + mt * 16 + (lane >> 2);
            int col = bn * 128 + wn * 32 + nt * 8 + 2 * (lane & 3);
            *(float2*)(out + (size_t)row * ldc + col) = make_float2(c[0], c[1]);
            *(float2*)(out + (size_t)(row + 8) * ldc + col) = make_float2(c[2], c[3]);
        }
}

// ---------------------------------------------------------------------------
// QKNorm + partial 2D RoPE + single-fp16 attn operand planes
// ---------------------------------------------------------------------------
__global__ __launch_bounds__(256)
void norm_rope_split(const float* __restrict__ qw, const float* __restrict__ kw) {
    int vec = blockIdx.x * 8 + (threadIdx.x >> 5);
    int lane = threadIdx.x & 31;
    int hh = vec % 24;
    int row = vec / 24;
    int bt = row / SEQ, s = row - bt * SEQ;

    if (hh >= NH + NKV) {
        // V: raw fp16
        const float* p = g_qkv + (size_t)row * QKV_N + GDIM + NKV * HD + (hh - NH - NKV) * HD;
        size_t o = ((size_t)(bt * NKV + (hh - NH - NKV)) * SEQ + s) * HD;
        g_vp[o + lane] = __float2half_rn(p[lane]);
        g_vp[o + lane + 32] = __float2half_rn(p[lane + 32]);
        return;
    }

    const float* p;
    bool is_q = hh < NH;
    size_t o;
    if (is_q) {
        p = g_qkv + (size_t)row * QKV_N + hh * HD;
        o = ((size_t)(bt * NH + hh) * SEQ + s) * HD;
    } else {
        p = g_qkv + (size_t)row * QKV_N + GDIM + (hh - NH) * HD;
        o = ((size_t)(bt * NKV + (hh - NH)) * SEQ + s) * HD;
    }
    float v0 = p[lane], v1 = p[lane + 32];

    float sq = v0 * v0 + v1 * v1;
#pragma unroll
    for (int of = 16; of; of >>= 1) sq += __shfl_xor_sync(0xffffffffu, sq, of);
    float scl = rsqrtf(sq * (1.0f / HD) + 1e-6f);
    const float* wv = is_q ? qw : kw;
    v0 *= scl * wv[lane];
    v1 *= scl * wv[lane + 32];
    if (s < NZ) {
        int j = lane & 15;
        float pos = (lane < 16) ? (float)(s >> 4) : (float)(s & 15);
        float invf = __expf(-(float)j * 0.57564627324851142f);
        float c, sn;
        sincosf(pos * invf, &sn, &c);
        float o0 = v0 * c - v1 * sn;
        float o1 = v1 * c + v0 * sn;
        v0 = o0; v1 = o1;
    }
    __half* dst = is_q ? g_qp : g_kp;
    dst[o + lane] = __float2half_rn(v0);
    dst[o + lane + 32] = __float2half_rn(v1);
}

// ---------------------------------------------------------------------------
// Flash-style mma attention: all single fp16, full KV resident, 2 CTA/SM
// ---------------------------------------------------------------------------
__global__ __launch_bounds__(192, 2) void attn_mma() {
    extern __shared__ __align__(1024) char smem[];
    const int tid = threadIdx.x;
    const int mt = blockIdx.x, h = blockIdx.y, bt = blockIdx.z;
    const int m0 = (mt == 0) ? 0 : (mt == 1 ? 96 : 168);
    const int kvh = h >> 2;
    const uint32_t sb = smem_u32(smem);

    size_t kvo = (size_t)(bt * NKV + kvh) * SEQ * HD;
    const __half* k_g = g_kp + kvo;
    const __half* v_g = g_vp + kvo;

    // ---- async load Q + full K/V ----
    for (int idx = tid; idx < SEQ * 8; idx += 192) {
        int r = idx >> 3, u = idx & 7;
        uint32_t doff = (uint32_t)(r * LDP + u * 16);
        int soff = r * HD + u * 8;
        cp16(sb + SM_K + doff, k_g + soff);
        cp16(sb + SM_V + doff, v_g + soff);
    }
    {
        size_t qo = ((size_t)(bt * NH + h) * SEQ + m0) * HD;
        const __half* q_g = g_qp + qo;
        for (int idx = tid; idx < 96 * 8; idx += 192) {
            int r = idx >> 3, u = idx & 7;
            cp16(sb + SM_Q + (uint32_t)(r * LDP + u * 16), q_g + r * HD + u * 8);
        }
    }
    // zero pad rows 264..271 (K and V)
    for (int idx = tid; idx < 8 * 36; idx += 192) {
        int off = (SEQ + idx / 36) * LDP + (idx % 36) * 4;
        *(uint32_t*)(smem + SM_K + off) = 0;
        *(uint32_t*)(smem + SM_V + off) = 0;
    }
    CP_COMMIT();
    CP_WAIT(0);
    __syncthreads();

    const int w = tid >> 5, lane = tid & 31;

    uint32_t qh[4][4];
    {
        int r = w * 16 + (lane & 15);
        int uo = lane >> 4;
#pragma unroll
        for (int kc = 0; kc < 4; kc++)
            ldsm4(qh[kc], sb + SM_Q + (uint32_t)(r * LDP + (2 * kc + uo) * 16));
    }

    float oacc[8][4];
#pragma unroll
    for (int i = 0; i < 8; i++)
#pragma unroll
        for (int j = 0; j < 4; j++) oacc[i][j] = 0.f;
    float lsum0 = 0.f, lsum1 = 0.f;

    const int krow = (lane & 7) + ((lane >> 4) & 1) * 8;
    const int ku = (lane >> 3) & 1;
    const int vrow = (lane & 7) + ((lane >> 3) & 1) * 8;
    const int vu = (lane >> 4) & 1;

    for (int np = 0; np < 17; np++) {
        // ---- S = Q K^T: 2 chains of 4 mmas ----
        float sA0[4] = {0,0,0,0}, sA1[4] = {0,0,0,0};
#pragma unroll
        for (int kc = 0; kc < 4; kc++) {
            uint32_t off = (uint32_t)((np * 16 + krow) * LDP + (2 * kc + ku) * 16);
            uint32_t bh[4];
            ldsm4(bh, sb + SM_K + off);
            mma16816h(sA0, qh[kc], bh);
            mma16816h(sA1, qh[kc], bh + 2);
        }
        float pf[2][4];
#pragma unroll
        for (int e = 0; e < 4; e++) {
            pf[0][e] = softcap_exp(sA0[e] * 0.125f);
            pf[1][e] = softcap_exp(sA1[e] * 0.125f);
        }
        if (np == 16) { pf[1][0] = pf[1][1] = pf[1][2] = pf[1][3] = 0.f; }
        lsum0 += pf[0][0] + pf[0][1] + pf[1][0] + pf[1][1];
        lsum1 += pf[0][2] + pf[0][3] + pf[1][2] + pf[1][3];

        uint32_t ph[4];
        __half2 p0 = __floats2half2_rn(pf[0][0], pf[0][1]);
        __half2 p1 = __floats2half2_rn(pf[0][2], pf[0][3]);
        __half2 p2 = __floats2half2_rn(pf[1][0], pf[1][1]);
        __half2 p3 = __floats2half2_rn(pf[1][2], pf[1][3]);
        ph[0] = *(uint32_t*)&p0; ph[1] = *(uint32_t*)&p1;
        ph[2] = *(uint32_t*)&p2; ph[3] = *(uint32_t*)&p3;

        // ---- O += P V: 8 independent mmas ----
        uint32_t vh[4][4];
#pragma unroll
        for (int db = 0; db < 4; db++) {
            uint32_t off = (uint32_t)((np * 16 + vrow) * LDP + (2 * db + vu) * 16);
            ldsm4t(vh[db], sb + SM_V + off);
        }
#pragma unroll
        for (int db = 0; db < 4; db++) {
            mma16816h(oacc[2*db],   ph, vh[db]);
            mma16816h(oacc[2*db+1], ph, vh[db] + 2);
        }
    }

    // ---- normalize + write single fp16 plane for O gemm ----
    lsum0 += __shfl_xor_sync(0xffffffffu, lsum0, 1);
    lsum0 += __shfl_xor_sync(0xffffffffu, lsum0, 2);
    lsum1 += __shfl_xor_sync(0xffffffffu, lsum1, 1);
    lsum1 += __shfl_xor_sync(0xffffffffu, lsum1, 2);
    float inv0 = __fdividef(1.f, lsum0);
    float inv1 = __fdividef(1.f, lsum1);

    size_t row0 = (size_t)bt * SEQ + m0 + w * 16 + (lane >> 2);
    int colb = h * HD + 2 * (lane & 3);
#pragma unroll
    for (int nb = 0; nb < 8; nb++) {
        int col = colb + nb * 8;
        *(__half2*)(g_a + row0 * GDIM + col) =
            __floats2half2_rn(oacc[nb][0] * inv0, oacc[nb][1] * inv0);
        *(__half2*)(g_a + (row0 + 8) * GDIM + col) =
            __floats2half2_rn(oacc[nb][2] * inv1, oacc[nb][3] * inv1);
    }
}

// ---------------------------------------------------------------------------
extern "C" void kernel_launch(void* const* d_in, const int* in_sizes, int n_in,
                              void* d_out, int out_size) {
    const float* x   = (const float*)d_in[0];
    const float* wq  = (const float*)d_in[1];
    const float* wk  = (const float*)d_in[2];
    const float* wv  = (const float*)d_in[3];
    const float* wo  = (const float*)d_in[4];
    const float* qnw = (const float*)d_in[5];
    const float* knw = (const float*)d_in[6];
    float* out = (float*)d_out;

    __half *xh, *wqkvh, *woh, *ah;
    float* qkv;
    cudaGetSymbolAddress((void**)&xh, g_x);
    cudaGetSymbolAddress((void**)&wqkvh, g_wqkv);
    cudaGetSymbolAddress((void**)&woh, g_wo);
    cudaGetSymbolAddress((void**)&ah, g_a);
    cudaGetSymbolAddress((void**)&qkv, g_qkv);

    cudaFuncSetAttribute((const void*)gemm_mma1,
                         cudaFuncAttributeMaxDynamicSharedMemorySize, GEMM1_SMEM);
    cudaFuncSetAttribute((const void*)attn_mma,
                         cudaFuncAttributeMaxDynamicSharedMemorySize, ATT_SMEM);

    // 1) operand conversion (all single fp16)
    conv_h<<<4224, 256>>>(x, xh, MROWS * GDIM / 8);
    pack_w_qkv<<<768, 256>>>(wq, wk, wv);
    conv_h<<<512, 256>>>(wo, woh, GDIM * GDIM / 8);

    // 2) QKV projection
    gemm_mma1<<<dim3(QKV_N / 128, MROWS / 128), 256, GEMM1_SMEM>>>(
        xh, wqkvh, qkv, QKV_N);

    // 3) QKNorm + 2D RoPE + attention planes
    norm_rope_split<<<MROWS * 3, 256>>>(qnw, knw);

    // 4) tensor-core attention (single fp16 operands, full KV resident)
    attn_mma<<<dim3(3, NH, BTN), 192, ATT_SMEM>>>();

    // 5) output projection
    gemm_mma1<<<dim3(GDIM / 128, MROWS / 128), 256, GEMM1_SMEM>>>(
        ah, woh, out, GDIM);
}

// round 15
// speedup vs baseline: 3.2599x; 1.0053x over previous
#include <cuda_runtime.h>
#include <cuda_bf16.h>
#include <cuda_fp16.h>
#include <stdint.h>
#include <math.h>

// Problem constants
#define BTN   64
#define SEQ   264
#define MROWS (BTN*SEQ)      // 16896
#define GDIM  1024
#define NH    16
#define NKV   4
#define HD    64
#define QKV_N 1536
#define NZ    256

// GEMM tiling: block 128x128, BK=64, 4 warps (warptile 64x64), 3-stage, 2 CTA/SM
#define BK    64
#define KT    (GDIM/BK)      // 16
#define PLANE_B 16384        // 128x64 fp16 (128B rows)
#define NSTG  3
#define STAGE1_B (2*PLANE_B)        // A + B = 32768
#define GEMM1_SMEM (NSTG*STAGE1_B)  // 98304

// Attention smem: full-K/V single fp16 planes + Q; 2 CTA/SM
#define LDP   144
#define KPAD  272
#define SM_K  0
#define SM_V  (KPAD*LDP)
#define SM_Q  (2*KPAD*LDP)
#define ATT_SMEM (SM_Q + 96*LDP)    // 92160

// ---------------------------------------------------------------------------
// device scratch
// ---------------------------------------------------------------------------
__device__ __align__(16) __half g_x[(size_t)MROWS * GDIM];       // A of QKV gemm
__device__ __align__(16) __half g_wqkv[(size_t)QKV_N * GDIM];    // B of QKV
__device__ __align__(16) __half g_wo[(size_t)GDIM * GDIM];       // B of O
__device__ __align__(16) __half g_a[(size_t)MROWS * GDIM];       // A of O gemm
__device__ __align__(16) __half g_qkvh[(size_t)MROWS * QKV_N];   // QKV out (fp16)
// attention operand planes (all single fp16)
__device__ __align__(16) __half g_kp[(size_t)BTN * NKV * SEQ * HD];
__device__ __align__(16) __half g_vp[(size_t)BTN * NKV * SEQ * HD];
__device__ __align__(16) __half g_qp[(size_t)BTN * NH * SEQ * HD];

// ---------------------------------------------------------------------------
// helpers
// ---------------------------------------------------------------------------
__device__ __forceinline__ uint32_t smem_u32(const void* p) {
    uint32_t a;
    asm("{ .reg .u64 t; cvta.to.shared.u64 t, %1; cvt.u32.u64 %0, t; }"
        : "=r"(a) : "l"(p));
    return a;
}
__device__ __forceinline__ void cp16(uint32_t dst, const void* src) {
    asm volatile("cp.async.cg.shared.global [%0], [%1], 16;" :: "r"(dst), "l"(src));
}
#define CP_COMMIT() asm volatile("cp.async.commit_group;" ::: "memory")
#define CP_WAIT(n)  asm volatile("cp.async.wait_group %0;" :: "n"(n) : "memory")

__device__ __forceinline__ void ldsm4(uint32_t* r, uint32_t addr) {
    asm volatile("ldmatrix.sync.aligned.m8n8.x4.shared.b16 {%0,%1,%2,%3}, [%4];"
                 : "=r"(r[0]), "=r"(r[1]), "=r"(r[2]), "=r"(r[3]) : "r"(addr));
}
__device__ __forceinline__ void ldsm4t(uint32_t* r, uint32_t addr) {
    asm volatile("ldmatrix.sync.aligned.m8n8.x4.trans.shared.b16 {%0,%1,%2,%3}, [%4];"
                 : "=r"(r[0]), "=r"(r[1]), "=r"(r[2]), "=r"(r[3]) : "r"(addr));
}
__device__ __forceinline__ void mma16816h(float* c, const uint32_t* a, const uint32_t* b) {
    asm volatile(
        "mma.sync.aligned.m16n8k16.row.col.f32.f16.f16.f32 "
        "{%0,%1,%2,%3}, {%4,%5,%6,%7}, {%8,%9}, {%0,%1,%2,%3};"
        : "+f"(c[0]), "+f"(c[1]), "+f"(c[2]), "+f"(c[3])
        : "r"(a[0]), "r"(a[1]), "r"(a[2]), "r"(a[3]), "r"(b[0]), "r"(b[1]));
}

// swizzled byte offset within a 128x64 fp16 plane (128B rows, 8 x 16B units)
__device__ __forceinline__ uint32_t swz(int r, int u) {
    return (uint32_t)(r * 128 + ((u ^ (r & 7)) << 4));
}

// softcap+exp on |s|<=8: exp(50*tanh(s/50)) = exp(s)*exp(u)
__device__ __forceinline__ float softcap_exp(float s) {
    float s2 = s * s;
    float u = s * s2 * (-1.33333333e-4f + s2 * 2.13333333e-8f);
    float corr = 1.f + u * (1.f + 0.5f * u);
    return __expf(s) * corr;
}

// ---------------------------------------------------------------------------
// conversion kernels
// ---------------------------------------------------------------------------
__global__ void conv_h(const float* __restrict__ src, __half* __restrict__ dst, int nunits) {
    for (int i = blockIdx.x * blockDim.x + threadIdx.x; i < nunits;
         i += gridDim.x * blockDim.x) {
        const float4 f0 = *(const float4*)(src + (size_t)i * 8);
        const float4 f1 = *(const float4*)(src + (size_t)i * 8 + 4);
        __half2 h[4];
        h[0] = __floats2half2_rn(f0.x, f0.y);
        h[1] = __floats2half2_rn(f0.z, f0.w);
        h[2] = __floats2half2_rn(f1.x, f1.y);
        h[3] = __floats2half2_rn(f1.z, f1.w);
        ((uint4*)dst)[i] = *(uint4*)h;
    }
}

__global__ void pack_w_qkv(const float* __restrict__ wq, const float* __restrict__ wk,
                           const float* __restrict__ wv) {
    int nunits = QKV_N * (GDIM / 8);
    for (int i = blockIdx.x * blockDim.x + threadIdx.x; i < nunits;
         i += gridDim.x * blockDim.x) {
        int row = i >> 7, ur = i & 127;
        const float* srow;
        if (row < NH * HD)                srow = wq + (size_t)row * GDIM;
        else if (row < NH*HD + NKV*HD)    srow = wk + (size_t)(row - NH*HD) * GDIM;
        else                              srow = wv + (size_t)(row - NH*HD - NKV*HD) * GDIM;
        const float4 f0 = *(const float4*)(srow + ur * 8);
        const float4 f1 = *(const float4*)(srow + ur * 8 + 4);
        __half2 h[4];
        h[0] = __floats2half2_rn(f0.x, f0.y);
        h[1] = __floats2half2_rn(f0.z, f0.w);
        h[2] = __floats2half2_rn(f1.x, f1.y);
        h[3] = __floats2half2_rn(f1.z, f1.w);
        ((uint4*)g_wqkv)[i] = *(uint4*)h;
    }
}

// ---------------------------------------------------------------------------
// fp16 GEMM core: 128x128 block, 4 warps (warptile 64x64), BK=64, 3-stage.
// OUT_HALF selects fp16 vs fp32 output.
// ---------------------------------------------------------------------------
__device__ __forceinline__ void load_stage1(uint32_t sb, int stage,
        const __half* __restrict__ A, const __half* __restrict__ B,
        int bm, int bn, int kc, int tid) {
    uint32_t st = sb + stage * STAGE1_B;
#pragma unroll
    for (int i = 0; i < 16; i++) {
        int v = i * 128 + tid;
        int op = v >> 10;         // 0:A 1:B
        int w = v & 1023;
        int r = w >> 3, u = w & 7;
        const __half* base = (op == 0) ? A : B;
        int grow = ((op == 0) ? bm : bn) * 128 + r;
        const __half* g = base + (size_t)grow * GDIM + kc * BK + u * 8;
        cp16(st + op * PLANE_B + swz(r, u), g);
    }
}

template <int OUT_HALF>
__device__ __forceinline__ void gemm_body(const __half* __restrict__ A,
        const __half* __restrict__ B, void* __restrict__ outv, int ldc) {
    extern __shared__ __align__(1024) char smem[];
    uint32_t sb = smem_u32(smem);
    int tid = threadIdx.x, wid = tid >> 5, lane = tid & 31;
    int bm = blockIdx.y, bn = blockIdx.x;
    int wm = wid >> 1;        // 0..1 -> m offset wm*64
    int wn = wid & 1;         // 0..1 -> n offset wn*64

    float acc[4][8][4];
#pragma unroll
    for (int a = 0; a < 4; a++)
#pragma unroll
        for (int b = 0; b < 8; b++)
#pragma unroll
            for (int c = 0; c < 4; c++) acc[a][b][c] = 0.f;

    load_stage1(sb, 0, A, B, bm, bn, 0, tid); CP_COMMIT();
    load_stage1(sb, 1, A, B, bm, bn, 1, tid); CP_COMMIT();

    for (int kc = 0; kc < KT; kc++) {
        CP_WAIT(1);
        __syncthreads();
        if (kc + 2 < KT)
            load_stage1(sb, (kc + 2) % NSTG, A, B, bm, bn, kc + 2, tid);
        CP_COMMIT();

        uint32_t st = sb + (kc % NSTG) * STAGE1_B;
#pragma unroll
        for (int ks = 0; ks < 4; ks++) {
            uint32_t af[4][4], bf[8][2];
#pragma unroll
            for (int mt = 0; mt < 4; mt++) {
                int r = wm * 64 + mt * 16 + (lane & 15);
                int u = 2 * ks + (lane >> 4);
                ldsm4(af[mt], st + swz(r, u));
            }
#pragma unroll
            for (int np = 0; np < 4; np++) {
                int r = wn * 64 + np * 16 + (lane & 7) + ((lane >> 4) & 1) * 8;
                int u = 2 * ks + ((lane >> 3) & 1);
                uint32_t t[4];
                ldsm4(t, st + PLANE_B + swz(r, u));
                bf[np*2][0] = t[0]; bf[np*2][1] = t[1];
                bf[np*2+1][0] = t[2]; bf[np*2+1][1] = t[3];
            }
#pragma unroll
            for (int mt = 0; mt < 4; mt++)
#pragma unroll
                for (int nt = 0; nt < 8; nt++) mma16816h(acc[mt][nt], af[mt], bf[nt]);
        }
    }

#pragma unroll
    for (int mt = 0; mt < 4; mt++)
#pragma unroll
        for (int nt = 0; nt < 8; nt++) {
            float* c = acc[mt][nt];
            int row = bm * 128 + wm * 64 + mt * 16 + (lane >> 2);
            int col = bn * 128 + wn * 64 + nt * 8 + 2 * (lane & 3);
            if (OUT_HALF) {
                __half* out = (__half*)outv;
                *(__half2*)(out + (size_t)row * ldc + col) = __floats2half2_rn(c[0], c[1]);
                *(__half2*)(out + (size_t)(row + 8) * ldc + col) = __floats2half2_rn(c[2], c[3]);
            } else {
                float* out = (float*)outv;
                *(float2*)(out + (size_t)row * ldc + col) = make_float2(c[0], c[1]);
                *(float2*)(out + (size_t)(row + 8) * ldc + col) = make_float2(c[2], c[3]);
            }
        }
}

__global__ __launch_bounds__(128, 2)
void gemm_f32(const __half* __restrict__ A, const __half* __restrict__ B,
              float* __restrict__ out, int ldc) {
    gemm_body<0>(A, B, out, ldc);
}
__global__ __launch_bounds__(128, 2)
void gemm_f16(const __half* __restrict__ A, const __half* __restrict__ B,
              __half* __restrict__ out, int ldc) {
    gemm_body<1>(A, B, out, ldc);
}

// ---------------------------------------------------------------------------
// QKNorm + partial 2D RoPE + single-fp16 attn operand planes (reads fp16 qkv)
// ---------------------------------------------------------------------------
__global__ __launch_bounds__(256)
void norm_rope_split(const float* __restrict__ qw, const float* __restrict__ kw) {
    int vec = blockIdx.x * 8 + (threadIdx.x >> 5);
    int lane = threadIdx.x & 31;
    int hh = vec % 24;
    int row = vec / 24;
    int bt = row / SEQ, s = row - bt * SEQ;

    if (hh >= NH + NKV) {
        // V: copy fp16
        const __half* p = g_qkvh + (size_t)row * QKV_N + GDIM + NKV * HD + (hh - NH - NKV) * HD;
        size_t o = ((size_t)(bt * NKV + (hh - NH - NKV)) * SEQ + s) * HD;
        g_vp[o + lane] = p[lane];
        g_vp[o + lane + 32] = p[lane + 32];
        return;
    }

    const __half* p;
    bool is_q = hh < NH;
    size_t o;
    if (is_q) {
        p = g_qkvh + (size_t)row * QKV_N + hh * HD;
        o = ((size_t)(bt * NH + hh) * SEQ + s) * HD;
    } else {
        p = g_qkvh + (size_t)row * QKV_N + GDIM + (hh - NH) * HD;
        o = ((size_t)(bt * NKV + (hh - NH)) * SEQ + s) * HD;
    }
    float v0 = __half2float(p[lane]), v1 = __half2float(p[lane + 32]);

    float sq = v0 * v0 + v1 * v1;
#pragma unroll
    for (int of = 16; of; of >>= 1) sq += __shfl_xor_sync(0xffffffffu, sq, of);
    float scl = rsqrtf(sq * (1.0f / HD) + 1e-6f);
    const float* wv = is_q ? qw : kw;
    v0 *= scl * wv[lane];
    v1 *= scl * wv[lane + 32];
    if (s < NZ) {
        int j = lane & 15;
        float pos = (lane < 16) ? (float)(s >> 4) : (float)(s & 15);
        float invf = __expf(-(float)j * 0.57564627324851142f);
        float c, sn;
        sincosf(pos * invf, &sn, &c);
        float o0 = v0 * c - v1 * sn;
        float o1 = v1 * c + v0 * sn;
        v0 = o0; v1 = o1;
    }
    __half* dst = is_q ? g_qp : g_kp;
    dst[o + lane] = __float2half_rn(v0);
    dst[o + lane + 32] = __float2half_rn(v1);
}

// ---------------------------------------------------------------------------
// Flash-style mma attention: all single fp16, full KV resident, 2 CTA/SM
// ---------------------------------------------------------------------------
__global__ __launch_bounds__(192, 2) void attn_mma() {
    extern __shared__ __align__(1024) char smem[];
    const int tid = threadIdx.x;
    const int mt = blockIdx.x, h = blockIdx.y, bt = blockIdx.z;
    const int m0 = (mt == 0) ? 0 : (mt == 1 ? 96 : 168);
    const int kvh = h >> 2;
    const uint32_t sb = smem_u32(smem);

    size_t kvo = (size_t)(bt * NKV + kvh) * SEQ * HD;
    const __half* k_g = g_kp + kvo;
    const __half* v_g = g_vp + kvo;

    for (int idx = tid; idx < SEQ * 8; idx += 192) {
        int r = idx >> 3, u = idx & 7;
        uint32_t doff = (uint32_t)(r * LDP + u * 16);
        int soff = r * HD + u * 8;
        cp16(sb + SM_K + doff, k_g + soff);
        cp16(sb + SM_V + doff, v_g + soff);
    }
    {
        size_t qo = ((size_t)(bt * NH + h) * SEQ + m0) * HD;
        const __half* q_g = g_qp + qo;
        for (int idx = tid; idx < 96 * 8; idx += 192) {
            int r = idx >> 3, u = idx & 7;
            cp16(sb + SM_Q + (uint32_t)(r * LDP + u * 16), q_g + r * HD + u * 8);
        }
    }
    for (int idx = tid; idx < 8 * 36; idx += 192) {
        int off = (SEQ + idx / 36) * LDP + (idx % 36) * 4;
        *(uint32_t*)(smem + SM_K + off) = 0;
        *(uint32_t*)(smem + SM_V + off) = 0;
    }
    CP_COMMIT();
    CP_WAIT(0);
    __syncthreads();

    const int w = tid >> 5, lane = tid & 31;

    uint32_t qh[4][4];
    {
        int r = w * 16 + (lane & 15);
        int uo = lane >> 4;
#pragma unroll
        for (int kc = 0; kc < 4; kc++)
            ldsm4(qh[kc], sb + SM_Q + (uint32_t)(r * LDP + (2 * kc + uo) * 16));
    }

    float oacc[8][4];
#pragma unroll
    for (int i = 0; i < 8; i++)
#pragma unroll
        for (int j = 0; j < 4; j++) oacc[i][j] = 0.f;
    float lsum0 = 0.f, lsum1 = 0.f;

    const int krow = (lane & 7) + ((lane >> 4) & 1) * 8;
    const int ku = (lane >> 3) & 1;
    const int vrow = (lane & 7) + ((lane >> 3) & 1) * 8;
    const int vu = (lane >> 4) & 1;

    for (int np = 0; np < 17; np++) {
        float sA0[4] = {0,0,0,0}, sA1[4] = {0,0,0,0};
#pragma unroll
        for (int kc = 0; kc < 4; kc++) {
            uint32_t off = (uint32_t)((np * 16 + krow) * LDP + (2 * kc + ku) * 16);
            uint32_t bh[4];
            ldsm4(bh, sb + SM_K + off);
            mma16816h(sA0, qh[kc], bh);
            mma16816h(sA1, qh[kc], bh + 2);
        }
        float pf[2][4];
#pragma unroll
        for (int e = 0; e < 4; e++) {
            pf[0][e] = softcap_exp(sA0[e] * 0.125f);
            pf[1][e] = softcap_exp(sA1[e] * 0.125f);
        }
        if (np == 16) { pf[1][0] = pf[1][1] = pf[1][2] = pf[1][3] = 0.f; }
        lsum0 += pf[0][0] + pf[0][1] + pf[1][0] + pf[1][1];
        lsum1 += pf[0][2] + pf[0][3] + pf[1][2] + pf[1][3];

        uint32_t ph[4];
        __half2 p0 = __floats2half2_rn(pf[0][0], pf[0][1]);
        __half2 p1 = __floats2half2_rn(pf[0][2], pf[0][3]);
        __half2 p2 = __floats2half2_rn(pf[1][0], pf[1][1]);
        __half2 p3 = __floats2half2_rn(pf[1][2], pf[1][3]);
        ph[0] = *(uint32_t*)&p0; ph[1] = *(uint32_t*)&p1;
        ph[2] = *(uint32_t*)&p2; ph[3] = *(uint32_t*)&p3;

        uint32_t vh[4][4];
#pragma unroll
        for (int db = 0; db < 4; db++) {
            uint32_t off = (uint32_t)((np * 16 + vrow) * LDP + (2 * db + vu) * 16);
            ldsm4t(vh[db], sb + SM_V + off);
        }
#pragma unroll
        for (int db = 0; db < 4; db++) {
            mma16816h(oacc[2*db],   ph, vh[db]);
            mma16816h(oacc[2*db+1], ph, vh[db] + 2);
        }
    }

    lsum0 += __shfl_xor_sync(0xffffffffu, lsum0, 1);
    lsum0 += __shfl_xor_sync(0xffffffffu, lsum0, 2);
    lsum1 += __shfl_xor_sync(0xffffffffu, lsum1, 1);
    lsum1 += __shfl_xor_sync(0xffffffffu, lsum1, 2);
    float inv0 = __fdividef(1.f, lsum0);
    float inv1 = __fdividef(1.f, lsum1);

    size_t row0 = (size_t)bt * SEQ + m0 + w * 16 + (lane >> 2);
    int colb = h * HD + 2 * (lane & 3);
#pragma unroll
    for (int nb = 0; nb < 8; nb++) {
        int col = colb + nb * 8;
        *(__half2*)(g_a + row0 * GDIM + col) =
            __floats2half2_rn(oacc[nb][0] * inv0, oacc[nb][1] * inv0);
        *(__half2*)(g_a + (row0 + 8) * GDIM + col) =
            __floats2half2_rn(oacc[nb][2] * inv1, oacc[nb][3] * inv1);
    }
}

// ---------------------------------------------------------------------------
extern "C" void kernel_launch(void* const* d_in, const int* in_sizes, int n_in,
                              void* d_out, int out_size) {
    const float* x   = (const float*)d_in[0];
    const float* wq  = (const float*)d_in[1];
    const float* wk  = (const float*)d_in[2];
    const float* wv  = (const float*)d_in[3];
    const float* wo  = (const float*)d_in[4];
    const float* qnw = (const float*)d_in[5];
    const float* knw = (const float*)d_in[6];
    float* out = (float*)d_out;

    __half *xh, *wqkvh, *woh, *ah, *qkvh;
    cudaGetSymbolAddress((void**)&xh, g_x);
    cudaGetSymbolAddress((void**)&wqkvh, g_wqkv);
    cudaGetSymbolAddress((void**)&woh, g_wo);
    cudaGetSymbolAddress((void**)&ah, g_a);
    cudaGetSymbolAddress((void**)&qkvh, g_qkvh);

    cudaFuncSetAttribute((const void*)gemm_f32,
                         cudaFuncAttributeMaxDynamicSharedMemorySize, GEMM1_SMEM);
    cudaFuncSetAttribute((const void*)gemm_f16,
                         cudaFuncAttributeMaxDynamicSharedMemorySize, GEMM1_SMEM);
    cudaFuncSetAttribute((const void*)attn_mma,
                         cudaFuncAttributeMaxDynamicSharedMemorySize, ATT_SMEM);

    // 1) operand conversion
    conv_h<<<4224, 256>>>(x, xh, MROWS * GDIM / 8);
    pack_w_qkv<<<768, 256>>>(wq, wk, wv);
    conv_h<<<512, 256>>>(wo, woh, GDIM * GDIM / 8);

    // 2) QKV projection (fp16 out)
    gemm_f16<<<dim3(QKV_N / 128, MROWS / 128), 128, GEMM1_SMEM>>>(
        xh, wqkvh, qkvh, QKV_N);

    // 3) QKNorm + 2D RoPE + attention planes
    norm_rope_split<<<MROWS * 3, 256>>>(qnw, knw);

    // 4) tensor-core attention
    attn_mma<<<dim3(3, NH, BTN), 192, ATT_SMEM>>>();

    // 5) output projection (fp32 out)
    gemm_f32<<<dim3(GDIM / 128, MROWS / 128), 128, GEMM1_SMEM>>>(
        ah, woh, out, GDIM);
}

// round 16
// speedup vs baseline: 3.4550x; 1.0598x over previous
#include <cuda_runtime.h>
#include <cuda_bf16.h>
#include <cuda_fp16.h>
#include <stdint.h>
#include <math.h>

// Problem constants
#define BTN   64
#define SEQ   264
#define MROWS (BTN*SEQ)      // 16896
#define GDIM  1024
#define NH    16
#define NKV   4
#define HD    64
#define QKV_N 1536
#define NZ    256

// GEMM tiling: block 128x128, BK=64, 4 warps (warptile 64x64), 3-stage
#define BK    64
#define KT    (GDIM/BK)      // 16
#define PLANE_B 16384
#define NSTG  3
#define STAGE1_B (2*PLANE_B)
#define GEMM1_SMEM (NSTG*STAGE1_B)  // 98304

// Attention smem
#define LDP   144
#define KPAD  272
#define SM_K  0
#define SM_V  (KPAD*LDP)
#define SM_Q  (2*KPAD*LDP)
#define ATT_SMEM (SM_Q + 96*LDP)    // 92160

// ---------------------------------------------------------------------------
// device scratch
// ---------------------------------------------------------------------------
__device__ __align__(16) __half g_x[(size_t)MROWS * GDIM];
__device__ __align__(16) __half g_wqkv[(size_t)QKV_N * GDIM];
__device__ __align__(16) __half g_wo[(size_t)GDIM * GDIM];
__device__ __align__(16) __half g_a[(size_t)MROWS * GDIM];
__device__ __align__(16) __half g_kp[(size_t)BTN * NKV * SEQ * HD];
__device__ __align__(16) __half g_vp[(size_t)BTN * NKV * SEQ * HD];
__device__ __align__(16) __half g_qp[(size_t)BTN * NH * SEQ * HD];
__device__ float g_cos[NZ * HD];
__device__ float g_sin[NZ * HD];

// ---------------------------------------------------------------------------
// helpers
// ---------------------------------------------------------------------------
__device__ __forceinline__ uint32_t smem_u32(const void* p) {
    uint32_t a;
    asm("{ .reg .u64 t; cvta.to.shared.u64 t, %1; cvt.u32.u64 %0, t; }"
        : "=r"(a) : "l"(p));
    return a;
}
__device__ __forceinline__ void cp16(uint32_t dst, const void* src) {
    asm volatile("cp.async.cg.shared.global [%0], [%1], 16;" :: "r"(dst), "l"(src));
}
#define CP_COMMIT() asm volatile("cp.async.commit_group;" ::: "memory")
#define CP_WAIT(n)  asm volatile("cp.async.wait_group %0;" :: "n"(n) : "memory")

__device__ __forceinline__ void ldsm4(uint32_t* r, uint32_t addr) {
    asm volatile("ldmatrix.sync.aligned.m8n8.x4.shared.b16 {%0,%1,%2,%3}, [%4];"
                 : "=r"(r[0]), "=r"(r[1]), "=r"(r[2]), "=r"(r[3]) : "r"(addr));
}
__device__ __forceinline__ void ldsm4t(uint32_t* r, uint32_t addr) {
    asm volatile("ldmatrix.sync.aligned.m8n8.x4.trans.shared.b16 {%0,%1,%2,%3}, [%4];"
                 : "=r"(r[0]), "=r"(r[1]), "=r"(r[2]), "=r"(r[3]) : "r"(addr));
}
__device__ __forceinline__ void mma16816h(float* c, const uint32_t* a, const uint32_t* b) {
    asm volatile(
        "mma.sync.aligned.m16n8k16.row.col.f32.f16.f16.f32 "
        "{%0,%1,%2,%3}, {%4,%5,%6,%7}, {%8,%9}, {%0,%1,%2,%3};"
        : "+f"(c[0]), "+f"(c[1]), "+f"(c[2]), "+f"(c[3])
        : "r"(a[0]), "r"(a[1]), "r"(a[2]), "r"(a[3]), "r"(b[0]), "r"(b[1]));
}

__device__ __forceinline__ uint32_t swz(int r, int u) {
    return (uint32_t)(r * 128 + ((u ^ (r & 7)) << 4));
}

__device__ __forceinline__ float softcap_exp(float s) {
    float s2 = s * s;
    float u = s * s2 * (-1.33333333e-4f + s2 * 2.13333333e-8f);
    float corr = 1.f + u * (1.f + 0.5f * u);
    return __expf(s) * corr;
}

// ---------------------------------------------------------------------------
// init kernels
// ---------------------------------------------------------------------------
__global__ void rope_table() {
    int i = blockIdx.x * blockDim.x + threadIdx.x;
    if (i >= NZ * HD) return;
    int s = i >> 6, d = i & 63;
    int j = d & 15;
    float pos = ((d & 31) < 16) ? (float)(s >> 4) : (float)(s & 15);
    float invf = __expf(-(float)j * 0.57564627324851142f);
    float c, sn;
    sincosf(pos * invf, &sn, &c);
    g_cos[i] = c;
    g_sin[i] = sn;
}

__global__ void conv_h(const float* __restrict__ src, __half* __restrict__ dst, int nunits) {
    for (int i = blockIdx.x * blockDim.x + threadIdx.x; i < nunits;
         i += gridDim.x * blockDim.x) {
        const float4 f0 = *(const float4*)(src + (size_t)i * 8);
        const float4 f1 = *(const float4*)(src + (size_t)i * 8 + 4);
        __half2 h[4];
        h[0] = __floats2half2_rn(f0.x, f0.y);
        h[1] = __floats2half2_rn(f0.z, f0.w);
        h[2] = __floats2half2_rn(f1.x, f1.y);
        h[3] = __floats2half2_rn(f1.z, f1.w);
        ((uint4*)dst)[i] = *(uint4*)h;
    }
}

__global__ void pack_w_qkv(const float* __restrict__ wq, const float* __restrict__ wk,
                           const float* __restrict__ wv) {
    int nunits = QKV_N * (GDIM / 8);
    for (int i = blockIdx.x * blockDim.x + threadIdx.x; i < nunits;
         i += gridDim.x * blockDim.x) {
        int row = i >> 7, ur = i & 127;
        const float* srow;
        if (row < NH * HD)                srow = wq + (size_t)row * GDIM;
        else if (row < NH*HD + NKV*HD)    srow = wk + (size_t)(row - NH*HD) * GDIM;
        else                              srow = wv + (size_t)(row - NH*HD - NKV*HD) * GDIM;
        const float4 f0 = *(const float4*)(srow + ur * 8);
        const float4 f1 = *(const float4*)(srow + ur * 8 + 4);
        __half2 h[4];
        h[0] = __floats2half2_rn(f0.x, f0.y);
        h[1] = __floats2half2_rn(f0.z, f0.w);
        h[2] = __floats2half2_rn(f1.x, f1.y);
        h[3] = __floats2half2_rn(f1.z, f1.w);
        ((uint4*)g_wqkv)[i] = *(uint4*)h;
    }
}

// ---------------------------------------------------------------------------
// fp16 GEMM core: 128x128 block, 4 warps (warptile 64x64), BK=64, 3-stage.
// MODE 0: fp32 out. MODE 1: fused QKNorm+RoPE+fp16 attn-plane epilogue.
// ---------------------------------------------------------------------------
__device__ __forceinline__ void load_stage1(uint32_t sb, int stage,
        const __half* __restrict__ A, const __half* __restrict__ B,
        int bm, int bn, int kc, int tid) {
    uint32_t st = sb + stage * STAGE1_B;
#pragma unroll
    for (int i = 0; i < 16; i++) {
        int v = i * 128 + tid;
        int op = v >> 10;
        int w = v & 1023;
        int r = w >> 3, u = w & 7;
        const __half* base = (op == 0) ? A : B;
        int grow = ((op == 0) ? bm : bn) * 128 + r;
        const __half* g = base + (size_t)grow * GDIM + kc * BK + u * 8;
        cp16(st + op * PLANE_B + swz(r, u), g);
    }
}

template <int MODE>
__device__ __forceinline__ void gemm_body(const __half* __restrict__ A,
        const __half* __restrict__ B, float* __restrict__ outv, int ldc,
        const float* __restrict__ qnw, const float* __restrict__ knw) {
    extern __shared__ __align__(1024) char smem[];
    uint32_t sb = smem_u32(smem);
    int tid = threadIdx.x, wid = tid >> 5, lane = tid & 31;
    int bm = blockIdx.y, bn = blockIdx.x;
    int wm = wid >> 1;
    int wn = wid & 1;

    float acc[4][8][4];
#pragma unroll
    for (int a = 0; a < 4; a++)
#pragma unroll
        for (int b = 0; b < 8; b++)
#pragma unroll
            for (int c = 0; c < 4; c++) acc[a][b][c] = 0.f;

    load_stage1(sb, 0, A, B, bm, bn, 0, tid); CP_COMMIT();
    load_stage1(sb, 1, A, B, bm, bn, 1, tid); CP_COMMIT();

    for (int kc = 0; kc < KT; kc++) {
        CP_WAIT(1);
        __syncthreads();
        if (kc + 2 < KT)
            load_stage1(sb, (kc + 2) % NSTG, A, B, bm, bn, kc + 2, tid);
        CP_COMMIT();

        uint32_t st = sb + (kc % NSTG) * STAGE1_B;
#pragma unroll
        for (int ks = 0; ks < 4; ks++) {
            uint32_t af[4][4], bf[8][2];
#pragma unroll
            for (int mt = 0; mt < 4; mt++) {
                int r = wm * 64 + mt * 16 + (lane & 15);
                int u = 2 * ks + (lane >> 4);
                ldsm4(af[mt], st + swz(r, u));
            }
#pragma unroll
            for (int np = 0; np < 4; np++) {
                int r = wn * 64 + np * 16 + (lane & 7) + ((lane >> 4) & 1) * 8;
                int u = 2 * ks + ((lane >> 3) & 1);
                uint32_t t[4];
                ldsm4(t, st + PLANE_B + swz(r, u));
                bf[np*2][0] = t[0]; bf[np*2][1] = t[1];
                bf[np*2+1][0] = t[2]; bf[np*2+1][1] = t[3];
            }
#pragma unroll
            for (int mt = 0; mt < 4; mt++)
#pragma unroll
                for (int nt = 0; nt < 8; nt++) mma16816h(acc[mt][nt], af[mt], bf[nt]);
        }
    }

    if (MODE == 0) {
        // plain fp32 output
#pragma unroll
        for (int mt = 0; mt < 4; mt++)
#pragma unroll
            for (int nt = 0; nt < 8; nt++) {
                float* c = acc[mt][nt];
                int row = bm * 128 + wm * 64 + mt * 16 + (lane >> 2);
                int col = bn * 128 + wn * 64 + nt * 8 + 2 * (lane & 3);
                *(float2*)(outv + (size_t)row * ldc + col) = make_float2(c[0], c[1]);
                *(float2*)(outv + (size_t)(row + 8) * ldc + col) = make_float2(c[2], c[3]);
            }
    } else {
        // fused QKNorm + 2D RoPE + fp16 plane scatter.
        // Warp's 64 n-cols = one head: H = bn*2 + wn (0..15 q, 16..19 k, 20..23 v)
        int H = bn * 2 + wn;
        bool isv = (H >= NH + NKV);
        bool isq = (H < NH);
        const float* nw = isq ? qnw : knw;
        int d0 = 2 * (lane & 3);   // thread's base d within head; cols d0+8*nt, d0+1+8*nt
#pragma unroll
        for (int mt = 0; mt < 4; mt++) {
#pragma unroll
            for (int half = 0; half < 2; half++) {   // row r and r+8
                int row = bm * 128 + wm * 64 + mt * 16 + (lane >> 2) + half * 8;
                int bt = row / SEQ, s = row - bt * SEQ;
                // gather this row's 16 values
                float v[16];
#pragma unroll
                for (int nt = 0; nt < 8; nt++) {
                    v[nt*2]   = acc[mt][nt][half*2];
                    v[nt*2+1] = acc[mt][nt][half*2+1];
                }
                __half* dst;
                size_t o;
                if (isv) {
                    o = ((size_t)(bt * NKV + (H - NH - NKV)) * SEQ + s) * HD;
                    dst = g_vp;
                } else {
                    // RMSNorm over the 64-col head: reduce over 4 lanes (xor 1,2)
                    float ss = 0.f;
#pragma unroll
                    for (int i = 0; i < 16; i++) ss += v[i] * v[i];
                    ss += __shfl_xor_sync(0xffffffffu, ss, 1);
                    ss += __shfl_xor_sync(0xffffffffu, ss, 2);
                    float scl = rsqrtf(ss * (1.0f / HD) + 1e-6f);
#pragma unroll
                    for (int i = 0; i < 16; i++) {
                        int d = (i >> 1) * 8 + d0 + (i & 1);
                        v[i] *= scl * nw[d];
                    }
                    if (s < NZ) {
                        float t[16];
#pragma unroll
                        for (int i = 0; i < 16; i++) {
                            int d = (i >> 1) * 8 + d0 + (i & 1);
                            float cs = g_cos[s * HD + d];
                            float sn = g_sin[s * HD + d];
                            float rot = (d < 32) ? -v[(i + 8) & 15] : v[(i + 8) & 15];
                            t[i] = v[i] * cs + rot * sn;
                        }
#pragma unroll
                        for (int i = 0; i < 16; i++) v[i] = t[i];
                    }
                    if (isq) {
                        o = ((size_t)(bt * NH + H) * SEQ + s) * HD;
                        dst = g_qp;
                    } else {
                        o = ((size_t)(bt * NKV + (H - NH)) * SEQ + s) * HD;
                        dst = g_kp;
                    }
                }
#pragma unroll
                for (int nt = 0; nt < 8; nt++) {
                    *(__half2*)(dst + o + nt * 8 + d0) =
                        __floats2half2_rn(v[nt*2], v[nt*2+1]);
                }
            }
        }
    }
}

__global__ __launch_bounds__(128, 2)
void gemm_f32(const __half* __restrict__ A, const __half* __restrict__ B,
              float* __restrict__ out, int ldc) {
    gemm_body<0>(A, B, out, ldc, nullptr, nullptr);
}
__global__ __launch_bounds__(128, 2)
void gemm_qkv(const __half* __restrict__ A, const __half* __restrict__ B,
              const float* __restrict__ qnw, const float* __restrict__ knw) {
    gemm_body<1>(A, B, nullptr, 0, qnw, knw);
}

// ---------------------------------------------------------------------------
// Flash-style mma attention: all single fp16, full KV resident, 2 CTA/SM
// ---------------------------------------------------------------------------
__global__ __launch_bounds__(192, 2) void attn_mma() {
    extern __shared__ __align__(1024) char smem[];
    const int tid = threadIdx.x;
    const int mt = blockIdx.x, h = blockIdx.y, bt = blockIdx.z;
    const int m0 = (mt == 0) ? 0 : (mt == 1 ? 96 : 168);
    const int kvh = h >> 2;
    const uint32_t sb = smem_u32(smem);

    size_t kvo = (size_t)(bt * NKV + kvh) * SEQ * HD;
    const __half* k_g = g_kp + kvo;
    const __half* v_g = g_vp + kvo;

    for (int idx = tid; idx < SEQ * 8; idx += 192) {
        int r = idx >> 3, u = idx & 7;
        uint32_t doff = (uint32_t)(r * LDP + u * 16);
        int soff = r * HD + u * 8;
        cp16(sb + SM_K + doff, k_g + soff);
        cp16(sb + SM_V + doff, v_g + soff);
    }
    {
        size_t qo = ((size_t)(bt * NH + h) * SEQ + m0) * HD;
        const __half* q_g = g_qp + qo;
        for (int idx = tid; idx < 96 * 8; idx += 192) {
            int r = idx >> 3, u = idx & 7;
            cp16(sb + SM_Q + (uint32_t)(r * LDP + u * 16), q_g + r * HD + u * 8);
        }
    }
    for (int idx = tid; idx < 8 * 36; idx += 192) {
        int off = (SEQ + idx / 36) * LDP + (idx % 36) * 4;
        *(uint32_t*)(smem + SM_K + off) = 0;
        *(uint32_t*)(smem + SM_V + off) = 0;
    }
    CP_COMMIT();
    CP_WAIT(0);
    __syncthreads();

    const int w = tid >> 5, lane = tid & 31;

    uint32_t qh[4][4];
    {
        int r = w * 16 + (lane & 15);
        int uo = lane >> 4;
#pragma unroll
        for (int kc = 0; kc < 4; kc++)
            ldsm4(qh[kc], sb + SM_Q + (uint32_t)(r * LDP + (2 * kc + uo) * 16));
    }

    float oacc[8][4];
#pragma unroll
    for (int i = 0; i < 8; i++)
#pragma unroll
        for (int j = 0; j < 4; j++) oacc[i][j] = 0.f;
    float lsum0 = 0.f, lsum1 = 0.f;

    const int krow = (lane & 7) + ((lane >> 4) & 1) * 8;
    const int ku = (lane >> 3) & 1;
    const int vrow = (lane & 7) + ((lane >> 3) & 1) * 8;
    const int vu = (lane >> 4) & 1;

    for (int np = 0; np < 17; np++) {
        float sA0[4] = {0,0,0,0}, sA1[4] = {0,0,0,0};
#pragma unroll
        for (int kc = 0; kc < 4; kc++) {
            uint32_t off = (uint32_t)((np * 16 + krow) * LDP + (2 * kc + ku) * 16);
            uint32_t bh[4];
            ldsm4(bh, sb + SM_K + off);
            mma16816h(sA0, qh[kc], bh);
            mma16816h(sA1, qh[kc], bh + 2);
        }
        float pf[2][4];
#pragma unroll
        for (int e = 0; e < 4; e++) {
            pf[0][e] = softcap_exp(sA0[e] * 0.125f);
            pf[1][e] = softcap_exp(sA1[e] * 0.125f);
        }
        if (np == 16) { pf[1][0] = pf[1][1] = pf[1][2] = pf[1][3] = 0.f; }
        lsum0 += pf[0][0] + pf[0][1] + pf[1][0] + pf[1][1];
        lsum1 += pf[0][2] + pf[0][3] + pf[1][2] + pf[1][3];

        uint32_t ph[4];
        __half2 p0 = __floats2half2_rn(pf[0][0], pf[0][1]);
        __half2 p1 = __floats2half2_rn(pf[0][2], pf[0][3]);
        __half2 p2 = __floats2half2_rn(pf[1][0], pf[1][1]);
        __half2 p3 = __floats2half2_rn(pf[1][2], pf[1][3]);
        ph[0] = *(uint32_t*)&p0; ph[1] = *(uint32_t*)&p1;
        ph[2] = *(uint32_t*)&p2; ph[3] = *(uint32_t*)&p3;

        uint32_t vh[4][4];
#pragma unroll
        for (int db = 0; db < 4; db++) {
            uint32_t off = (uint32_t)((np * 16 + vrow) * LDP + (2 * db + vu) * 16);
            ldsm4t(vh[db], sb + SM_V + off);
        }
#pragma unroll
        for (int db = 0; db < 4; db++) {
            mma16816h(oacc[2*db],   ph, vh[db]);
            mma16816h(oacc[2*db+1], ph, vh[db] + 2);
        }
    }

    lsum0 += __shfl_xor_sync(0xffffffffu, lsum0, 1);
    lsum0 += __shfl_xor_sync(0xffffffffu, lsum0, 2);
    lsum1 += __shfl_xor_sync(0xffffffffu, lsum1, 1);
    lsum1 += __shfl_xor_sync(0xffffffffu, lsum1, 2);
    float inv0 = __fdividef(1.f, lsum0);
    float inv1 = __fdividef(1.f, lsum1);

    size_t row0 = (size_t)bt * SEQ + m0 + w * 16 + (lane >> 2);
    int colb = h * HD + 2 * (lane & 3);
#pragma unroll
    for (int nb = 0; nb < 8; nb++) {
        int col = colb + nb * 8;
        *(__half2*)(g_a + row0 * GDIM + col) =
            __floats2half2_rn(oacc[nb][0] * inv0, oacc[nb][1] * inv0);
        *(__half2*)(g_a + (row0 + 8) * GDIM + col) =
            __floats2half2_rn(oacc[nb][2] * inv1, oacc[nb][3] * inv1);
    }
}

// ---------------------------------------------------------------------------
extern "C" void kernel_launch(void* const* d_in, const int* in_sizes, int n_in,
                              void* d_out, int out_size) {
    const float* x   = (const float*)d_in[0];
    const float* wq  = (const float*)d_in[1];
    const float* wk  = (const float*)d_in[2];
    const float* wv  = (const float*)d_in[3];
    const float* wo  = (const float*)d_in[4];
    const float* qnw = (const float*)d_in[5];
    const float* knw = (const float*)d_in[6];
    float* out = (float*)d_out;

    __half *xh, *wqkvh, *woh, *ah;
    cudaGetSymbolAddress((void**)&xh, g_x);
    cudaGetSymbolAddress((void**)&wqkvh, g_wqkv);
    cudaGetSymbolAddress((void**)&woh, g_wo);
    cudaGetSymbolAddress((void**)&ah, g_a);

    cudaFuncSetAttribute((const void*)gemm_f32,
                         cudaFuncAttributeMaxDynamicSharedMemorySize, GEMM1_SMEM);
    cudaFuncSetAttribute((const void*)gemm_qkv,
                         cudaFuncAttributeMaxDynamicSharedMemorySize, GEMM1_SMEM);
    cudaFuncSetAttribute((const void*)attn_mma,
                         cudaFuncAttributeMaxDynamicSharedMemorySize, ATT_SMEM);

    // 1) operand conversion + rope table
    rope_table<<<64, 256>>>();
    conv_h<<<4224, 256>>>(x, xh, MROWS * GDIM / 8);
    pack_w_qkv<<<768, 256>>>(wq, wk, wv);
    conv_h<<<512, 256>>>(wo, woh, GDIM * GDIM / 8);

    // 2) QKV projection with fused QKNorm + RoPE + plane scatter
    gemm_qkv<<<dim3(QKV_N / 128, MROWS / 128), 128, GEMM1_SMEM>>>(
        xh, wqkvh, qnw, knw);

    // 3) tensor-core attention
    attn_mma<<<dim3(3, NH, BTN), 192, ATT_SMEM>>>();

    // 4) output projection
    gemm_f32<<<dim3(GDIM / 128, MROWS / 128), 128, GEMM1_SMEM>>>(
        ah, woh, out, GDIM);
}